// round 1
// baseline (speedup 1.0000x reference)
#include <cuda_runtime.h>
#include <math.h>
#include <stdint.h>

#define S_LEN 4096
#define DIM   3072
#define HEADS 24
#define HD    128
#define MH    9216
#define FOUT  27648      // 3*DIM + 2*MH
#define QKV   9216       // 3*DIM
#define EPS   1e-6f

// ---------------- scratch (device globals; no allocations allowed) ----------
__device__ float g_h   [(size_t)S_LEN * DIM];
__device__ float g_P   [(size_t)S_LEN * FOUT];
__device__ float g_Qb  [(size_t)HEADS * S_LEN * HD];
__device__ float g_Kb  [(size_t)HEADS * S_LEN * HD];
__device__ float g_Vb  [(size_t)HEADS * S_LEN * HD];
__device__ float g_attn[(size_t)S_LEN * DIM];
__device__ float g_mlp [(size_t)S_LEN * MH];
__device__ float g_acc [(size_t)S_LEN * DIM];

// ---------------- kernel 1: LayerNorm + modulation --------------------------
__global__ __launch_bounds__(256) void k_lnmod(
    const float* __restrict__ x, const float* __restrict__ temb,
    float* __restrict__ h)
{
    int s = blockIdx.x;
    const float* xr = x + (size_t)s * DIM;
    float v[12];
    float lsum = 0.f, lsq = 0.f;
    #pragma unroll
    for (int i = 0; i < 12; i++) {
        float t = xr[threadIdx.x + i * 256];
        v[i] = t; lsum += t; lsq += t * t;
    }
    __shared__ float red[16];
    #pragma unroll
    for (int o = 16; o; o >>= 1) {
        lsum += __shfl_xor_sync(0xffffffffu, lsum, o);
        lsq  += __shfl_xor_sync(0xffffffffu, lsq,  o);
    }
    int w = threadIdx.x >> 5;
    if ((threadIdx.x & 31) == 0) { red[w] = lsum; red[8 + w] = lsq; }
    __syncthreads();
    float ssum = 0.f, ssq = 0.f;
    #pragma unroll
    for (int i = 0; i < 8; i++) { ssum += red[i]; ssq += red[8 + i]; }
    float mu  = ssum * (1.0f / DIM);
    float var = ssq * (1.0f / DIM) - mu * mu;
    float rs  = rsqrtf(var + EPS);
    float* hr = h + (size_t)s * DIM;
    #pragma unroll
    for (int i = 0; i < 12; i++) {
        int d = threadIdx.x + i * 256;
        float sc = temb[DIM + d];
        float sh = temb[d];
        hr[d] = (v[i] - mu) * rs * (1.f + sc) + sh;
    }
}

// ---------------- kernel 2: SGEMM (C [+]= A[M,K] * B[K,N]) -------------------
// BM=BN=128, BK=8, 256 threads, 8x8 microtile.
template <bool ACC>
__global__ __launch_bounds__(256) void k_sgemm(
    const float* __restrict__ A, const float* __restrict__ B,
    float* __restrict__ C, int M, int N, int K)
{
    __shared__ float As[8][132];   // transposed A tile, padded
    __shared__ float Bs[8][128];
    int bm = blockIdx.y * 128;
    int bn = blockIdx.x * 128;
    int tid = threadIdx.x;
    int ty = tid >> 4, tx = tid & 15;

    float acc[8][8];
    #pragma unroll
    for (int i = 0; i < 8; i++)
        #pragma unroll
        for (int j = 0; j < 8; j++) acc[i][j] = 0.f;

    int aRow = tid >> 1, aHalf = tid & 1;
    int bRow = tid >> 5, bCol = (tid & 31) << 2;
    const float* Ap = A + (size_t)(bm + aRow) * K + aHalf * 4;
    const float* Bp = B + (size_t)bRow * N + bn + bCol;

    for (int k0 = 0; k0 < K; k0 += 8) {
        float4 av = *(const float4*)(Ap + k0);
        float4 bv = *(const float4*)(Bp + (size_t)k0 * N);
        As[aHalf * 4 + 0][aRow] = av.x;
        As[aHalf * 4 + 1][aRow] = av.y;
        As[aHalf * 4 + 2][aRow] = av.z;
        As[aHalf * 4 + 3][aRow] = av.w;
        *(float4*)&Bs[bRow][bCol] = bv;
        __syncthreads();
        #pragma unroll
        for (int k = 0; k < 8; k++) {
            float4 a0 = *(const float4*)&As[k][ty * 8];
            float4 a1 = *(const float4*)&As[k][ty * 8 + 4];
            float4 b0 = *(const float4*)&Bs[k][tx * 8];
            float4 b1 = *(const float4*)&Bs[k][tx * 8 + 4];
            float ar[8] = {a0.x, a0.y, a0.z, a0.w, a1.x, a1.y, a1.z, a1.w};
            float br[8] = {b0.x, b0.y, b0.z, b0.w, b1.x, b1.y, b1.z, b1.w};
            #pragma unroll
            for (int i = 0; i < 8; i++)
                #pragma unroll
                for (int j = 0; j < 8; j++)
                    acc[i][j] += ar[i] * br[j];
        }
        __syncthreads();
    }

    #pragma unroll
    for (int i = 0; i < 8; i++) {
        float* cp = C + (size_t)(bm + ty * 8 + i) * N + bn + tx * 8;
        float4 c0 = make_float4(acc[i][0], acc[i][1], acc[i][2], acc[i][3]);
        float4 c1 = make_float4(acc[i][4], acc[i][5], acc[i][6], acc[i][7]);
        if (ACC) {
            float4 o0 = *(float4*)cp;
            float4 o1 = *(float4*)(cp + 4);
            c0.x += o0.x; c0.y += o0.y; c0.z += o0.z; c0.w += o0.w;
            c1.x += o1.x; c1.y += o1.y; c1.z += o1.z; c1.w += o1.w;
        }
        *(float4*)cp       = c0;
        *(float4*)(cp + 4) = c1;
    }
}

// ---------------- kernel 3: QKV extract + RMSNorm + RoPE ---------------------
__global__ __launch_bounds__(128) void k_qkvprep(
    const float* __restrict__ P, const float* __restrict__ cosb,
    const float* __restrict__ sinb, const float* __restrict__ nqw,
    const float* __restrict__ nkw,
    float* __restrict__ Qb, float* __restrict__ Kb, float* __restrict__ Vb)
{
    int s = blockIdx.x, h = blockIdx.y, d = threadIdx.x;
    const float* row = P + (size_t)s * FOUT + h * HD;
    float q = row[d];
    float k = row[DIM + d];
    float v = row[2 * DIM + d];

    __shared__ float sQ[HD], sK[HD], sred[8];
    float sq = q * q, sk = k * k;
    #pragma unroll
    for (int o = 16; o; o >>= 1) {
        sq += __shfl_xor_sync(0xffffffffu, sq, o);
        sk += __shfl_xor_sync(0xffffffffu, sk, o);
    }
    int w = d >> 5;
    if ((d & 31) == 0) { sred[w] = sq; sred[4 + w] = sk; }
    __syncthreads();
    float ssq = sred[0] + sred[1] + sred[2] + sred[3];
    float ssk = sred[4] + sred[5] + sred[6] + sred[7];
    float qn = q * rsqrtf(ssq * (1.0f / HD) + EPS) * nqw[d];
    float kn = k * rsqrtf(ssk * (1.0f / HD) + EPS) * nkw[d];
    sQ[d] = qn; sK[d] = kn;
    __syncthreads();
    float qrot = (d & 1) ? sQ[d - 1] : -sQ[d + 1];
    float krot = (d & 1) ? sK[d - 1] : -sK[d + 1];
    float c  = cosb[(size_t)s * HD + d];
    float sn = sinb[(size_t)s * HD + d];
    size_t o = ((size_t)h * S_LEN + s) * HD + d;
    Qb[o] = qn * c + qrot * sn;
    Kb[o] = kn * c + krot * sn;
    Vb[o] = v;
}

// ---------------- kernel 4: flash attention ---------------------------------
#define BQ 128
#define BK 64
#define QSTR 132
#define KSTR 129
#define VSTR 132
#define PSTR 64

__global__ __launch_bounds__(512, 1) void k_attn(
    const float* __restrict__ Qb, const float* __restrict__ Kb,
    const float* __restrict__ Vb, float* __restrict__ attn)
{
    extern __shared__ float smem[];
    float* Qs = smem;                    // BQ x QSTR
    float* Ks = Qs + BQ * QSTR;          // BK x KSTR
    float* Vs = Ks + BK * KSTR;          // BK x VSTR
    float* Ps = Vs + BK * VSTR;          // BQ x PSTR

    int h  = blockIdx.y;
    int q0 = blockIdx.x * BQ;
    int tid = threadIdx.x;
    int tr = tid >> 4;     // 0..31 -> rows tr*4 .. tr*4+3
    int tc = tid & 15;     // 0..15 -> S cols tc*4.., O cols tc*8..
    const float scale = 0.08838834764831843f;  // 1/sqrt(128)

    // load Q tile
    const float* Qg = Qb + ((size_t)h * S_LEN + q0) * HD;
    for (int i = tid; i < BQ * HD / 4; i += 512) {
        int r  = i >> 5;
        int c4 = (i & 31) << 2;
        float4 qv = *(const float4*)(Qg + (size_t)r * HD + c4);
        *(float4*)&Qs[r * QSTR + c4] = qv;
    }

    float m[4], l[4], o[4][8];
    #pragma unroll
    for (int i = 0; i < 4; i++) {
        m[i] = -1e30f; l[i] = 0.f;
        #pragma unroll
        for (int j = 0; j < 8; j++) o[i][j] = 0.f;
    }
    __syncthreads();

    for (int t0 = 0; t0 < S_LEN; t0 += BK) {
        const float* Kg = Kb + ((size_t)h * S_LEN + t0) * HD;
        const float* Vg = Vb + ((size_t)h * S_LEN + t0) * HD;
        for (int i = tid; i < BK * HD / 4; i += 512) {
            int r  = i >> 5;
            int c4 = (i & 31) << 2;
            float4 kv = *(const float4*)(Kg + (size_t)r * HD + c4);
            Ks[r * KSTR + c4 + 0] = kv.x;
            Ks[r * KSTR + c4 + 1] = kv.y;
            Ks[r * KSTR + c4 + 2] = kv.z;
            Ks[r * KSTR + c4 + 3] = kv.w;
            float4 vv = *(const float4*)(Vg + (size_t)r * HD + c4);
            *(float4*)&Vs[r * VSTR + c4] = vv;
        }
        __syncthreads();

        // S = Q K^T (per thread: 4x4)
        float acc[4][4];
        #pragma unroll
        for (int i = 0; i < 4; i++)
            #pragma unroll
            for (int j = 0; j < 4; j++) acc[i][j] = 0.f;
        #pragma unroll 4
        for (int d = 0; d < HD; d++) {
            float qr[4], kr[4];
            #pragma unroll
            for (int i = 0; i < 4; i++) qr[i] = Qs[(tr * 4 + i) * QSTR + d];
            #pragma unroll
            for (int j = 0; j < 4; j++) kr[j] = Ks[(tc * 4 + j) * KSTR + d];
            #pragma unroll
            for (int i = 0; i < 4; i++)
                #pragma unroll
                for (int j = 0; j < 4; j++)
                    acc[i][j] += qr[i] * kr[j];
        }

        // online softmax (row groups of 16 lanes)
        #pragma unroll
        for (int i = 0; i < 4; i++) {
            float s0 = acc[i][0] * scale, s1 = acc[i][1] * scale;
            float s2 = acc[i][2] * scale, s3 = acc[i][3] * scale;
            float mx = fmaxf(fmaxf(s0, s1), fmaxf(s2, s3));
            #pragma unroll
            for (int off = 8; off; off >>= 1)
                mx = fmaxf(mx, __shfl_xor_sync(0xffffffffu, mx, off));
            float mnew = fmaxf(m[i], mx);
            float corr = __expf(m[i] - mnew);
            float p0 = __expf(s0 - mnew), p1 = __expf(s1 - mnew);
            float p2 = __expf(s2 - mnew), p3 = __expf(s3 - mnew);
            float rs = p0 + p1 + p2 + p3;
            #pragma unroll
            for (int off = 8; off; off >>= 1)
                rs += __shfl_xor_sync(0xffffffffu, rs, off);
            l[i] = l[i] * corr + rs;
            m[i] = mnew;
            #pragma unroll
            for (int jj = 0; jj < 8; jj++) o[i][jj] *= corr;
            Ps[(tr * 4 + i) * PSTR + tc * 4 + 0] = p0;
            Ps[(tr * 4 + i) * PSTR + tc * 4 + 1] = p1;
            Ps[(tr * 4 + i) * PSTR + tc * 4 + 2] = p2;
            Ps[(tr * 4 + i) * PSTR + tc * 4 + 3] = p3;
        }
        __syncthreads();

        // O += P V  (per thread: 4 rows x 8 cols)
        #pragma unroll 2
        for (int c = 0; c < BK; c++) {
            float p4[4];
            #pragma unroll
            for (int i = 0; i < 4; i++) p4[i] = Ps[(tr * 4 + i) * PSTR + c];
            float4 v0 = *(const float4*)&Vs[c * VSTR + tc * 8];
            float4 v1 = *(const float4*)&Vs[c * VSTR + tc * 8 + 4];
            float vr[8] = {v0.x, v0.y, v0.z, v0.w, v1.x, v1.y, v1.z, v1.w};
            #pragma unroll
            for (int i = 0; i < 4; i++)
                #pragma unroll
                for (int jj = 0; jj < 8; jj++)
                    o[i][jj] += p4[i] * vr[jj];
        }
        __syncthreads();
    }

    // write normalized O: attn[s][h*128 + d]
    #pragma unroll
    for (int i = 0; i < 4; i++) {
        float inv = 1.0f / l[i];
        int r = q0 + tr * 4 + i;
        float* op = attn + ((size_t)r * HEADS + h) * HD + tc * 8;
        float4 o0 = make_float4(o[i][0] * inv, o[i][1] * inv, o[i][2] * inv, o[i][3] * inv);
        float4 o1 = make_float4(o[i][4] * inv, o[i][5] * inv, o[i][6] * inv, o[i][7] * inv);
        *(float4*)op       = o0;
        *(float4*)(op + 4) = o1;
    }
}

// ---------------- kernel 5: SwiGLU ------------------------------------------
__global__ __launch_bounds__(256) void k_swiglu(
    const float* __restrict__ P, float* __restrict__ mlp)
{
    int j = blockIdx.x * 256 + threadIdx.x;   // 0..MH-1
    int s = blockIdx.y;
    float a = P[(size_t)s * FOUT + QKV + j];
    float b = P[(size_t)s * FOUT + QKV + MH + j];
    mlp[(size_t)s * MH + j] = (a / (1.f + __expf(-a))) * b;
}

// ---------------- kernel 6: gated residual ----------------------------------
__global__ __launch_bounds__(256) void k_final(
    const float* __restrict__ x, const float* __restrict__ temb,
    const float* __restrict__ acc, float* __restrict__ out)
{
    int d = blockIdx.x * 256 + threadIdx.x;   // 0..DIM-1
    int s = blockIdx.y;
    size_t idx = (size_t)s * DIM + d;
    out[idx] = x[idx] + temb[2 * DIM + d] * acc[idx];
}

// ---------------- launch -----------------------------------------------------
extern "C" void kernel_launch(void* const* d_in, const int* in_sizes, int n_in,
                              void* d_out, int out_size)
{
    const float* x       = (const float*)d_in[0];
    const float* temb    = (const float*)d_in[1];
    const float* rcos    = (const float*)d_in[2];
    const float* rsin    = (const float*)d_in[3];
    const float* w1      = (const float*)d_in[4];
    const float* wo_attn = (const float*)d_in[5];
    const float* wo_mlp  = (const float*)d_in[6];
    const float* nqw     = (const float*)d_in[7];
    const float* nkw     = (const float*)d_in[8];
    float* out = (float*)d_out;

    float *h, *P, *Qb, *Kb, *Vb, *attn, *mlp, *acc;
    cudaGetSymbolAddress((void**)&h,    g_h);
    cudaGetSymbolAddress((void**)&P,    g_P);
    cudaGetSymbolAddress((void**)&Qb,   g_Qb);
    cudaGetSymbolAddress((void**)&Kb,   g_Kb);
    cudaGetSymbolAddress((void**)&Vb,   g_Vb);
    cudaGetSymbolAddress((void**)&attn, g_attn);
    cudaGetSymbolAddress((void**)&mlp,  g_mlp);
    cudaGetSymbolAddress((void**)&acc,  g_acc);

    // 1) LayerNorm + modulation
    k_lnmod<<<S_LEN, 256>>>(x, temb, h);

    // 2) fused QKV+MLP projection: P = h @ w1   [4096 x 27648]
    {
        dim3 g(FOUT / 128, S_LEN / 128);
        k_sgemm<false><<<g, 256>>>(h, w1, P, S_LEN, FOUT, DIM);
    }

    // 3) QKV heads + RMSNorm + RoPE
    {
        dim3 g(S_LEN, HEADS);
        k_qkvprep<<<g, 128>>>(P, rcos, rsin, nqw, nkw, Qb, Kb, Vb);
    }

    // 4) attention
    {
        int smem_bytes = (BQ * QSTR + BK * KSTR + BK * VSTR + BQ * PSTR) * (int)sizeof(float);
        cudaFuncSetAttribute(k_attn, cudaFuncAttributeMaxDynamicSharedMemorySize, smem_bytes);
        dim3 g(S_LEN / BQ, HEADS);
        k_attn<<<g, 512, smem_bytes>>>(Qb, Kb, Vb, attn);
    }

    // 5) SwiGLU
    {
        dim3 g(MH / 256, S_LEN);
        k_swiglu<<<g, 256>>>(P, mlp);
    }

    // 6) out = attn @ wo_attn ; 7) out += mlp @ wo_mlp
    {
        dim3 g(DIM / 128, S_LEN / 128);
        k_sgemm<false><<<g, 256>>>(attn, wo_attn, acc, S_LEN, DIM, DIM);
        k_sgemm<true><<<g, 256>>>(mlp, wo_mlp, acc, S_LEN, DIM, MH);
    }

    // 8) gated residual
    {
        dim3 g(DIM / 256, S_LEN);
        k_final<<<g, 256>>>(x, temb, acc, out);
    }
}

// round 2
// speedup vs baseline: 2.3254x; 2.3254x over previous
#include <cuda_runtime.h>
#include <math.h>
#include <stdint.h>

#define S_LEN 4096
#define DIM   3072
#define HEADS 24
#define HD    128
#define MH    9216
#define FOUT  27648      // 3*DIM + 2*MH
#define QKV   9216       // 3*DIM
#define EPS   1e-6f

// ---------------- scratch (device globals; no allocations allowed) ----------
__device__ float g_h   [(size_t)S_LEN * DIM];
__device__ float g_P   [(size_t)S_LEN * FOUT];
__device__ float g_Qb  [(size_t)HEADS * S_LEN * HD];
__device__ float g_Kb  [(size_t)HEADS * S_LEN * HD];
__device__ float g_Vb  [(size_t)HEADS * S_LEN * HD];
__device__ float g_attn[(size_t)S_LEN * DIM];
__device__ float g_mlp [(size_t)S_LEN * MH];
__device__ float g_acc [(size_t)S_LEN * DIM];
// tf32-rounded weights
__device__ float g_w1r [(size_t)DIM * FOUT];
__device__ float g_woar[(size_t)DIM * DIM];
__device__ float g_womr[(size_t)MH * DIM];

__device__ __forceinline__ float tf32r(float x) {
    unsigned u;
    asm("cvt.rna.tf32.f32 %0, %1;" : "=r"(u) : "f"(x));
    return __uint_as_float(u);
}

// ---------------- kernel 0: tf32 rounding of weights -------------------------
__global__ __launch_bounds__(256) void k_round(
    const float4* __restrict__ in, float4* __restrict__ out, size_t n4)
{
    size_t stride = (size_t)gridDim.x * 256;
    for (size_t i = (size_t)blockIdx.x * 256 + threadIdx.x; i < n4; i += stride) {
        float4 v = in[i];
        v.x = tf32r(v.x); v.y = tf32r(v.y); v.z = tf32r(v.z); v.w = tf32r(v.w);
        out[i] = v;
    }
}

// ---------------- kernel 1: LayerNorm + modulation --------------------------
__global__ __launch_bounds__(256) void k_lnmod(
    const float* __restrict__ x, const float* __restrict__ temb,
    float* __restrict__ h)
{
    int s = blockIdx.x;
    const float* xr = x + (size_t)s * DIM;
    float v[12];
    float lsum = 0.f, lsq = 0.f;
    #pragma unroll
    for (int i = 0; i < 12; i++) {
        float t = xr[threadIdx.x + i * 256];
        v[i] = t; lsum += t; lsq += t * t;
    }
    __shared__ float red[16];
    #pragma unroll
    for (int o = 16; o; o >>= 1) {
        lsum += __shfl_xor_sync(0xffffffffu, lsum, o);
        lsq  += __shfl_xor_sync(0xffffffffu, lsq,  o);
    }
    int w = threadIdx.x >> 5;
    if ((threadIdx.x & 31) == 0) { red[w] = lsum; red[8 + w] = lsq; }
    __syncthreads();
    float ssum = 0.f, ssq = 0.f;
    #pragma unroll
    for (int i = 0; i < 8; i++) { ssum += red[i]; ssq += red[8 + i]; }
    float mu  = ssum * (1.0f / DIM);
    float var = ssq * (1.0f / DIM) - mu * mu;
    float rs  = rsqrtf(var + EPS);
    float* hr = h + (size_t)s * DIM;
    #pragma unroll
    for (int i = 0; i < 12; i++) {
        int d = threadIdx.x + i * 256;
        float sc = temb[DIM + d];
        float sh = temb[d];
        hr[d] = tf32r((v[i] - mu) * rs * (1.f + sc) + sh);
    }
}

// ---------------- kernel 2: tf32 tensor-core GEMM ----------------------------
// C[M,N] (+)= A[M,K] * B[K,N].  BM=BN=128, BK=32, 256 thr, warp tile 64x32.
#define ASTR 36
#define BSTR 136
#define ASZ (128 * ASTR)
#define BSZ (32 * BSTR)

__device__ __forceinline__ void cp16(uint32_t s, const float* g) {
    asm volatile("cp.async.cg.shared.global [%0], [%1], 16;\n" :: "r"(s), "l"(g));
}
__device__ __forceinline__ void mma_tf32(float c[4],
    uint32_t a0, uint32_t a1, uint32_t a2, uint32_t a3, uint32_t b0, uint32_t b1)
{
    asm volatile(
        "mma.sync.aligned.m16n8k8.row.col.f32.tf32.tf32.f32 "
        "{%0,%1,%2,%3},{%4,%5,%6,%7},{%8,%9},{%0,%1,%2,%3};"
        : "+f"(c[0]), "+f"(c[1]), "+f"(c[2]), "+f"(c[3])
        : "r"(a0), "r"(a1), "r"(a2), "r"(a3), "r"(b0), "r"(b1));
}

template <bool ACC>
__global__ __launch_bounds__(256) void k_mm(
    const float* __restrict__ A, const float* __restrict__ B,
    float* __restrict__ C, int M, int N, int K, int tiles_m, int tiles_n)
{
    extern __shared__ float smf[];
    float* As = smf;              // 2 stages of [128][ASTR]
    float* Bs = smf + 2 * ASZ;    // 2 stages of [32][BSTR]

    // block swizzle (GROUP_M = 16)
    int pid = blockIdx.x;
    const int GROUPM = 16;
    int npg     = GROUPM * tiles_n;
    int groupid = pid / npg;
    int firstm  = groupid * GROUPM;
    int gsz     = min(GROUPM, tiles_m - firstm);
    int pm      = firstm + (pid % npg) % gsz;
    int pn      = (pid % npg) / gsz;
    int bm = pm * 128, bn = pn * 128;

    int tid  = threadIdx.x;
    int warp = tid >> 5, lane = tid & 31;
    int wm = warp >> 2, wn = warp & 3;     // 2 x 4 warp grid
    int gid = lane >> 2, tid4 = lane & 3;

    float acc[4][4][4];
    #pragma unroll
    for (int i = 0; i < 4; i++)
        #pragma unroll
        for (int j = 0; j < 4; j++)
            #pragma unroll
            for (int q = 0; q < 4; q++) acc[i][j][q] = 0.f;

    // cp.async base addresses
    const float* Ab = A + (size_t)(bm + (tid >> 3)) * K + (tid & 7) * 4;
    const float* Bb = B + (size_t)(tid >> 5) * N + bn + (tid & 31) * 4;
    uint32_t sAb = (uint32_t)__cvta_generic_to_shared(As)
                 + ((tid >> 3) * ASTR + (tid & 7) * 4) * 4;
    uint32_t sBb = (uint32_t)__cvta_generic_to_shared(Bs)
                 + ((tid >> 5) * BSTR + (tid & 31) * 4) * 4;

    int ntiles = K >> 5;

    // prologue: stage 0
    {
        #pragma unroll
        for (int i = 0; i < 4; i++) {
            cp16(sAb + i * 32 * ASTR * 4, Ab + (size_t)i * 32 * K);
            cp16(sBb + i * 8 * BSTR * 4,  Bb + (size_t)i * 8 * N);
        }
        asm volatile("cp.async.commit_group;\n");
    }

    for (int t = 0; t < ntiles; t++) {
        if (t + 1 < ntiles) {
            int s = (t + 1) & 1;
            int kt = (t + 1) << 5;
            #pragma unroll
            for (int i = 0; i < 4; i++) {
                cp16(sAb + (s * ASZ + i * 32 * ASTR) * 4, Ab + kt + (size_t)i * 32 * K);
                cp16(sBb + (s * BSZ + i * 8 * BSTR) * 4,  Bb + (size_t)(kt + i * 8) * N);
            }
            asm volatile("cp.async.commit_group;\n");
            asm volatile("cp.async.wait_group 1;\n");
        } else {
            asm volatile("cp.async.wait_group 0;\n");
        }
        __syncthreads();

        const float* Asp = As + (t & 1) * ASZ;
        const float* Bsp = Bs + (t & 1) * BSZ;
        #pragma unroll
        for (int k8 = 0; k8 < 4; k8++) {
            int k0 = k8 * 8;
            uint32_t af[4][4], bf[4][2];
            #pragma unroll
            for (int mt = 0; mt < 4; mt++) {
                int r = wm * 64 + mt * 16 + gid;
                af[mt][0] = __float_as_uint(Asp[r * ASTR + k0 + tid4]);
                af[mt][1] = __float_as_uint(Asp[(r + 8) * ASTR + k0 + tid4]);
                af[mt][2] = __float_as_uint(Asp[r * ASTR + k0 + tid4 + 4]);
                af[mt][3] = __float_as_uint(Asp[(r + 8) * ASTR + k0 + tid4 + 4]);
            }
            #pragma unroll
            for (int nt = 0; nt < 4; nt++) {
                int cn = wn * 32 + nt * 8 + gid;
                bf[nt][0] = __float_as_uint(Bsp[(k0 + tid4) * BSTR + cn]);
                bf[nt][1] = __float_as_uint(Bsp[(k0 + tid4 + 4) * BSTR + cn]);
            }
            #pragma unroll
            for (int mt = 0; mt < 4; mt++)
                #pragma unroll
                for (int nt = 0; nt < 4; nt++)
                    mma_tf32(acc[mt][nt], af[mt][0], af[mt][1], af[mt][2], af[mt][3],
                             bf[nt][0], bf[nt][1]);
        }
        __syncthreads();
    }

    // epilogue
    #pragma unroll
    for (int mt = 0; mt < 4; mt++) {
        int r0 = bm + wm * 64 + mt * 16 + gid;
        #pragma unroll
        for (int nt = 0; nt < 4; nt++) {
            int c0 = bn + wn * 32 + nt * 8 + tid4 * 2;
            float2* p0 = (float2*)(C + (size_t)r0 * N + c0);
            float2* p1 = (float2*)(C + (size_t)(r0 + 8) * N + c0);
            float2 v0 = make_float2(acc[mt][nt][0], acc[mt][nt][1]);
            float2 v1 = make_float2(acc[mt][nt][2], acc[mt][nt][3]);
            if (ACC) {
                float2 o0 = *p0, o1 = *p1;
                v0.x += o0.x; v0.y += o0.y;
                v1.x += o1.x; v1.y += o1.y;
            }
            *p0 = v0;
            *p1 = v1;
        }
    }
}

// ---------------- kernel 3: QKV extract + RMSNorm + RoPE ---------------------
__global__ __launch_bounds__(128) void k_qkvprep(
    const float* __restrict__ P, const float* __restrict__ cosb,
    const float* __restrict__ sinb, const float* __restrict__ nqw,
    const float* __restrict__ nkw,
    float* __restrict__ Qb, float* __restrict__ Kb, float* __restrict__ Vb)
{
    int s = blockIdx.x, h = blockIdx.y, d = threadIdx.x;
    const float* row = P + (size_t)s * FOUT + h * HD;
    float q = row[d];
    float k = row[DIM + d];
    float v = row[2 * DIM + d];

    __shared__ float sQ[HD], sK[HD], sred[8];
    float sq = q * q, sk = k * k;
    #pragma unroll
    for (int o = 16; o; o >>= 1) {
        sq += __shfl_xor_sync(0xffffffffu, sq, o);
        sk += __shfl_xor_sync(0xffffffffu, sk, o);
    }
    int w = d >> 5;
    if ((d & 31) == 0) { sred[w] = sq; sred[4 + w] = sk; }
    __syncthreads();
    float ssq = sred[0] + sred[1] + sred[2] + sred[3];
    float ssk = sred[4] + sred[5] + sred[6] + sred[7];
    float qn = q * rsqrtf(ssq * (1.0f / HD) + EPS) * nqw[d];
    float kn = k * rsqrtf(ssk * (1.0f / HD) + EPS) * nkw[d];
    sQ[d] = qn; sK[d] = kn;
    __syncthreads();
    float qrot = (d & 1) ? sQ[d - 1] : -sQ[d + 1];
    float krot = (d & 1) ? sK[d - 1] : -sK[d + 1];
    float c  = cosb[(size_t)s * HD + d];
    float sn = sinb[(size_t)s * HD + d];
    size_t o = ((size_t)h * S_LEN + s) * HD + d;
    Qb[o] = qn * c + qrot * sn;
    Kb[o] = kn * c + krot * sn;
    Vb[o] = v;
}

// ---------------- kernel 4: flash attention (fp32 SIMT, unchanged) -----------
#define BQ 128
#define BK 64
#define QSTR 132
#define KSTR 129
#define VSTR 132
#define PSTR 64

__global__ __launch_bounds__(512, 1) void k_attn(
    const float* __restrict__ Qb, const float* __restrict__ Kb,
    const float* __restrict__ Vb, float* __restrict__ attn)
{
    extern __shared__ float smem[];
    float* Qs = smem;                    // BQ x QSTR
    float* Ks = Qs + BQ * QSTR;          // BK x KSTR
    float* Vs = Ks + BK * KSTR;          // BK x VSTR
    float* Ps = Vs + BK * VSTR;          // BQ x PSTR

    int h  = blockIdx.y;
    int q0 = blockIdx.x * BQ;
    int tid = threadIdx.x;
    int tr = tid >> 4;
    int tc = tid & 15;
    const float scale = 0.08838834764831843f;

    const float* Qg = Qb + ((size_t)h * S_LEN + q0) * HD;
    for (int i = tid; i < BQ * HD / 4; i += 512) {
        int r  = i >> 5;
        int c4 = (i & 31) << 2;
        float4 qv = *(const float4*)(Qg + (size_t)r * HD + c4);
        *(float4*)&Qs[r * QSTR + c4] = qv;
    }

    float m[4], l[4], o[4][8];
    #pragma unroll
    for (int i = 0; i < 4; i++) {
        m[i] = -1e30f; l[i] = 0.f;
        #pragma unroll
        for (int j = 0; j < 8; j++) o[i][j] = 0.f;
    }
    __syncthreads();

    for (int t0 = 0; t0 < S_LEN; t0 += BK) {
        const float* Kg = Kb + ((size_t)h * S_LEN + t0) * HD;
        const float* Vg = Vb + ((size_t)h * S_LEN + t0) * HD;
        for (int i = tid; i < BK * HD / 4; i += 512) {
            int r  = i >> 5;
            int c4 = (i & 31) << 2;
            float4 kv = *(const float4*)(Kg + (size_t)r * HD + c4);
            Ks[r * KSTR + c4 + 0] = kv.x;
            Ks[r * KSTR + c4 + 1] = kv.y;
            Ks[r * KSTR + c4 + 2] = kv.z;
            Ks[r * KSTR + c4 + 3] = kv.w;
            float4 vv = *(const float4*)(Vg + (size_t)r * HD + c4);
            *(float4*)&Vs[r * VSTR + c4] = vv;
        }
        __syncthreads();

        float acc[4][4];
        #pragma unroll
        for (int i = 0; i < 4; i++)
            #pragma unroll
            for (int j = 0; j < 4; j++) acc[i][j] = 0.f;
        #pragma unroll 4
        for (int d = 0; d < HD; d++) {
            float qr[4], kr[4];
            #pragma unroll
            for (int i = 0; i < 4; i++) qr[i] = Qs[(tr * 4 + i) * QSTR + d];
            #pragma unroll
            for (int j = 0; j < 4; j++) kr[j] = Ks[(tc * 4 + j) * KSTR + d];
            #pragma unroll
            for (int i = 0; i < 4; i++)
                #pragma unroll
                for (int j = 0; j < 4; j++)
                    acc[i][j] += qr[i] * kr[j];
        }

        #pragma unroll
        for (int i = 0; i < 4; i++) {
            float s0 = acc[i][0] * scale, s1 = acc[i][1] * scale;
            float s2 = acc[i][2] * scale, s3 = acc[i][3] * scale;
            float mx = fmaxf(fmaxf(s0, s1), fmaxf(s2, s3));
            #pragma unroll
            for (int off = 8; off; off >>= 1)
                mx = fmaxf(mx, __shfl_xor_sync(0xffffffffu, mx, off));
            float mnew = fmaxf(m[i], mx);
            float corr = __expf(m[i] - mnew);
            float p0 = __expf(s0 - mnew), p1 = __expf(s1 - mnew);
            float p2 = __expf(s2 - mnew), p3 = __expf(s3 - mnew);
            float rs = p0 + p1 + p2 + p3;
            #pragma unroll
            for (int off = 8; off; off >>= 1)
                rs += __shfl_xor_sync(0xffffffffu, rs, off);
            l[i] = l[i] * corr + rs;
            m[i] = mnew;
            #pragma unroll
            for (int jj = 0; jj < 8; jj++) o[i][jj] *= corr;
            Ps[(tr * 4 + i) * PSTR + tc * 4 + 0] = p0;
            Ps[(tr * 4 + i) * PSTR + tc * 4 + 1] = p1;
            Ps[(tr * 4 + i) * PSTR + tc * 4 + 2] = p2;
            Ps[(tr * 4 + i) * PSTR + tc * 4 + 3] = p3;
        }
        __syncthreads();

        #pragma unroll 2
        for (int c = 0; c < BK; c++) {
            float p4[4];
            #pragma unroll
            for (int i = 0; i < 4; i++) p4[i] = Ps[(tr * 4 + i) * PSTR + c];
            float4 v0 = *(const float4*)&Vs[c * VSTR + tc * 8];
            float4 v1 = *(const float4*)&Vs[c * VSTR + tc * 8 + 4];
            float vr[8] = {v0.x, v0.y, v0.z, v0.w, v1.x, v1.y, v1.z, v1.w};
            #pragma unroll
            for (int i = 0; i < 4; i++)
                #pragma unroll
                for (int jj = 0; jj < 8; jj++)
                    o[i][jj] += p4[i] * vr[jj];
        }
        __syncthreads();
    }

    #pragma unroll
    for (int i = 0; i < 4; i++) {
        float inv = 1.0f / l[i];
        int r = q0 + tr * 4 + i;
        float* op = attn + ((size_t)r * HEADS + h) * HD + tc * 8;
        float4 o0 = make_float4(tf32r(o[i][0] * inv), tf32r(o[i][1] * inv),
                                tf32r(o[i][2] * inv), tf32r(o[i][3] * inv));
        float4 o1 = make_float4(tf32r(o[i][4] * inv), tf32r(o[i][5] * inv),
                                tf32r(o[i][6] * inv), tf32r(o[i][7] * inv));
        *(float4*)op       = o0;
        *(float4*)(op + 4) = o1;
    }
}

// ---------------- kernel 5: SwiGLU ------------------------------------------
__global__ __launch_bounds__(256) void k_swiglu(
    const float* __restrict__ P, float* __restrict__ mlp)
{
    int j = blockIdx.x * 256 + threadIdx.x;
    int s = blockIdx.y;
    float a = P[(size_t)s * FOUT + QKV + j];
    float b = P[(size_t)s * FOUT + QKV + MH + j];
    mlp[(size_t)s * MH + j] = tf32r((a / (1.f + __expf(-a))) * b);
}

// ---------------- kernel 6: gated residual ----------------------------------
__global__ __launch_bounds__(256) void k_final(
    const float* __restrict__ x, const float* __restrict__ temb,
    const float* __restrict__ acc, float* __restrict__ out)
{
    int d = blockIdx.x * 256 + threadIdx.x;
    int s = blockIdx.y;
    size_t idx = (size_t)s * DIM + d;
    out[idx] = x[idx] + temb[2 * DIM + d] * acc[idx];
}

// ---------------- launch -----------------------------------------------------
extern "C" void kernel_launch(void* const* d_in, const int* in_sizes, int n_in,
                              void* d_out, int out_size)
{
    const float* x       = (const float*)d_in[0];
    const float* temb    = (const float*)d_in[1];
    const float* rcos    = (const float*)d_in[2];
    const float* rsin    = (const float*)d_in[3];
    const float* w1      = (const float*)d_in[4];
    const float* wo_attn = (const float*)d_in[5];
    const float* wo_mlp  = (const float*)d_in[6];
    const float* nqw     = (const float*)d_in[7];
    const float* nkw     = (const float*)d_in[8];
    float* out = (float*)d_out;

    float *h, *P, *Qb, *Kb, *Vb, *attn, *mlp, *acc, *w1r, *woar, *womr;
    cudaGetSymbolAddress((void**)&h,    g_h);
    cudaGetSymbolAddress((void**)&P,    g_P);
    cudaGetSymbolAddress((void**)&Qb,   g_Qb);
    cudaGetSymbolAddress((void**)&Kb,   g_Kb);
    cudaGetSymbolAddress((void**)&Vb,   g_Vb);
    cudaGetSymbolAddress((void**)&attn, g_attn);
    cudaGetSymbolAddress((void**)&mlp,  g_mlp);
    cudaGetSymbolAddress((void**)&acc,  g_acc);
    cudaGetSymbolAddress((void**)&w1r,  g_w1r);
    cudaGetSymbolAddress((void**)&woar, g_woar);
    cudaGetSymbolAddress((void**)&womr, g_womr);

    // 0) round weights to tf32 (scratch copies)
    {
        int blocks = 148 * 8;
        k_round<<<blocks, 256>>>((const float4*)w1,      (float4*)w1r,
                                 (size_t)DIM * FOUT / 4);
        k_round<<<blocks, 256>>>((const float4*)wo_attn, (float4*)woar,
                                 (size_t)DIM * DIM / 4);
        k_round<<<blocks, 256>>>((const float4*)wo_mlp,  (float4*)womr,
                                 (size_t)MH * DIM / 4);
    }

    // 1) LayerNorm + modulation (outputs tf32-rounded h)
    k_lnmod<<<S_LEN, 256>>>(x, temb, h);

    int mm_smem = 2 * (ASZ + BSZ) * (int)sizeof(float);
    cudaFuncSetAttribute(k_mm<false>, cudaFuncAttributeMaxDynamicSharedMemorySize, mm_smem);
    cudaFuncSetAttribute(k_mm<true>,  cudaFuncAttributeMaxDynamicSharedMemorySize, mm_smem);

    // 2) fused QKV+MLP projection: P = h @ w1   [4096 x 27648]
    {
        int tm = S_LEN / 128, tn = FOUT / 128;
        k_mm<false><<<tm * tn, 256, mm_smem>>>(h, w1r, P, S_LEN, FOUT, DIM, tm, tn);
    }

    // 3) QKV heads + RMSNorm + RoPE
    {
        dim3 g(S_LEN, HEADS);
        k_qkvprep<<<g, 128>>>(P, rcos, rsin, nqw, nkw, Qb, Kb, Vb);
    }

    // 4) attention
    {
        int smem_bytes = (BQ * QSTR + BK * KSTR + BK * VSTR + BQ * PSTR) * (int)sizeof(float);
        cudaFuncSetAttribute(k_attn, cudaFuncAttributeMaxDynamicSharedMemorySize, smem_bytes);
        dim3 g(S_LEN / BQ, HEADS);
        k_attn<<<g, 512, smem_bytes>>>(Qb, Kb, Vb, attn);
    }

    // 5) SwiGLU
    {
        dim3 g(MH / 256, S_LEN);
        k_swiglu<<<g, 256>>>(P, mlp);
    }

    // 6) out = attn @ wo_attn ; 7) out += mlp @ wo_mlp
    {
        int tm = S_LEN / 128, tn = DIM / 128;
        k_mm<false><<<tm * tn, 256, mm_smem>>>(attn, woar, acc, S_LEN, DIM, DIM, tm, tn);
        k_mm<true><<<tm * tn, 256, mm_smem>>>(mlp, womr, acc, S_LEN, DIM, MH, tm, tn);
    }

    // 8) gated residual
    {
        dim3 g(DIM / 256, S_LEN);
        k_final<<<g, 256>>>(x, temb, acc, out);
    }
}

// round 3
// speedup vs baseline: 4.0519x; 1.7425x over previous
#include <cuda_runtime.h>
#include <math.h>
#include <stdint.h>

#define S_LEN 4096
#define DIM   3072
#define HEADS 24
#define HD    128
#define MH    9216
#define FOUT  27648      // 3*DIM + 2*MH
#define QKV   9216       // 3*DIM
#define EPS   1e-6f

// ---------------- scratch (device globals; no allocations allowed) ----------
__device__ float g_h   [(size_t)S_LEN * DIM];
__device__ float g_P   [(size_t)S_LEN * FOUT];
__device__ float g_Qb  [(size_t)HEADS * S_LEN * HD];
__device__ float g_Kb  [(size_t)HEADS * S_LEN * HD];
__device__ float g_Vb  [(size_t)HEADS * S_LEN * HD];
__device__ float g_attn[(size_t)S_LEN * DIM];
__device__ float g_mlp [(size_t)S_LEN * MH];
__device__ float g_acc [(size_t)S_LEN * DIM];
// tf32-rounded weights
__device__ float g_w1r [(size_t)DIM * FOUT];
__device__ float g_woar[(size_t)DIM * DIM];
__device__ float g_womr[(size_t)MH * DIM];

__device__ __forceinline__ float tf32r(float x) {
    unsigned u;
    asm("cvt.rna.tf32.f32 %0, %1;" : "=r"(u) : "f"(x));
    return __uint_as_float(u);
}
__device__ __forceinline__ void cp16(uint32_t s, const float* g) {
    asm volatile("cp.async.cg.shared.global [%0], [%1], 16;\n" :: "r"(s), "l"(g));
}
__device__ __forceinline__ void mma_tf32(float c[4],
    uint32_t a0, uint32_t a1, uint32_t a2, uint32_t a3, uint32_t b0, uint32_t b1)
{
    asm volatile(
        "mma.sync.aligned.m16n8k8.row.col.f32.tf32.tf32.f32 "
        "{%0,%1,%2,%3},{%4,%5,%6,%7},{%8,%9},{%0,%1,%2,%3};"
        : "+f"(c[0]), "+f"(c[1]), "+f"(c[2]), "+f"(c[3])
        : "r"(a0), "r"(a1), "r"(a2), "r"(a3), "r"(b0), "r"(b1));
}

// ---------------- kernel 0: tf32 rounding of weights -------------------------
__global__ __launch_bounds__(256) void k_round(
    const float4* __restrict__ in, float4* __restrict__ out, size_t n4)
{
    size_t stride = (size_t)gridDim.x * 256;
    for (size_t i = (size_t)blockIdx.x * 256 + threadIdx.x; i < n4; i += stride) {
        float4 v = in[i];
        v.x = tf32r(v.x); v.y = tf32r(v.y); v.z = tf32r(v.z); v.w = tf32r(v.w);
        out[i] = v;
    }
}

// ---------------- kernel 1: LayerNorm + modulation --------------------------
__global__ __launch_bounds__(256) void k_lnmod(
    const float* __restrict__ x, const float* __restrict__ temb,
    float* __restrict__ h)
{
    int s = blockIdx.x;
    const float* xr = x + (size_t)s * DIM;
    float v[12];
    float lsum = 0.f, lsq = 0.f;
    #pragma unroll
    for (int i = 0; i < 12; i++) {
        float t = xr[threadIdx.x + i * 256];
        v[i] = t; lsum += t; lsq += t * t;
    }
    __shared__ float red[16];
    #pragma unroll
    for (int o = 16; o; o >>= 1) {
        lsum += __shfl_xor_sync(0xffffffffu, lsum, o);
        lsq  += __shfl_xor_sync(0xffffffffu, lsq,  o);
    }
    int w = threadIdx.x >> 5;
    if ((threadIdx.x & 31) == 0) { red[w] = lsum; red[8 + w] = lsq; }
    __syncthreads();
    float ssum = 0.f, ssq = 0.f;
    #pragma unroll
    for (int i = 0; i < 8; i++) { ssum += red[i]; ssq += red[8 + i]; }
    float mu  = ssum * (1.0f / DIM);
    float var = ssq * (1.0f / DIM) - mu * mu;
    float rs  = rsqrtf(var + EPS);
    float* hr = h + (size_t)s * DIM;
    #pragma unroll
    for (int i = 0; i < 12; i++) {
        int d = threadIdx.x + i * 256;
        float sc = temb[DIM + d];
        float sh = temb[d];
        hr[d] = tf32r((v[i] - mu) * rs * (1.f + sc) + sh);
    }
}

// ---------------- kernel 2: tf32 tensor-core GEMM ----------------------------
#define ASTR 36
#define BSTR 136
#define ASZ (128 * ASTR)
#define BSZ (32 * BSTR)

template <bool ACC>
__global__ __launch_bounds__(256) void k_mm(
    const float* __restrict__ A, const float* __restrict__ B,
    float* __restrict__ C, int M, int N, int K, int tiles_m, int tiles_n)
{
    extern __shared__ float smf[];
    float* As = smf;
    float* Bs = smf + 2 * ASZ;

    int pid = blockIdx.x;
    const int GROUPM = 16;
    int npg     = GROUPM * tiles_n;
    int groupid = pid / npg;
    int firstm  = groupid * GROUPM;
    int gsz     = min(GROUPM, tiles_m - firstm);
    int pm      = firstm + (pid % npg) % gsz;
    int pn      = (pid % npg) / gsz;
    int bm = pm * 128, bn = pn * 128;

    int tid  = threadIdx.x;
    int warp = tid >> 5, lane = tid & 31;
    int wm = warp >> 2, wn = warp & 3;
    int gid = lane >> 2, tid4 = lane & 3;

    float acc[4][4][4];
    #pragma unroll
    for (int i = 0; i < 4; i++)
        #pragma unroll
        for (int j = 0; j < 4; j++)
            #pragma unroll
            for (int q = 0; q < 4; q++) acc[i][j][q] = 0.f;

    const float* Ab = A + (size_t)(bm + (tid >> 3)) * K + (tid & 7) * 4;
    const float* Bb = B + (size_t)(tid >> 5) * N + bn + (tid & 31) * 4;
    uint32_t sAb = (uint32_t)__cvta_generic_to_shared(As)
                 + ((tid >> 3) * ASTR + (tid & 7) * 4) * 4;
    uint32_t sBb = (uint32_t)__cvta_generic_to_shared(Bs)
                 + ((tid >> 5) * BSTR + (tid & 31) * 4) * 4;

    int ntiles = K >> 5;

    {
        #pragma unroll
        for (int i = 0; i < 4; i++) {
            cp16(sAb + i * 32 * ASTR * 4, Ab + (size_t)i * 32 * K);
            cp16(sBb + i * 8 * BSTR * 4,  Bb + (size_t)i * 8 * N);
        }
        asm volatile("cp.async.commit_group;\n");
    }

    for (int t = 0; t < ntiles; t++) {
        if (t + 1 < ntiles) {
            int s = (t + 1) & 1;
            int kt = (t + 1) << 5;
            #pragma unroll
            for (int i = 0; i < 4; i++) {
                cp16(sAb + (s * ASZ + i * 32 * ASTR) * 4, Ab + kt + (size_t)i * 32 * K);
                cp16(sBb + (s * BSZ + i * 8 * BSTR) * 4,  Bb + (size_t)(kt + i * 8) * N);
            }
            asm volatile("cp.async.commit_group;\n");
            asm volatile("cp.async.wait_group 1;\n");
        } else {
            asm volatile("cp.async.wait_group 0;\n");
        }
        __syncthreads();

        const float* Asp = As + (t & 1) * ASZ;
        const float* Bsp = Bs + (t & 1) * BSZ;
        #pragma unroll
        for (int k8 = 0; k8 < 4; k8++) {
            int k0 = k8 * 8;
            uint32_t af[4][4], bf[4][2];
            #pragma unroll
            for (int mt = 0; mt < 4; mt++) {
                int r = wm * 64 + mt * 16 + gid;
                af[mt][0] = __float_as_uint(Asp[r * ASTR + k0 + tid4]);
                af[mt][1] = __float_as_uint(Asp[(r + 8) * ASTR + k0 + tid4]);
                af[mt][2] = __float_as_uint(Asp[r * ASTR + k0 + tid4 + 4]);
                af[mt][3] = __float_as_uint(Asp[(r + 8) * ASTR + k0 + tid4 + 4]);
            }
            #pragma unroll
            for (int nt = 0; nt < 4; nt++) {
                int cn = wn * 32 + nt * 8 + gid;
                bf[nt][0] = __float_as_uint(Bsp[(k0 + tid4) * BSTR + cn]);
                bf[nt][1] = __float_as_uint(Bsp[(k0 + tid4 + 4) * BSTR + cn]);
            }
            #pragma unroll
            for (int mt = 0; mt < 4; mt++)
                #pragma unroll
                for (int nt = 0; nt < 4; nt++)
                    mma_tf32(acc[mt][nt], af[mt][0], af[mt][1], af[mt][2], af[mt][3],
                             bf[nt][0], bf[nt][1]);
        }
        __syncthreads();
    }

    #pragma unroll
    for (int mt = 0; mt < 4; mt++) {
        int r0 = bm + wm * 64 + mt * 16 + gid;
        #pragma unroll
        for (int nt = 0; nt < 4; nt++) {
            int c0 = bn + wn * 32 + nt * 8 + tid4 * 2;
            float2* p0 = (float2*)(C + (size_t)r0 * N + c0);
            float2* p1 = (float2*)(C + (size_t)(r0 + 8) * N + c0);
            float2 v0 = make_float2(acc[mt][nt][0], acc[mt][nt][1]);
            float2 v1 = make_float2(acc[mt][nt][2], acc[mt][nt][3]);
            if (ACC) {
                float2 o0 = *p0, o1 = *p1;
                v0.x += o0.x; v0.y += o0.y;
                v1.x += o1.x; v1.y += o1.y;
            }
            *p0 = v0;
            *p1 = v1;
        }
    }
}

// ---------------- kernel 3: QKV extract + RMSNorm + RoPE ---------------------
__global__ __launch_bounds__(128) void k_qkvprep(
    const float* __restrict__ P, const float* __restrict__ cosb,
    const float* __restrict__ sinb, const float* __restrict__ nqw,
    const float* __restrict__ nkw,
    float* __restrict__ Qb, float* __restrict__ Kb, float* __restrict__ Vb)
{
    int s = blockIdx.x, h = blockIdx.y, d = threadIdx.x;
    const float* row = P + (size_t)s * FOUT + h * HD;
    float q = row[d];
    float k = row[DIM + d];
    float v = row[2 * DIM + d];

    __shared__ float sQ[HD], sK[HD], sred[8];
    float sq = q * q, sk = k * k;
    #pragma unroll
    for (int o = 16; o; o >>= 1) {
        sq += __shfl_xor_sync(0xffffffffu, sq, o);
        sk += __shfl_xor_sync(0xffffffffu, sk, o);
    }
    int w = d >> 5;
    if ((d & 31) == 0) { sred[w] = sq; sred[4 + w] = sk; }
    __syncthreads();
    float ssq = sred[0] + sred[1] + sred[2] + sred[3];
    float ssk = sred[4] + sred[5] + sred[6] + sred[7];
    float qn = q * rsqrtf(ssq * (1.0f / HD) + EPS) * nqw[d];
    float kn = k * rsqrtf(ssk * (1.0f / HD) + EPS) * nkw[d];
    sQ[d] = qn; sK[d] = kn;
    __syncthreads();
    float qrot = (d & 1) ? sQ[d - 1] : -sQ[d + 1];
    float krot = (d & 1) ? sK[d - 1] : -sK[d + 1];
    float c  = cosb[(size_t)s * HD + d];
    float sn = sinb[(size_t)s * HD + d];
    size_t o = ((size_t)h * S_LEN + s) * HD + d;
    Qb[o] = qn * c + qrot * sn;
    Kb[o] = kn * c + krot * sn;
    Vb[o] = v;
}

// ---------------- kernel 4: flash attention (tf32 tensor cores) --------------
// 256 threads = 8 warps. BQ=128 (16 rows/warp), BK=64, HD=128.
// smem: Ks[2][64][132] | Vs[2][64][132] | Ps[8][16][68]
#define KV_STR 132
#define KV_STAGE (64 * KV_STR)       // 8448 floats
#define P_STR 68
#define PW_SZ (16 * P_STR)           // 1088 floats
#define ATTN_SMEM ((4 * KV_STAGE + 8 * PW_SZ) * 4)

__global__ __launch_bounds__(256, 1) void k_attn2(
    const float* __restrict__ Qb, const float* __restrict__ Kb,
    const float* __restrict__ Vb, float* __restrict__ attn)
{
    extern __shared__ float sm[];
    float* VsBase = sm + 2 * KV_STAGE;
    float* Ps     = sm + 4 * KV_STAGE;

    int h  = blockIdx.y;
    int q0 = blockIdx.x * 128;
    int tid = threadIdx.x, warp = tid >> 5, lane = tid & 31;
    int gid = lane >> 2, tid4 = lane & 3;
    float* Pw = Ps + warp * PW_SZ;
    const float scale = 0.08838834764831843f;   // 1/sqrt(128)
    uint32_t smbase = (uint32_t)__cvta_generic_to_shared(sm);

    // ---- prologue: Q tile -> smem (borrows the Ks stages), extract frags ----
    const float* Qg = Qb + ((size_t)h * S_LEN + q0) * HD;
    for (int i = tid; i < 128 * 32; i += 256) {
        int r = i >> 5, c4 = (i & 31) << 2;
        float4 v = *(const float4*)(Qg + (size_t)r * HD + c4);
        v.x *= scale; v.y *= scale; v.z *= scale; v.w *= scale;
        *(float4*)&sm[r * KV_STR + c4] = v;
    }
    __syncthreads();
    uint32_t qf[16][4];
    {
        int r0 = warp * 16 + gid;
        #pragma unroll
        for (int kc = 0; kc < 16; kc++) {
            qf[kc][0] = __float_as_uint(sm[r0 * KV_STR + kc * 8 + tid4]);
            qf[kc][1] = __float_as_uint(sm[(r0 + 8) * KV_STR + kc * 8 + tid4]);
            qf[kc][2] = __float_as_uint(sm[r0 * KV_STR + kc * 8 + tid4 + 4]);
            qf[kc][3] = __float_as_uint(sm[(r0 + 8) * KV_STR + kc * 8 + tid4 + 4]);
        }
    }
    __syncthreads();

    float m0 = -1e30f, m1 = -1e30f, l0 = 0.f, l1 = 0.f;
    float o[16][4];
    #pragma unroll
    for (int dt = 0; dt < 16; dt++)
        #pragma unroll
        for (int j = 0; j < 4; j++) o[dt][j] = 0.f;

    // KV tile loader (cp.async), stage s
    #define LOAD_KV(T, SS)                                                       \
    {                                                                            \
        const float* Kg = Kb + ((size_t)h * S_LEN + (T) * 64) * HD;              \
        const float* Vg = Vb + ((size_t)h * S_LEN + (T) * 64) * HD;              \
        uint32_t ks = smbase + (uint32_t)((SS) * KV_STAGE) * 4u;                 \
        uint32_t vs = smbase + (uint32_t)((2 + (SS)) * KV_STAGE) * 4u;           \
        _Pragma("unroll")                                                        \
        for (int i = 0; i < 8; i++) {                                            \
            int idx = tid + i * 256;                                             \
            int r = idx >> 5, c4 = (idx & 31) << 2;                              \
            cp16(ks + (uint32_t)(r * KV_STR + c4) * 4u, Kg + (size_t)r * HD + c4);\
            cp16(vs + (uint32_t)(r * KV_STR + c4) * 4u, Vg + (size_t)r * HD + c4);\
        }                                                                        \
        asm volatile("cp.async.commit_group;\n");                                \
    }

    LOAD_KV(0, 0)

    for (int t = 0; t < 64; t++) {
        if (t + 1 < 64) {
            LOAD_KV(t + 1, (t + 1) & 1)
            asm volatile("cp.async.wait_group 1;\n");
        } else {
            asm volatile("cp.async.wait_group 0;\n");
        }
        __syncthreads();

        const float* Ks = sm + (t & 1) * KV_STAGE;
        const float* Vs = VsBase + (t & 1) * KV_STAGE;

        // ---- S = Q K^T : per-warp 16x64 ----
        float sa[8][4];
        #pragma unroll
        for (int nt = 0; nt < 8; nt++)
            #pragma unroll
            for (int j = 0; j < 4; j++) sa[nt][j] = 0.f;
        #pragma unroll
        for (int nt = 0; nt < 8; nt++) {
            const float* Kr = Ks + (nt * 8 + gid) * KV_STR;
            #pragma unroll
            for (int kc = 0; kc < 16; kc++) {
                uint32_t b0 = __float_as_uint(Kr[kc * 8 + tid4]);
                uint32_t b1 = __float_as_uint(Kr[kc * 8 + tid4 + 4]);
                mma_tf32(sa[nt], qf[kc][0], qf[kc][1], qf[kc][2], qf[kc][3], b0, b1);
            }
        }

        // ---- online softmax ----
        float mx0 = -1e30f, mx1 = -1e30f;
        #pragma unroll
        for (int nt = 0; nt < 8; nt++) {
            mx0 = fmaxf(mx0, fmaxf(sa[nt][0], sa[nt][1]));
            mx1 = fmaxf(mx1, fmaxf(sa[nt][2], sa[nt][3]));
        }
        mx0 = fmaxf(mx0, __shfl_xor_sync(0xffffffffu, mx0, 1));
        mx0 = fmaxf(mx0, __shfl_xor_sync(0xffffffffu, mx0, 2));
        mx1 = fmaxf(mx1, __shfl_xor_sync(0xffffffffu, mx1, 1));
        mx1 = fmaxf(mx1, __shfl_xor_sync(0xffffffffu, mx1, 2));
        float nm0 = fmaxf(m0, mx0), nm1 = fmaxf(m1, mx1);
        float corr0 = __expf(m0 - nm0), corr1 = __expf(m1 - nm1);
        float rs0 = 0.f, rs1 = 0.f;
        #pragma unroll
        for (int nt = 0; nt < 8; nt++) {
            float p0 = __expf(sa[nt][0] - nm0);
            float p1 = __expf(sa[nt][1] - nm0);
            float p2 = __expf(sa[nt][2] - nm1);
            float p3 = __expf(sa[nt][3] - nm1);
            rs0 += p0 + p1; rs1 += p2 + p3;
            *(float2*)&Pw[gid * P_STR + nt * 8 + 2 * tid4]       = make_float2(p0, p1);
            *(float2*)&Pw[(gid + 8) * P_STR + nt * 8 + 2 * tid4] = make_float2(p2, p3);
        }
        rs0 += __shfl_xor_sync(0xffffffffu, rs0, 1);
        rs0 += __shfl_xor_sync(0xffffffffu, rs0, 2);
        rs1 += __shfl_xor_sync(0xffffffffu, rs1, 1);
        rs1 += __shfl_xor_sync(0xffffffffu, rs1, 2);
        l0 = l0 * corr0 + rs0;
        l1 = l1 * corr1 + rs1;
        m0 = nm0; m1 = nm1;
        #pragma unroll
        for (int dt = 0; dt < 16; dt++) {
            o[dt][0] *= corr0; o[dt][1] *= corr0;
            o[dt][2] *= corr1; o[dt][3] *= corr1;
        }
        __syncwarp();

        // ---- O += P V : per-warp 16x128 ----
        #pragma unroll
        for (int kc = 0; kc < 8; kc++) {
            uint32_t a0 = __float_as_uint(Pw[gid * P_STR + kc * 8 + tid4]);
            uint32_t a1 = __float_as_uint(Pw[(gid + 8) * P_STR + kc * 8 + tid4]);
            uint32_t a2 = __float_as_uint(Pw[gid * P_STR + kc * 8 + tid4 + 4]);
            uint32_t a3 = __float_as_uint(Pw[(gid + 8) * P_STR + kc * 8 + tid4 + 4]);
            const float* Vr0 = Vs + (kc * 8 + tid4) * KV_STR;
            const float* Vr1 = Vs + (kc * 8 + tid4 + 4) * KV_STR;
            #pragma unroll
            for (int dt = 0; dt < 16; dt++) {
                uint32_t b0 = __float_as_uint(Vr0[dt * 8 + gid]);
                uint32_t b1 = __float_as_uint(Vr1[dt * 8 + gid]);
                mma_tf32(o[dt], a0, a1, a2, a3, b0, b1);
            }
        }
        __syncthreads();
    }

    // ---- epilogue ----
    float inv0 = 1.0f / l0, inv1 = 1.0f / l1;
    int r0 = q0 + warp * 16 + gid;
    #pragma unroll
    for (int dt = 0; dt < 16; dt++) {
        int col = h * HD + dt * 8 + 2 * tid4;
        *(float2*)&attn[(size_t)r0 * DIM + col] =
            make_float2(tf32r(o[dt][0] * inv0), tf32r(o[dt][1] * inv0));
        *(float2*)&attn[(size_t)(r0 + 8) * DIM + col] =
            make_float2(tf32r(o[dt][2] * inv1), tf32r(o[dt][3] * inv1));
    }
}

// ---------------- kernel 5: SwiGLU ------------------------------------------
__global__ __launch_bounds__(256) void k_swiglu(
    const float* __restrict__ P, float* __restrict__ mlp)
{
    int j = blockIdx.x * 256 + threadIdx.x;
    int s = blockIdx.y;
    float a = P[(size_t)s * FOUT + QKV + j];
    float b = P[(size_t)s * FOUT + QKV + MH + j];
    mlp[(size_t)s * MH + j] = tf32r((a / (1.f + __expf(-a))) * b);
}

// ---------------- kernel 6: gated residual ----------------------------------
__global__ __launch_bounds__(256) void k_final(
    const float* __restrict__ x, const float* __restrict__ temb,
    const float* __restrict__ acc, float* __restrict__ out)
{
    int d = blockIdx.x * 256 + threadIdx.x;
    int s = blockIdx.y;
    size_t idx = (size_t)s * DIM + d;
    out[idx] = x[idx] + temb[2 * DIM + d] * acc[idx];
}

// ---------------- launch -----------------------------------------------------
extern "C" void kernel_launch(void* const* d_in, const int* in_sizes, int n_in,
                              void* d_out, int out_size)
{
    const float* x       = (const float*)d_in[0];
    const float* temb    = (const float*)d_in[1];
    const float* rcos    = (const float*)d_in[2];
    const float* rsin    = (const float*)d_in[3];
    const float* w1      = (const float*)d_in[4];
    const float* wo_attn = (const float*)d_in[5];
    const float* wo_mlp  = (const float*)d_in[6];
    const float* nqw     = (const float*)d_in[7];
    const float* nkw     = (const float*)d_in[8];
    float* out = (float*)d_out;

    float *h, *P, *Qb, *Kb, *Vb, *attn, *mlp, *acc, *w1r, *woar, *womr;
    cudaGetSymbolAddress((void**)&h,    g_h);
    cudaGetSymbolAddress((void**)&P,    g_P);
    cudaGetSymbolAddress((void**)&Qb,   g_Qb);
    cudaGetSymbolAddress((void**)&Kb,   g_Kb);
    cudaGetSymbolAddress((void**)&Vb,   g_Vb);
    cudaGetSymbolAddress((void**)&attn, g_attn);
    cudaGetSymbolAddress((void**)&mlp,  g_mlp);
    cudaGetSymbolAddress((void**)&acc,  g_acc);
    cudaGetSymbolAddress((void**)&w1r,  g_w1r);
    cudaGetSymbolAddress((void**)&woar, g_woar);
    cudaGetSymbolAddress((void**)&womr, g_womr);

    // 0) round weights to tf32 (scratch copies)
    {
        int blocks = 148 * 8;
        k_round<<<blocks, 256>>>((const float4*)w1,      (float4*)w1r,
                                 (size_t)DIM * FOUT / 4);
        k_round<<<blocks, 256>>>((const float4*)wo_attn, (float4*)woar,
                                 (size_t)DIM * DIM / 4);
        k_round<<<blocks, 256>>>((const float4*)wo_mlp,  (float4*)womr,
                                 (size_t)MH * DIM / 4);
    }

    // 1) LayerNorm + modulation
    k_lnmod<<<S_LEN, 256>>>(x, temb, h);

    int mm_smem = 2 * (ASZ + BSZ) * (int)sizeof(float);
    cudaFuncSetAttribute(k_mm<false>, cudaFuncAttributeMaxDynamicSharedMemorySize, mm_smem);
    cudaFuncSetAttribute(k_mm<true>,  cudaFuncAttributeMaxDynamicSharedMemorySize, mm_smem);

    // 2) fused QKV+MLP projection: P = h @ w1
    {
        int tm = S_LEN / 128, tn = FOUT / 128;
        k_mm<false><<<tm * tn, 256, mm_smem>>>(h, w1r, P, S_LEN, FOUT, DIM, tm, tn);
    }

    // 3) QKV heads + RMSNorm + RoPE
    {
        dim3 g(S_LEN, HEADS);
        k_qkvprep<<<g, 128>>>(P, rcos, rsin, nqw, nkw, Qb, Kb, Vb);
    }

    // 4) attention (tf32 mma)
    {
        cudaFuncSetAttribute(k_attn2, cudaFuncAttributeMaxDynamicSharedMemorySize, ATTN_SMEM);
        dim3 g(S_LEN / 128, HEADS);
        k_attn2<<<g, 256, ATTN_SMEM>>>(Qb, Kb, Vb, attn);
    }

    // 5) SwiGLU
    {
        dim3 g(MH / 256, S_LEN);
        k_swiglu<<<g, 256>>>(P, mlp);
    }

    // 6) out = attn @ wo_attn ; 7) out += mlp @ wo_mlp
    {
        int tm = S_LEN / 128, tn = DIM / 128;
        k_mm<false><<<tm * tn, 256, mm_smem>>>(attn, woar, acc, S_LEN, DIM, DIM, tm, tn);
        k_mm<true><<<tm * tn, 256, mm_smem>>>(mlp, womr, acc, S_LEN, DIM, MH, tm, tn);
    }

    // 8) gated residual
    {
        dim3 g(DIM / 256, S_LEN);
        k_final<<<g, 256>>>(x, temb, acc, out);
    }
}

// round 7
// speedup vs baseline: 4.0681x; 1.0040x over previous
#include <cuda_runtime.h>
#include <math.h>
#include <stdint.h>

#define S_LEN 4096
#define DIM   3072
#define HEADS 24
#define HD    128
#define MH    9216
#define FOUT  27648      // 3*DIM + 2*MH
#define QKV   9216       // 3*DIM
#define EPS   1e-6f

// ---------------- scratch (device globals; no allocations allowed) ----------
__device__ float g_h   [(size_t)S_LEN * DIM];
__device__ float g_P   [(size_t)S_LEN * FOUT];
__device__ float g_Qb  [(size_t)HEADS * S_LEN * HD];
__device__ float g_Kb  [(size_t)HEADS * S_LEN * HD];
__device__ float g_Vb  [(size_t)HEADS * S_LEN * HD];
__device__ float g_attn[(size_t)S_LEN * DIM];
__device__ float g_mlp [(size_t)S_LEN * MH];
__device__ float g_acc [(size_t)S_LEN * DIM];

__device__ __forceinline__ float tf32r(float x) {
    unsigned u;
    asm("cvt.rna.tf32.f32 %0, %1;" : "=r"(u) : "f"(x));
    return __uint_as_float(u);
}
__device__ __forceinline__ uint32_t tf32u(float x) {
    unsigned u;
    asm("cvt.rna.tf32.f32 %0, %1;" : "=r"(u) : "f"(x));
    return u;
}
__device__ __forceinline__ void cp16(uint32_t s, const float* g) {
    asm volatile("cp.async.cg.shared.global [%0], [%1], 16;\n" :: "r"(s), "l"(g));
}
__device__ __forceinline__ void mma_tf32(float c[4],
    uint32_t a0, uint32_t a1, uint32_t a2, uint32_t a3, uint32_t b0, uint32_t b1)
{
    asm volatile(
        "mma.sync.aligned.m16n8k8.row.col.f32.tf32.tf32.f32 "
        "{%0,%1,%2,%3},{%4,%5,%6,%7},{%8,%9},{%0,%1,%2,%3};"
        : "+f"(c[0]), "+f"(c[1]), "+f"(c[2]), "+f"(c[3])
        : "r"(a0), "r"(a1), "r"(a2), "r"(a3), "r"(b0), "r"(b1));
}

// ---------------- kernel 1: LayerNorm + modulation --------------------------
__global__ __launch_bounds__(256) void k_lnmod(
    const float* __restrict__ x, const float* __restrict__ temb,
    float* __restrict__ h)
{
    int s = blockIdx.x;
    const float* xr = x + (size_t)s * DIM;
    float v[12];
    float lsum = 0.f, lsq = 0.f;
    #pragma unroll
    for (int i = 0; i < 12; i++) {
        float t = xr[threadIdx.x + i * 256];
        v[i] = t; lsum += t; lsq += t * t;
    }
    __shared__ float red[16];
    #pragma unroll
    for (int o = 16; o; o >>= 1) {
        lsum += __shfl_xor_sync(0xffffffffu, lsum, o);
        lsq  += __shfl_xor_sync(0xffffffffu, lsq,  o);
    }
    int w = threadIdx.x >> 5;
    if ((threadIdx.x & 31) == 0) { red[w] = lsum; red[8 + w] = lsq; }
    __syncthreads();
    float ssum = 0.f, ssq = 0.f;
    #pragma unroll
    for (int i = 0; i < 8; i++) { ssum += red[i]; ssq += red[8 + i]; }
    float mu  = ssum * (1.0f / DIM);
    float var = ssq * (1.0f / DIM) - mu * mu;
    float rs  = rsqrtf(var + EPS);
    float* hr = h + (size_t)s * DIM;
    #pragma unroll
    for (int i = 0; i < 12; i++) {
        int d = threadIdx.x + i * 256;
        float sc = temb[DIM + d];
        float sh = temb[d];
        hr[d] = tf32r((v[i] - mu) * rs * (1.f + sc) + sh);
    }
}

// ---------------- kernel 2: tf32 tensor-core GEMM, 128x256 CTA tile ----------
// C[M,N] (+)= A[M,K] * B[K,N].  B is RAW fp32; rounded to tf32 in registers.
// 256 thr = 8 warps (2m x 4n), warp tile 64x64, BK=32, 3-stage cp.async.
#define ASTR2 36
#define BSTR2 264
#define A_ST (128 * ASTR2)          // 4608 floats
#define B_ST (32 * BSTR2)           // 8448 floats
#define ST_FL (A_ST + B_ST)         // 13056 floats
#define MM_STAGES 3
#define MM_SMEM (MM_STAGES * ST_FL * 4)   // 156672 bytes

template <bool ACC>
__global__ __launch_bounds__(256, 1) void k_mm2(
    const float* __restrict__ A, const float* __restrict__ B,
    float* __restrict__ C, int M, int N, int K, int tiles_m, int tiles_n)
{
    extern __shared__ float smf[];

    // block swizzle (GROUP_M = 16)
    int pid = blockIdx.x;
    const int GROUPM = 16;
    int npg     = GROUPM * tiles_n;
    int groupid = pid / npg;
    int firstm  = groupid * GROUPM;
    int gsz     = min(GROUPM, tiles_m - firstm);
    int pm      = firstm + (pid % npg) % gsz;
    int pn      = (pid % npg) / gsz;
    int bm = pm * 128, bn = pn * 256;

    int tid  = threadIdx.x;
    int warp = tid >> 5, lane = tid & 31;
    int wm = warp & 1, wn = warp >> 1;        // 2 x 4 warp grid
    int gid = lane >> 2, tid4 = lane & 3;

    float acc[4][8][4];
    #pragma unroll
    for (int i = 0; i < 4; i++)
        #pragma unroll
        for (int j = 0; j < 8; j++)
            #pragma unroll
            for (int q = 0; q < 4; q++) acc[i][j][q] = 0.f;

    uint32_t smb = (uint32_t)__cvta_generic_to_shared(smf);

    // loader geometry
    // A: 4 chunks/thread: id = tid + i*256 -> r=id>>3, c=id&7
    // B: 8 chunks/thread: id = tid + i*256 -> r=id>>6, c=id&63
    const float* Ag = A + (size_t)bm * K;
    const float* Bg = B + bn;

    #define MM_LOAD(KB, SS)                                                     \
    {                                                                           \
        int kt_ = (KB) * 32;                                                    \
        uint32_t sa_ = smb + (uint32_t)((SS) * ST_FL) * 4u;                     \
        uint32_t sb_ = sa_ + (uint32_t)A_ST * 4u;                               \
        _Pragma("unroll")                                                       \
        for (int i_ = 0; i_ < 4; i_++) {                                        \
            int id_ = tid + i_ * 256;                                           \
            int r_ = id_ >> 3, c_ = id_ & 7;                                    \
            cp16(sa_ + (uint32_t)(r_ * ASTR2 + c_ * 4) * 4u,                    \
                 Ag + (size_t)r_ * K + kt_ + c_ * 4);                           \
        }                                                                       \
        _Pragma("unroll")                                                       \
        for (int i_ = 0; i_ < 8; i_++) {                                        \
            int id_ = tid + i_ * 256;                                           \
            int r_ = id_ >> 6, c_ = id_ & 63;                                   \
            cp16(sb_ + (uint32_t)(r_ * BSTR2 + c_ * 4) * 4u,                    \
                 Bg + (size_t)(kt_ + r_) * N + c_ * 4);                         \
        }                                                                       \
        asm volatile("cp.async.commit_group;\n");                               \
    }

    int ntiles = K >> 5;

    MM_LOAD(0, 0)
    if (ntiles > 1) MM_LOAD(1, 1)

    for (int t = 0; t < ntiles; t++) {
        if (t + 2 < ntiles) {
            MM_LOAD(t + 2, (t + 2) % MM_STAGES)
            asm volatile("cp.async.wait_group 2;\n");
        } else if (t + 1 < ntiles) {
            asm volatile("cp.async.wait_group 1;\n");
        } else {
            asm volatile("cp.async.wait_group 0;\n");
        }
        __syncthreads();

        const float* Asp = smf + (t % MM_STAGES) * ST_FL;
        const float* Bsp = Asp + A_ST;

        #pragma unroll
        for (int k8 = 0; k8 < 4; k8++) {
            int k0 = k8 * 8;
            uint32_t af[4][4], bf[8][2];
            #pragma unroll
            for (int mt = 0; mt < 4; mt++) {
                int r = wm * 64 + mt * 16 + gid;
                af[mt][0] = __float_as_uint(Asp[r * ASTR2 + k0 + tid4]);
                af[mt][1] = __float_as_uint(Asp[(r + 8) * ASTR2 + k0 + tid4]);
                af[mt][2] = __float_as_uint(Asp[r * ASTR2 + k0 + tid4 + 4]);
                af[mt][3] = __float_as_uint(Asp[(r + 8) * ASTR2 + k0 + tid4 + 4]);
            }
            #pragma unroll
            for (int nt = 0; nt < 8; nt++) {
                int cn = wn * 64 + nt * 8 + gid;
                bf[nt][0] = tf32u(Bsp[(k0 + tid4) * BSTR2 + cn]);
                bf[nt][1] = tf32u(Bsp[(k0 + tid4 + 4) * BSTR2 + cn]);
            }
            #pragma unroll
            for (int mt = 0; mt < 4; mt++)
                #pragma unroll
                for (int nt = 0; nt < 8; nt++)
                    mma_tf32(acc[mt][nt], af[mt][0], af[mt][1], af[mt][2], af[mt][3],
                             bf[nt][0], bf[nt][1]);
        }
        __syncthreads();
    }

    // epilogue
    #pragma unroll
    for (int mt = 0; mt < 4; mt++) {
        int r0 = bm + wm * 64 + mt * 16 + gid;
        #pragma unroll
        for (int nt = 0; nt < 8; nt++) {
            int c0 = bn + wn * 64 + nt * 8 + tid4 * 2;
            float2* p0 = (float2*)(C + (size_t)r0 * N + c0);
            float2* p1 = (float2*)(C + (size_t)(r0 + 8) * N + c0);
            float2 v0 = make_float2(acc[mt][nt][0], acc[mt][nt][1]);
            float2 v1 = make_float2(acc[mt][nt][2], acc[mt][nt][3]);
            if (ACC) {
                float2 o0 = *p0, o1 = *p1;
                v0.x += o0.x; v0.y += o0.y;
                v1.x += o1.x; v1.y += o1.y;
            }
            *p0 = v0;
            *p1 = v1;
        }
    }
}

// ---------------- kernel 3: QKV extract + RMSNorm + RoPE ---------------------
__global__ __launch_bounds__(128) void k_qkvprep(
    const float* __restrict__ P, const float* __restrict__ cosb,
    const float* __restrict__ sinb, const float* __restrict__ nqw,
    const float* __restrict__ nkw,
    float* __restrict__ Qb, float* __restrict__ Kb, float* __restrict__ Vb)
{
    int s = blockIdx.x, h = blockIdx.y, d = threadIdx.x;
    const float* row = P + (size_t)s * FOUT + h * HD;
    float q = row[d];
    float k = row[DIM + d];
    float v = row[2 * DIM + d];

    __shared__ float sQ[HD], sK[HD], sred[8];
    float sq = q * q, sk = k * k;
    #pragma unroll
    for (int o = 16; o; o >>= 1) {
        sq += __shfl_xor_sync(0xffffffffu, sq, o);
        sk += __shfl_xor_sync(0xffffffffu, sk, o);
    }
    int w = d >> 5;
    if ((d & 31) == 0) { sred[w] = sq; sred[4 + w] = sk; }
    __syncthreads();
    float ssq = sred[0] + sred[1] + sred[2] + sred[3];
    float ssk = sred[4] + sred[5] + sred[6] + sred[7];
    float qn = q * rsqrtf(ssq * (1.0f / HD) + EPS) * nqw[d];
    float kn = k * rsqrtf(ssk * (1.0f / HD) + EPS) * nkw[d];
    sQ[d] = qn; sK[d] = kn;
    __syncthreads();
    float qrot = (d & 1) ? sQ[d - 1] : -sQ[d + 1];
    float krot = (d & 1) ? sK[d - 1] : -sK[d + 1];
    float c  = cosb[(size_t)s * HD + d];
    float sn = sinb[(size_t)s * HD + d];
    size_t o = ((size_t)h * S_LEN + s) * HD + d;
    Qb[o] = qn * c + qrot * sn;
    Kb[o] = kn * c + krot * sn;
    Vb[o] = v;
}

// ---------------- kernel 4: flash attention (tf32 mma.sync) ------------------
#define KV_STR 132
#define KV_STAGE (64 * KV_STR)
#define P_STR 68
#define PW_SZ (16 * P_STR)
#define ATTN_SMEM ((4 * KV_STAGE + 8 * PW_SZ) * 4)

__global__ __launch_bounds__(256, 1) void k_attn2(
    const float* __restrict__ Qb, const float* __restrict__ Kb,
    const float* __restrict__ Vb, float* __restrict__ attn)
{
    extern __shared__ float sm[];
    float* VsBase = sm + 2 * KV_STAGE;
    float* Ps     = sm + 4 * KV_STAGE;

    int h  = blockIdx.y;
    int q0 = blockIdx.x * 128;
    int tid = threadIdx.x, warp = tid >> 5, lane = tid & 31;
    int gid = lane >> 2, tid4 = lane & 3;
    float* Pw = Ps + warp * PW_SZ;
    const float scale = 0.08838834764831843f;
    uint32_t smbase = (uint32_t)__cvta_generic_to_shared(sm);

    const float* Qg = Qb + ((size_t)h * S_LEN + q0) * HD;
    for (int i = tid; i < 128 * 32; i += 256) {
        int r = i >> 5, c4 = (i & 31) << 2;
        float4 v = *(const float4*)(Qg + (size_t)r * HD + c4);
        v.x *= scale; v.y *= scale; v.z *= scale; v.w *= scale;
        *(float4*)&sm[r * KV_STR + c4] = v;
    }
    __syncthreads();
    uint32_t qf[16][4];
    {
        int r0 = warp * 16 + gid;
        #pragma unroll
        for (int kc = 0; kc < 16; kc++) {
            qf[kc][0] = __float_as_uint(sm[r0 * KV_STR + kc * 8 + tid4]);
            qf[kc][1] = __float_as_uint(sm[(r0 + 8) * KV_STR + kc * 8 + tid4]);
            qf[kc][2] = __float_as_uint(sm[r0 * KV_STR + kc * 8 + tid4 + 4]);
            qf[kc][3] = __float_as_uint(sm[(r0 + 8) * KV_STR + kc * 8 + tid4 + 4]);
        }
    }
    __syncthreads();

    float m0 = -1e30f, m1 = -1e30f, l0 = 0.f, l1 = 0.f;
    float o[16][4];
    #pragma unroll
    for (int dt = 0; dt < 16; dt++)
        #pragma unroll
        for (int j = 0; j < 4; j++) o[dt][j] = 0.f;

    #define LOAD_KV(T, SS)                                                       \
    {                                                                            \
        const float* Kg = Kb + ((size_t)h * S_LEN + (T) * 64) * HD;              \
        const float* Vg = Vb + ((size_t)h * S_LEN + (T) * 64) * HD;              \
        uint32_t ks = smbase + (uint32_t)((SS) * KV_STAGE) * 4u;                 \
        uint32_t vs = smbase + (uint32_t)((2 + (SS)) * KV_STAGE) * 4u;           \
        _Pragma("unroll")                                                        \
        for (int i = 0; i < 8; i++) {                                            \
            int idx = tid + i * 256;                                             \
            int r = idx >> 5, c4 = (idx & 31) << 2;                              \
            cp16(ks + (uint32_t)(r * KV_STR + c4) * 4u, Kg + (size_t)r * HD + c4);\
            cp16(vs + (uint32_t)(r * KV_STR + c4) * 4u, Vg + (size_t)r * HD + c4);\
        }                                                                        \
        asm volatile("cp.async.commit_group;\n");                                \
    }

    LOAD_KV(0, 0)

    for (int t = 0; t < 64; t++) {
        if (t + 1 < 64) {
            LOAD_KV(t + 1, (t + 1) & 1)
            asm volatile("cp.async.wait_group 1;\n");
        } else {
            asm volatile("cp.async.wait_group 0;\n");
        }
        __syncthreads();

        const float* Ks = sm + (t & 1) * KV_STAGE;
        const float* Vs = VsBase + (t & 1) * KV_STAGE;

        float sa[8][4];
        #pragma unroll
        for (int nt = 0; nt < 8; nt++)
            #pragma unroll
            for (int j = 0; j < 4; j++) sa[nt][j] = 0.f;
        #pragma unroll
        for (int nt = 0; nt < 8; nt++) {
            const float* Kr = Ks + (nt * 8 + gid) * KV_STR;
            #pragma unroll
            for (int kc = 0; kc < 16; kc++) {
                uint32_t b0 = __float_as_uint(Kr[kc * 8 + tid4]);
                uint32_t b1 = __float_as_uint(Kr[kc * 8 + tid4 + 4]);
                mma_tf32(sa[nt], qf[kc][0], qf[kc][1], qf[kc][2], qf[kc][3], b0, b1);
            }
        }

        float mx0 = -1e30f, mx1 = -1e30f;
        #pragma unroll
        for (int nt = 0; nt < 8; nt++) {
            mx0 = fmaxf(mx0, fmaxf(sa[nt][0], sa[nt][1]));
            mx1 = fmaxf(mx1, fmaxf(sa[nt][2], sa[nt][3]));
        }
        mx0 = fmaxf(mx0, __shfl_xor_sync(0xffffffffu, mx0, 1));
        mx0 = fmaxf(mx0, __shfl_xor_sync(0xffffffffu, mx0, 2));
        mx1 = fmaxf(mx1, __shfl_xor_sync(0xffffffffu, mx1, 1));
        mx1 = fmaxf(mx1, __shfl_xor_sync(0xffffffffu, mx1, 2));
        float nm0 = fmaxf(m0, mx0), nm1 = fmaxf(m1, mx1);
        float corr0 = __expf(m0 - nm0), corr1 = __expf(m1 - nm1);
        float rs0 = 0.f, rs1 = 0.f;
        #pragma unroll
        for (int nt = 0; nt < 8; nt++) {
            float p0 = __expf(sa[nt][0] - nm0);
            float p1 = __expf(sa[nt][1] - nm0);
            float p2 = __expf(sa[nt][2] - nm1);
            float p3 = __expf(sa[nt][3] - nm1);
            rs0 += p0 + p1; rs1 += p2 + p3;
            *(float2*)&Pw[gid * P_STR + nt * 8 + 2 * tid4]       = make_float2(p0, p1);
            *(float2*)&Pw[(gid + 8) * P_STR + nt * 8 + 2 * tid4] = make_float2(p2, p3);
        }
        rs0 += __shfl_xor_sync(0xffffffffu, rs0, 1);
        rs0 += __shfl_xor_sync(0xffffffffu, rs0, 2);
        rs1 += __shfl_xor_sync(0xffffffffu, rs1, 1);
        rs1 += __shfl_xor_sync(0xffffffffu, rs1, 2);
        l0 = l0 * corr0 + rs0;
        l1 = l1 * corr1 + rs1;
        m0 = nm0; m1 = nm1;
        #pragma unroll
        for (int dt = 0; dt < 16; dt++) {
            o[dt][0] *= corr0; o[dt][1] *= corr0;
            o[dt][2] *= corr1; o[dt][3] *= corr1;
        }
        __syncwarp();

        #pragma unroll
        for (int kc = 0; kc < 8; kc++) {
            uint32_t a0 = __float_as_uint(Pw[gid * P_STR + kc * 8 + tid4]);
            uint32_t a1 = __float_as_uint(Pw[(gid + 8) * P_STR + kc * 8 + tid4]);
            uint32_t a2 = __float_as_uint(Pw[gid * P_STR + kc * 8 + tid4 + 4]);
            uint32_t a3 = __float_as_uint(Pw[(gid + 8) * P_STR + kc * 8 + tid4 + 4]);
            const float* Vr0 = Vs + (kc * 8 + tid4) * KV_STR;
            const float* Vr1 = Vs + (kc * 8 + tid4 + 4) * KV_STR;
            #pragma unroll
            for (int dt = 0; dt < 16; dt++) {
                uint32_t b0 = __float_as_uint(Vr0[dt * 8 + gid]);
                uint32_t b1 = __float_as_uint(Vr1[dt * 8 + gid]);
                mma_tf32(o[dt], a0, a1, a2, a3, b0, b1);
            }
        }
        __syncthreads();
    }

    float inv0 = 1.0f / l0, inv1 = 1.0f / l1;
    int r0 = q0 + warp * 16 + gid;
    #pragma unroll
    for (int dt = 0; dt < 16; dt++) {
        int col = h * HD + dt * 8 + 2 * tid4;
        *(float2*)&attn[(size_t)r0 * DIM + col] =
            make_float2(tf32r(o[dt][0] * inv0), tf32r(o[dt][1] * inv0));
        *(float2*)&attn[(size_t)(r0 + 8) * DIM + col] =
            make_float2(tf32r(o[dt][2] * inv1), tf32r(o[dt][3] * inv1));
    }
}

// ---------------- kernel 5: SwiGLU ------------------------------------------
__global__ __launch_bounds__(256) void k_swiglu(
    const float* __restrict__ P, float* __restrict__ mlp)
{
    int j = blockIdx.x * 256 + threadIdx.x;
    int s = blockIdx.y;
    float a = P[(size_t)s * FOUT + QKV + j];
    float b = P[(size_t)s * FOUT + QKV + MH + j];
    mlp[(size_t)s * MH + j] = tf32r((a / (1.f + __expf(-a))) * b);
}

// ---------------- kernel 6: gated residual ----------------------------------
__global__ __launch_bounds__(256) void k_final(
    const float* __restrict__ x, const float* __restrict__ temb,
    const float* __restrict__ acc, float* __restrict__ out)
{
    int d = blockIdx.x * 256 + threadIdx.x;
    int s = blockIdx.y;
    size_t idx = (size_t)s * DIM + d;
    out[idx] = x[idx] + temb[2 * DIM + d] * acc[idx];
}

// ---------------- launch -----------------------------------------------------
extern "C" void kernel_launch(void* const* d_in, const int* in_sizes, int n_in,
                              void* d_out, int out_size)
{
    const float* x       = (const float*)d_in[0];
    const float* temb    = (const float*)d_in[1];
    const float* rcos    = (const float*)d_in[2];
    const float* rsin    = (const float*)d_in[3];
    const float* w1      = (const float*)d_in[4];
    const float* wo_attn = (const float*)d_in[5];
    const float* wo_mlp  = (const float*)d_in[6];
    const float* nqw     = (const float*)d_in[7];
    const float* nkw     = (const float*)d_in[8];
    float* out = (float*)d_out;

    float *h, *P, *Qb, *Kb, *Vb, *attn, *mlp, *acc;
    cudaGetSymbolAddress((void**)&h,    g_h);
    cudaGetSymbolAddress((void**)&P,    g_P);
    cudaGetSymbolAddress((void**)&Qb,   g_Qb);
    cudaGetSymbolAddress((void**)&Kb,   g_Kb);
    cudaGetSymbolAddress((void**)&Vb,   g_Vb);
    cudaGetSymbolAddress((void**)&attn, g_attn);
    cudaGetSymbolAddress((void**)&mlp,  g_mlp);
    cudaGetSymbolAddress((void**)&acc,  g_acc);

    // 1) LayerNorm + modulation (tf32-rounded activations)
    k_lnmod<<<S_LEN, 256>>>(x, temb, h);

    cudaFuncSetAttribute(k_mm2<false>, cudaFuncAttributeMaxDynamicSharedMemorySize, MM_SMEM);
    cudaFuncSetAttribute(k_mm2<true>,  cudaFuncAttributeMaxDynamicSharedMemorySize, MM_SMEM);

    // 2) fused QKV+MLP projection: P = h @ w1   [4096 x 27648]
    {
        int tm = S_LEN / 128, tn = FOUT / 256;
        k_mm2<false><<<tm * tn, 256, MM_SMEM>>>(h, w1, P, S_LEN, FOUT, DIM, tm, tn);
    }

    // 3) QKV heads + RMSNorm + RoPE
    {
        dim3 g(S_LEN, HEADS);
        k_qkvprep<<<g, 128>>>(P, rcos, rsin, nqw, nkw, Qb, Kb, Vb);
    }

    // 4) attention
    {
        cudaFuncSetAttribute(k_attn2, cudaFuncAttributeMaxDynamicSharedMemorySize, ATTN_SMEM);
        dim3 g(S_LEN / 128, HEADS);
        k_attn2<<<g, 256, ATTN_SMEM>>>(Qb, Kb, Vb, attn);
    }

    // 5) SwiGLU
    {
        dim3 g(MH / 256, S_LEN);
        k_swiglu<<<g, 256>>>(P, mlp);
    }

    // 6) acc = attn @ wo_attn ; 7) acc += mlp @ wo_mlp
    {
        int tm = S_LEN / 128, tn = DIM / 256;
        k_mm2<false><<<tm * tn, 256, MM_SMEM>>>(attn, wo_attn, acc, S_LEN, DIM, DIM, tm, tn);
        k_mm2<true><<<tm * tn, 256, MM_SMEM>>>(mlp, wo_mlp, acc, S_LEN, DIM, MH, tm, tn);
    }

    // 8) gated residual
    {
        dim3 g(DIM / 256, S_LEN);
        k_final<<<g, 256>>>(x, temb, acc, out);
    }
}

// round 8
// speedup vs baseline: 4.5062x; 1.1077x over previous
#include <cuda_runtime.h>
#include <math.h>
#include <stdint.h>

#define S_LEN 4096
#define DIM   3072
#define HEADS 24
#define HD    128
#define MH    9216
#define FOUT  27648      // 3*DIM + 2*MH
#define QKV   9216       // 3*DIM
#define CATK  12288      // DIM + MH
#define EPS   1e-6f

// ---------------- scratch (device globals; no allocations allowed) ----------
__device__ float g_h   [(size_t)S_LEN * DIM];
__device__ float g_P   [(size_t)S_LEN * FOUT];
__device__ float g_Qb  [(size_t)HEADS * S_LEN * HD];
__device__ float g_Kb  [(size_t)HEADS * S_LEN * HD];
__device__ float g_Vb  [(size_t)HEADS * S_LEN * HD];
__device__ float g_cat [(size_t)S_LEN * CATK];   // [attn | swiglu]

__device__ __forceinline__ float tf32r(float x) {
    unsigned u;
    asm("cvt.rna.tf32.f32 %0, %1;" : "=r"(u) : "f"(x));
    return __uint_as_float(u);
}
__device__ __forceinline__ uint32_t tf32u(float x) {
    unsigned u;
    asm("cvt.rna.tf32.f32 %0, %1;" : "=r"(u) : "f"(x));
    return u;
}
__device__ __forceinline__ void cp16(uint32_t s, const float* g) {
    asm volatile("cp.async.cg.shared.global [%0], [%1], 16;\n" :: "r"(s), "l"(g));
}
__device__ __forceinline__ void mma_tf32(float c[4],
    uint32_t a0, uint32_t a1, uint32_t a2, uint32_t a3, uint32_t b0, uint32_t b1)
{
    asm volatile(
        "mma.sync.aligned.m16n8k8.row.col.f32.tf32.tf32.f32 "
        "{%0,%1,%2,%3},{%4,%5,%6,%7},{%8,%9},{%0,%1,%2,%3};"
        : "+f"(c[0]), "+f"(c[1]), "+f"(c[2]), "+f"(c[3])
        : "r"(a0), "r"(a1), "r"(a2), "r"(a3), "r"(b0), "r"(b1));
}

// ---------------- kernel 1: LayerNorm + modulation --------------------------
__global__ __launch_bounds__(256) void k_lnmod(
    const float* __restrict__ x, const float* __restrict__ temb,
    float* __restrict__ h)
{
    int s = blockIdx.x;
    const float* xr = x + (size_t)s * DIM;
    float v[12];
    float lsum = 0.f, lsq = 0.f;
    #pragma unroll
    for (int i = 0; i < 12; i++) {
        float t = xr[threadIdx.x + i * 256];
        v[i] = t; lsum += t; lsq += t * t;
    }
    __shared__ float red[16];
    #pragma unroll
    for (int o = 16; o; o >>= 1) {
        lsum += __shfl_xor_sync(0xffffffffu, lsum, o);
        lsq  += __shfl_xor_sync(0xffffffffu, lsq,  o);
    }
    int w = threadIdx.x >> 5;
    if ((threadIdx.x & 31) == 0) { red[w] = lsum; red[8 + w] = lsq; }
    __syncthreads();
    float ssum = 0.f, ssq = 0.f;
    #pragma unroll
    for (int i = 0; i < 8; i++) { ssum += red[i]; ssq += red[8 + i]; }
    float mu  = ssum * (1.0f / DIM);
    float var = ssq * (1.0f / DIM) - mu * mu;
    float rs  = rsqrtf(var + EPS);
    float* hr = h + (size_t)s * DIM;
    #pragma unroll
    for (int i = 0; i < 12; i++) {
        int d = threadIdx.x + i * 256;
        float sc = temb[DIM + d];
        float sh = temb[d];
        hr[d] = tf32r((v[i] - mu) * rs * (1.f + sc) + sh);
    }
}

// ---------------- kernel 2: tf32 GEMM, 128x128 CTA, 2 CTAs/SM ---------------
// C[M,N] (+epilogue) = A[M,K] * B[K,N].  B raw fp32, tf32-rounded in regs.
// B rows k<K1 come from B1, else B2 (concat weight). FINAL epilogue:
// out = x + gate * acc.
#define ASTR3 36
#define BSTR3 136
#define A_ST3 (128 * ASTR3)         // 4608 floats
#define B_ST3 (32 * BSTR3)          // 4352 floats
#define ST3   (A_ST3 + B_ST3)       // 8960 floats
#define MM_STG 3
#define MM_SMEM3 (MM_STG * ST3 * 4) // 107520 bytes

template <bool FINAL>
__global__ __launch_bounds__(256, 2) void k_mm3(
    const float* __restrict__ A, const float* __restrict__ B1,
    const float* __restrict__ B2, float* __restrict__ C,
    int M, int N, int K, int K1, int tiles_m, int tiles_n,
    const float* __restrict__ xres, const float* __restrict__ temb)
{
    extern __shared__ float smf[];

    // block swizzle (GROUP_M = 16)
    int pid = blockIdx.x;
    const int GROUPM = 16;
    int npg     = GROUPM * tiles_n;
    int groupid = pid / npg;
    int firstm  = groupid * GROUPM;
    int gsz     = min(GROUPM, tiles_m - firstm);
    int pm      = firstm + (pid % npg) % gsz;
    int pn      = (pid % npg) / gsz;
    int bm = pm * 128, bn = pn * 128;

    int tid  = threadIdx.x;
    int warp = tid >> 5, lane = tid & 31;
    int wm = warp & 1, wn = warp >> 1;        // 2m x 4n warp grid
    int gid = lane >> 2, tid4 = lane & 3;

    float acc[4][4][4];
    #pragma unroll
    for (int i = 0; i < 4; i++)
        #pragma unroll
        for (int j = 0; j < 4; j++)
            #pragma unroll
            for (int q = 0; q < 4; q++) acc[i][j][q] = 0.f;

    uint32_t smb = (uint32_t)__cvta_generic_to_shared(smf);
    const float* Ag = A + (size_t)bm * K;

    // A: 4 chunks: id=tid+i*256 -> r=id>>3 (0..127), c=id&7
    // B: 4 chunks: id=tid+i*256 -> r=id>>5 (0..31),  c=id&31
    #define MM3_LOAD(KB, SS)                                                    \
    {                                                                           \
        int kt_ = (KB) * 32;                                                    \
        uint32_t sa_ = smb + (uint32_t)((SS) * ST3) * 4u;                       \
        uint32_t sb_ = sa_ + (uint32_t)A_ST3 * 4u;                              \
        _Pragma("unroll")                                                       \
        for (int i_ = 0; i_ < 4; i_++) {                                        \
            int id_ = tid + i_ * 256;                                           \
            int r_ = id_ >> 3, c_ = id_ & 7;                                    \
            cp16(sa_ + (uint32_t)(r_ * ASTR3 + c_ * 4) * 4u,                    \
                 Ag + (size_t)r_ * K + kt_ + c_ * 4);                           \
        }                                                                       \
        _Pragma("unroll")                                                       \
        for (int i_ = 0; i_ < 4; i_++) {                                        \
            int id_ = tid + i_ * 256;                                           \
            int r_ = id_ >> 5, c_ = id_ & 31;                                   \
            int rk_ = kt_ + r_;                                                 \
            const float* bp_ = (rk_ < K1)                                       \
                ? B1 + (size_t)rk_ * N : B2 + (size_t)(rk_ - K1) * N;           \
            cp16(sb_ + (uint32_t)(r_ * BSTR3 + c_ * 4) * 4u, bp_ + bn + c_ * 4);\
        }                                                                       \
        asm volatile("cp.async.commit_group;\n");                               \
    }

    int ntiles = K >> 5;

    MM3_LOAD(0, 0)
    MM3_LOAD(1, 1)

    for (int t = 0; t < ntiles; t++) {
        if (t + 2 < ntiles) {
            MM3_LOAD(t + 2, (t + 2) % MM_STG)
            asm volatile("cp.async.wait_group 2;\n");
        } else if (t + 1 < ntiles) {
            asm volatile("cp.async.wait_group 1;\n");
        } else {
            asm volatile("cp.async.wait_group 0;\n");
        }
        __syncthreads();

        const float* Asp = smf + (t % MM_STG) * ST3;
        const float* Bsp = Asp + A_ST3;

        #pragma unroll
        for (int k8 = 0; k8 < 4; k8++) {
            int k0 = k8 * 8;
            uint32_t af[4][4], bf[4][2];
            #pragma unroll
            for (int mt = 0; mt < 4; mt++) {
                int r = wm * 64 + mt * 16 + gid;
                af[mt][0] = __float_as_uint(Asp[r * ASTR3 + k0 + tid4]);
                af[mt][1] = __float_as_uint(Asp[(r + 8) * ASTR3 + k0 + tid4]);
                af[mt][2] = __float_as_uint(Asp[r * ASTR3 + k0 + tid4 + 4]);
                af[mt][3] = __float_as_uint(Asp[(r + 8) * ASTR3 + k0 + tid4 + 4]);
            }
            #pragma unroll
            for (int nt = 0; nt < 4; nt++) {
                int cn = wn * 32 + nt * 8 + gid;
                bf[nt][0] = tf32u(Bsp[(k0 + tid4) * BSTR3 + cn]);
                bf[nt][1] = tf32u(Bsp[(k0 + tid4 + 4) * BSTR3 + cn]);
            }
            #pragma unroll
            for (int mt = 0; mt < 4; mt++)
                #pragma unroll
                for (int nt = 0; nt < 4; nt++)
                    mma_tf32(acc[mt][nt], af[mt][0], af[mt][1], af[mt][2], af[mt][3],
                             bf[nt][0], bf[nt][1]);
        }
        __syncthreads();
    }

    // epilogue
    #pragma unroll
    for (int mt = 0; mt < 4; mt++) {
        int r0 = bm + wm * 64 + mt * 16 + gid;
        #pragma unroll
        for (int nt = 0; nt < 4; nt++) {
            int c0 = bn + wn * 32 + nt * 8 + tid4 * 2;
            float2 v0 = make_float2(acc[mt][nt][0], acc[mt][nt][1]);
            float2 v1 = make_float2(acc[mt][nt][2], acc[mt][nt][3]);
            float2* p0 = (float2*)(C + (size_t)r0 * N + c0);
            float2* p1 = (float2*)(C + (size_t)(r0 + 8) * N + c0);
            if (FINAL) {
                float gx = temb[2 * DIM + c0], gy = temb[2 * DIM + c0 + 1];
                float2 x0 = *(const float2*)(xres + (size_t)r0 * N + c0);
                float2 x1 = *(const float2*)(xres + (size_t)(r0 + 8) * N + c0);
                v0.x = x0.x + gx * v0.x; v0.y = x0.y + gy * v0.y;
                v1.x = x1.x + gx * v1.x; v1.y = x1.y + gy * v1.y;
            }
            *p0 = v0;
            *p1 = v1;
        }
    }
}

// ---------------- kernel 3: QKV extract + RMSNorm + RoPE ---------------------
__global__ __launch_bounds__(128) void k_qkvprep(
    const float* __restrict__ P, const float* __restrict__ cosb,
    const float* __restrict__ sinb, const float* __restrict__ nqw,
    const float* __restrict__ nkw,
    float* __restrict__ Qb, float* __restrict__ Kb, float* __restrict__ Vb)
{
    int s = blockIdx.x, h = blockIdx.y, d = threadIdx.x;
    const float* row = P + (size_t)s * FOUT + h * HD;
    float q = row[d];
    float k = row[DIM + d];
    float v = row[2 * DIM + d];

    __shared__ float sQ[HD], sK[HD], sred[8];
    float sq = q * q, sk = k * k;
    #pragma unroll
    for (int o = 16; o; o >>= 1) {
        sq += __shfl_xor_sync(0xffffffffu, sq, o);
        sk += __shfl_xor_sync(0xffffffffu, sk, o);
    }
    int w = d >> 5;
    if ((d & 31) == 0) { sred[w] = sq; sred[4 + w] = sk; }
    __syncthreads();
    float ssq = sred[0] + sred[1] + sred[2] + sred[3];
    float ssk = sred[4] + sred[5] + sred[6] + sred[7];
    float qn = q * rsqrtf(ssq * (1.0f / HD) + EPS) * nqw[d];
    float kn = k * rsqrtf(ssk * (1.0f / HD) + EPS) * nkw[d];
    sQ[d] = qn; sK[d] = kn;
    __syncthreads();
    float qrot = (d & 1) ? sQ[d - 1] : -sQ[d + 1];
    float krot = (d & 1) ? sK[d - 1] : -sK[d + 1];
    float c  = cosb[(size_t)s * HD + d];
    float sn = sinb[(size_t)s * HD + d];
    size_t o = ((size_t)h * S_LEN + s) * HD + d;
    Qb[o] = qn * c + qrot * sn;
    Kb[o] = kn * c + krot * sn;
    Vb[o] = v;
}

// ---------------- kernel 4: flash attention (tf32 mma.sync) ------------------
// K stride 132 (conflict-free QK b-frags); V stride 136 (conflict-free PV b-frags)
#define K_STR 132
#define V_STR 136
#define K_STAGE (64 * K_STR)
#define V_STAGE (64 * V_STR)
#define P_STR 68
#define PW_SZ (16 * P_STR)
#define ATTN_SMEM ((2 * K_STAGE + 2 * V_STAGE + 8 * PW_SZ) * 4)

__global__ __launch_bounds__(256, 1) void k_attn2(
    const float* __restrict__ Qb, const float* __restrict__ Kb,
    const float* __restrict__ Vb, float* __restrict__ attnout)
{
    extern __shared__ float sm[];
    float* VsBase = sm + 2 * K_STAGE;
    float* Ps     = sm + 2 * K_STAGE + 2 * V_STAGE;

    int h  = blockIdx.y;
    int q0 = blockIdx.x * 128;
    int tid = threadIdx.x, warp = tid >> 5, lane = tid & 31;
    int gid = lane >> 2, tid4 = lane & 3;
    float* Pw = Ps + warp * PW_SZ;
    const float scale = 0.08838834764831843f;
    uint32_t smbase = (uint32_t)__cvta_generic_to_shared(sm);

    const float* Qg = Qb + ((size_t)h * S_LEN + q0) * HD;
    for (int i = tid; i < 128 * 32; i += 256) {
        int r = i >> 5, c4 = (i & 31) << 2;
        float4 v = *(const float4*)(Qg + (size_t)r * HD + c4);
        v.x *= scale; v.y *= scale; v.z *= scale; v.w *= scale;
        *(float4*)&sm[r * K_STR + c4] = v;
    }
    __syncthreads();
    uint32_t qf[16][4];
    {
        int r0 = warp * 16 + gid;
        #pragma unroll
        for (int kc = 0; kc < 16; kc++) {
            qf[kc][0] = __float_as_uint(sm[r0 * K_STR + kc * 8 + tid4]);
            qf[kc][1] = __float_as_uint(sm[(r0 + 8) * K_STR + kc * 8 + tid4]);
            qf[kc][2] = __float_as_uint(sm[r0 * K_STR + kc * 8 + tid4 + 4]);
            qf[kc][3] = __float_as_uint(sm[(r0 + 8) * K_STR + kc * 8 + tid4 + 4]);
        }
    }
    __syncthreads();

    float m0 = -1e30f, m1 = -1e30f, l0 = 0.f, l1 = 0.f;
    float o[16][4];
    #pragma unroll
    for (int dt = 0; dt < 16; dt++)
        #pragma unroll
        for (int j = 0; j < 4; j++) o[dt][j] = 0.f;

    #define LOAD_KV(T, SS)                                                       \
    {                                                                            \
        const float* Kg = Kb + ((size_t)h * S_LEN + (T) * 64) * HD;              \
        const float* Vg = Vb + ((size_t)h * S_LEN + (T) * 64) * HD;              \
        uint32_t ks = smbase + (uint32_t)((SS) * K_STAGE) * 4u;                  \
        uint32_t vs = smbase + (uint32_t)(2 * K_STAGE + (SS) * V_STAGE) * 4u;    \
        _Pragma("unroll")                                                        \
        for (int i = 0; i < 8; i++) {                                            \
            int idx = tid + i * 256;                                             \
            int r = idx >> 5, c4 = (idx & 31) << 2;                              \
            cp16(ks + (uint32_t)(r * K_STR + c4) * 4u, Kg + (size_t)r * HD + c4);\
            cp16(vs + (uint32_t)(r * V_STR + c4) * 4u, Vg + (size_t)r * HD + c4);\
        }                                                                        \
        asm volatile("cp.async.commit_group;\n");                                \
    }

    LOAD_KV(0, 0)

    for (int t = 0; t < 64; t++) {
        if (t + 1 < 64) {
            LOAD_KV(t + 1, (t + 1) & 1)
            asm volatile("cp.async.wait_group 1;\n");
        } else {
            asm volatile("cp.async.wait_group 0;\n");
        }
        __syncthreads();

        const float* Ks = sm + (t & 1) * K_STAGE;
        const float* Vs = VsBase + (t & 1) * V_STAGE;

        float sa[8][4];
        #pragma unroll
        for (int nt = 0; nt < 8; nt++)
            #pragma unroll
            for (int j = 0; j < 4; j++) sa[nt][j] = 0.f;
        #pragma unroll
        for (int nt = 0; nt < 8; nt++) {
            const float* Kr = Ks + (nt * 8 + gid) * K_STR;
            #pragma unroll
            for (int kc = 0; kc < 16; kc++) {
                uint32_t b0 = __float_as_uint(Kr[kc * 8 + tid4]);
                uint32_t b1 = __float_as_uint(Kr[kc * 8 + tid4 + 4]);
                mma_tf32(sa[nt], qf[kc][0], qf[kc][1], qf[kc][2], qf[kc][3], b0, b1);
            }
        }

        float mx0 = -1e30f, mx1 = -1e30f;
        #pragma unroll
        for (int nt = 0; nt < 8; nt++) {
            mx0 = fmaxf(mx0, fmaxf(sa[nt][0], sa[nt][1]));
            mx1 = fmaxf(mx1, fmaxf(sa[nt][2], sa[nt][3]));
        }
        mx0 = fmaxf(mx0, __shfl_xor_sync(0xffffffffu, mx0, 1));
        mx0 = fmaxf(mx0, __shfl_xor_sync(0xffffffffu, mx0, 2));
        mx1 = fmaxf(mx1, __shfl_xor_sync(0xffffffffu, mx1, 1));
        mx1 = fmaxf(mx1, __shfl_xor_sync(0xffffffffu, mx1, 2));
        float nm0 = fmaxf(m0, mx0), nm1 = fmaxf(m1, mx1);
        float corr0 = __expf(m0 - nm0), corr1 = __expf(m1 - nm1);
        float rs0 = 0.f, rs1 = 0.f;
        #pragma unroll
        for (int nt = 0; nt < 8; nt++) {
            float p0 = __expf(sa[nt][0] - nm0);
            float p1 = __expf(sa[nt][1] - nm0);
            float p2 = __expf(sa[nt][2] - nm1);
            float p3 = __expf(sa[nt][3] - nm1);
            rs0 += p0 + p1; rs1 += p2 + p3;
            *(float2*)&Pw[gid * P_STR + nt * 8 + 2 * tid4]       = make_float2(p0, p1);
            *(float2*)&Pw[(gid + 8) * P_STR + nt * 8 + 2 * tid4] = make_float2(p2, p3);
        }
        rs0 += __shfl_xor_sync(0xffffffffu, rs0, 1);
        rs0 += __shfl_xor_sync(0xffffffffu, rs0, 2);
        rs1 += __shfl_xor_sync(0xffffffffu, rs1, 1);
        rs1 += __shfl_xor_sync(0xffffffffu, rs1, 2);
        l0 = l0 * corr0 + rs0;
        l1 = l1 * corr1 + rs1;
        m0 = nm0; m1 = nm1;
        #pragma unroll
        for (int dt = 0; dt < 16; dt++) {
            o[dt][0] *= corr0; o[dt][1] *= corr0;
            o[dt][2] *= corr1; o[dt][3] *= corr1;
        }
        __syncwarp();

        #pragma unroll
        for (int kc = 0; kc < 8; kc++) {
            uint32_t a0 = __float_as_uint(Pw[gid * P_STR + kc * 8 + tid4]);
            uint32_t a1 = __float_as_uint(Pw[(gid + 8) * P_STR + kc * 8 + tid4]);
            uint32_t a2 = __float_as_uint(Pw[gid * P_STR + kc * 8 + tid4 + 4]);
            uint32_t a3 = __float_as_uint(Pw[(gid + 8) * P_STR + kc * 8 + tid4 + 4]);
            const float* Vr0 = Vs + (kc * 8 + tid4) * V_STR;
            const float* Vr1 = Vs + (kc * 8 + tid4 + 4) * V_STR;
            #pragma unroll
            for (int dt = 0; dt < 16; dt++) {
                uint32_t b0 = __float_as_uint(Vr0[dt * 8 + gid]);
                uint32_t b1 = __float_as_uint(Vr1[dt * 8 + gid]);
                mma_tf32(o[dt], a0, a1, a2, a3, b0, b1);
            }
        }
        __syncthreads();
    }

    // epilogue -> g_cat columns [h*128, h*128+128)
    float inv0 = 1.0f / l0, inv1 = 1.0f / l1;
    int r0 = q0 + warp * 16 + gid;
    #pragma unroll
    for (int dt = 0; dt < 16; dt++) {
        int col = h * HD + dt * 8 + 2 * tid4;
        *(float2*)&attnout[(size_t)r0 * CATK + col] =
            make_float2(tf32r(o[dt][0] * inv0), tf32r(o[dt][1] * inv0));
        *(float2*)&attnout[(size_t)(r0 + 8) * CATK + col] =
            make_float2(tf32r(o[dt][2] * inv1), tf32r(o[dt][3] * inv1));
    }
}

// ---------------- kernel 5: SwiGLU -> concat buffer --------------------------
__global__ __launch_bounds__(256) void k_swiglu(
    const float* __restrict__ P, float* __restrict__ cat)
{
    int j = blockIdx.x * 256 + threadIdx.x;
    int s = blockIdx.y;
    float a = P[(size_t)s * FOUT + QKV + j];
    float b = P[(size_t)s * FOUT + QKV + MH + j];
    cat[(size_t)s * CATK + DIM + j] = tf32r((a / (1.f + __expf(-a))) * b);
}

// ---------------- launch -----------------------------------------------------
extern "C" void kernel_launch(void* const* d_in, const int* in_sizes, int n_in,
                              void* d_out, int out_size)
{
    const float* x       = (const float*)d_in[0];
    const float* temb    = (const float*)d_in[1];
    const float* rcos    = (const float*)d_in[2];
    const float* rsin    = (const float*)d_in[3];
    const float* w1      = (const float*)d_in[4];
    const float* wo_attn = (const float*)d_in[5];
    const float* wo_mlp  = (const float*)d_in[6];
    const float* nqw     = (const float*)d_in[7];
    const float* nkw     = (const float*)d_in[8];
    float* out = (float*)d_out;

    float *h, *P, *Qb, *Kb, *Vb, *cat;
    cudaGetSymbolAddress((void**)&h,   g_h);
    cudaGetSymbolAddress((void**)&P,   g_P);
    cudaGetSymbolAddress((void**)&Qb,  g_Qb);
    cudaGetSymbolAddress((void**)&Kb,  g_Kb);
    cudaGetSymbolAddress((void**)&Vb,  g_Vb);
    cudaGetSymbolAddress((void**)&cat, g_cat);

    // 1) LayerNorm + modulation
    k_lnmod<<<S_LEN, 256>>>(x, temb, h);

    cudaFuncSetAttribute(k_mm3<false>, cudaFuncAttributeMaxDynamicSharedMemorySize, MM_SMEM3);
    cudaFuncSetAttribute(k_mm3<true>,  cudaFuncAttributeMaxDynamicSharedMemorySize, MM_SMEM3);

    // 2) fused QKV+MLP projection: P = h @ w1   [4096 x 27648]
    {
        int tm = S_LEN / 128, tn = FOUT / 128;
        k_mm3<false><<<tm * tn, 256, MM_SMEM3>>>(
            h, w1, w1, P, S_LEN, FOUT, DIM, DIM, tm, tn, nullptr, nullptr);
    }

    // 3) QKV heads + RMSNorm + RoPE
    {
        dim3 g(S_LEN, HEADS);
        k_qkvprep<<<g, 128>>>(P, rcos, rsin, nqw, nkw, Qb, Kb, Vb);
    }

    // 4) attention -> cat[:, 0:3072]
    {
        cudaFuncSetAttribute(k_attn2, cudaFuncAttributeMaxDynamicSharedMemorySize, ATTN_SMEM);
        dim3 g(S_LEN / 128, HEADS);
        k_attn2<<<g, 256, ATTN_SMEM>>>(Qb, Kb, Vb, cat);
    }

    // 5) SwiGLU -> cat[:, 3072:12288]
    {
        dim3 g(MH / 256, S_LEN);
        k_swiglu<<<g, 256>>>(P, cat);
    }

    // 6) out = x + gate * (cat @ [wo_attn ; wo_mlp])   (K = 12288)
    {
        int tm = S_LEN / 128, tn = DIM / 128;
        k_mm3<true><<<tm * tn, 256, MM_SMEM3>>>(
            cat, wo_attn, wo_mlp, out, S_LEN, DIM, CATK, DIM, tm, tn, x, temb);
    }
}

// round 9
// speedup vs baseline: 6.1036x; 1.3545x over previous
#include <cuda_runtime.h>
#include <cuda_fp16.h>
#include <math.h>
#include <stdint.h>

#define S_LEN 4096
#define DIM   3072
#define HEADS 24
#define HD    128
#define MH    9216
#define FOUT  27648      // 3*DIM + 2*MH
#define QKV   9216       // 3*DIM
#define CATK  12288      // DIM + MH
#define EPS   1e-6f

// ---------------- scratch (device globals; no allocations allowed) ----------
__device__ __half g_h   [(size_t)S_LEN * DIM];
__device__ float  g_P   [(size_t)S_LEN * FOUT];
__device__ float  g_Qb  [(size_t)HEADS * S_LEN * HD];
__device__ float  g_Kb  [(size_t)HEADS * S_LEN * HD];
__device__ float  g_Vb  [(size_t)HEADS * S_LEN * HD];
__device__ __half g_cat [(size_t)S_LEN * CATK];     // [attn | swiglu] as half
__device__ __half g_w1h [(size_t)FOUT * DIM];       // w1^T   [FOUT][DIM]
__device__ __half g_woh [(size_t)DIM * CATK];       // [wo_attn;wo_mlp]^T [DIM][CATK]

__device__ __forceinline__ float tf32r(float x) {
    unsigned u;
    asm("cvt.rna.tf32.f32 %0, %1;" : "=r"(u) : "f"(x));
    return __uint_as_float(u);
}
__device__ __forceinline__ void cp16(uint32_t s, const void* g) {
    asm volatile("cp.async.cg.shared.global [%0], [%1], 16;\n" :: "r"(s), "l"(g));
}
__device__ __forceinline__ void mma_tf32(float c[4],
    uint32_t a0, uint32_t a1, uint32_t a2, uint32_t a3, uint32_t b0, uint32_t b1)
{
    asm volatile(
        "mma.sync.aligned.m16n8k8.row.col.f32.tf32.tf32.f32 "
        "{%0,%1,%2,%3},{%4,%5,%6,%7},{%8,%9},{%0,%1,%2,%3};"
        : "+f"(c[0]), "+f"(c[1]), "+f"(c[2]), "+f"(c[3])
        : "r"(a0), "r"(a1), "r"(a2), "r"(a3), "r"(b0), "r"(b1));
}
__device__ __forceinline__ void mma_f16(float c[4],
    uint32_t a0, uint32_t a1, uint32_t a2, uint32_t a3, uint32_t b0, uint32_t b1)
{
    asm volatile(
        "mma.sync.aligned.m16n8k16.row.col.f32.f16.f16.f32 "
        "{%0,%1,%2,%3},{%4,%5,%6,%7},{%8,%9},{%0,%1,%2,%3};"
        : "+f"(c[0]), "+f"(c[1]), "+f"(c[2]), "+f"(c[3])
        : "r"(a0), "r"(a1), "r"(a2), "r"(a3), "r"(b0), "r"(b1));
}

// ---------------- kernel 0: fp32 [K][N] -> half [N][outK] transpose ----------
__global__ __launch_bounds__(256) void k_cvtT(
    const float* __restrict__ in, __half* __restrict__ out,
    int K, int N, int outK, int kofs)
{
    __shared__ float t[32][33];
    int k0 = blockIdx.y * 32, n0 = blockIdx.x * 32;
    int tx = threadIdx.x & 31, ty = threadIdx.x >> 5;
    #pragma unroll
    for (int i = 0; i < 32; i += 8)
        t[ty + i][tx] = in[(size_t)(k0 + ty + i) * N + n0 + tx];
    __syncthreads();
    #pragma unroll
    for (int i = 0; i < 32; i += 8)
        out[(size_t)(n0 + ty + i) * outK + kofs + k0 + tx] = __float2half_rn(t[tx][ty + i]);
}

// ---------------- kernel 1: LayerNorm + modulation (-> half) -----------------
__global__ __launch_bounds__(256) void k_lnmod(
    const float* __restrict__ x, const float* __restrict__ temb,
    __half* __restrict__ h)
{
    int s = blockIdx.x;
    const float* xr = x + (size_t)s * DIM;
    float v[12];
    float lsum = 0.f, lsq = 0.f;
    #pragma unroll
    for (int i = 0; i < 12; i++) {
        float t = xr[threadIdx.x + i * 256];
        v[i] = t; lsum += t; lsq += t * t;
    }
    __shared__ float red[16];
    #pragma unroll
    for (int o = 16; o; o >>= 1) {
        lsum += __shfl_xor_sync(0xffffffffu, lsum, o);
        lsq  += __shfl_xor_sync(0xffffffffu, lsq,  o);
    }
    int w = threadIdx.x >> 5;
    if ((threadIdx.x & 31) == 0) { red[w] = lsum; red[8 + w] = lsq; }
    __syncthreads();
    float ssum = 0.f, ssq = 0.f;
    #pragma unroll
    for (int i = 0; i < 8; i++) { ssum += red[i]; ssq += red[8 + i]; }
    float mu  = ssum * (1.0f / DIM);
    float var = ssq * (1.0f / DIM) - mu * mu;
    float rs  = rsqrtf(var + EPS);
    __half* hr = h + (size_t)s * DIM;
    #pragma unroll
    for (int i = 0; i < 12; i++) {
        int d = threadIdx.x + i * 256;
        float sc = temb[DIM + d];
        float sh = temb[d];
        hr[d] = __float2half_rn((v[i] - mu) * rs * (1.f + sc) + sh);
    }
}

// ---------------- kernel 2: fp16 GEMM, 128x128 CTA, 2 CTAs/SM ---------------
// C[M,N] = A[M,K] * B^T  with A [M][K] half, B [N][K] half (both K-major).
// FINAL epilogue: out = x + gate * acc.
// smem: per stage A 128x20 words + B 128x20 words (stride 20 -> conflict-free)
#define MM4_STG 4
#define ST4W  5120                      // words per stage (A 2560 + B 2560)
#define ST4B  (ST4W * 4)
#define MM_SMEM4 (MM4_STG * ST4B)       // 81920 bytes

template <bool FINAL>
__global__ __launch_bounds__(256, 2) void k_mm4(
    const __half* __restrict__ A, const __half* __restrict__ B,
    float* __restrict__ C, int M, int N, int K, int tiles_m, int tiles_n,
    const float* __restrict__ xres, const float* __restrict__ temb)
{
    extern __shared__ float smf[];

    // block swizzle (GROUP_M = 16)
    int pid = blockIdx.x;
    const int GROUPM = 16;
    int npg     = GROUPM * tiles_n;
    int groupid = pid / npg;
    int firstm  = groupid * GROUPM;
    int gsz     = min(GROUPM, tiles_m - firstm);
    int pm      = firstm + (pid % npg) % gsz;
    int pn      = (pid % npg) / gsz;
    int bm = pm * 128, bn = pn * 128;

    int tid  = threadIdx.x;
    int warp = tid >> 5, lane = tid & 31;
    int wm = warp & 1, wn = warp >> 1;        // 2m x 4n warp grid
    int gid = lane >> 2, tid4 = lane & 3;

    float acc[4][4][4];
    #pragma unroll
    for (int i = 0; i < 4; i++)
        #pragma unroll
        for (int j = 0; j < 4; j++)
            #pragma unroll
            for (int q = 0; q < 4; q++) acc[i][j][q] = 0.f;

    uint32_t smb = (uint32_t)__cvta_generic_to_shared(smf);
    const __half* Ag = A + (size_t)bm * K;
    const __half* Bg = B + (size_t)bn * K;

    // loader: 2 x 16B chunks per thread for A and for B per stage
    // id = tid + i*256 -> r = id>>2 (0..127), c = id&3 (16B chunk = 8 halfs)
    #define MM4_LOAD(KB, SS)                                                    \
    {                                                                           \
        int kt_ = (KB) * 32;                                                    \
        uint32_t sa_ = smb + (uint32_t)((SS) * ST4B);                           \
        uint32_t sb_ = sa_ + 10240u;                                            \
        _Pragma("unroll")                                                       \
        for (int i_ = 0; i_ < 2; i_++) {                                        \
            int id_ = tid + i_ * 256;                                           \
            int r_ = id_ >> 2, c_ = id_ & 3;                                    \
            cp16(sa_ + (uint32_t)(r_ * 80 + c_ * 16),                           \
                 Ag + (size_t)r_ * K + kt_ + c_ * 8);                           \
            cp16(sb_ + (uint32_t)(r_ * 80 + c_ * 16),                           \
                 Bg + (size_t)r_ * K + kt_ + c_ * 8);                           \
        }                                                                       \
        asm volatile("cp.async.commit_group;\n");                               \
    }

    int ntiles = K >> 5;

    MM4_LOAD(0, 0)
    MM4_LOAD(1, 1)
    MM4_LOAD(2, 2)

    for (int t = 0; t < ntiles; t++) {
        if (t + 3 < ntiles) {
            MM4_LOAD(t + 3, (t + 3) & 3)
            asm volatile("cp.async.wait_group 3;\n");
        } else if (t + 2 < ntiles) {
            asm volatile("cp.async.wait_group 2;\n");
        } else if (t + 1 < ntiles) {
            asm volatile("cp.async.wait_group 1;\n");
        } else {
            asm volatile("cp.async.wait_group 0;\n");
        }
        __syncthreads();

        const uint32_t* Asp = (const uint32_t*)smf + (t & 3) * ST4W;
        const uint32_t* Bsp = Asp + 2560;

        #pragma unroll
        for (int k16 = 0; k16 < 2; k16++) {
            int kc = k16 * 8;
            uint32_t af[4][4], bf[4][2];
            #pragma unroll
            for (int mt = 0; mt < 4; mt++) {
                int r = wm * 64 + mt * 16 + gid;
                af[mt][0] = Asp[r * 20 + kc + tid4];
                af[mt][1] = Asp[(r + 8) * 20 + kc + tid4];
                af[mt][2] = Asp[r * 20 + kc + tid4 + 4];
                af[mt][3] = Asp[(r + 8) * 20 + kc + tid4 + 4];
            }
            #pragma unroll
            for (int nt = 0; nt < 4; nt++) {
                int cn = wn * 32 + nt * 8 + gid;
                bf[nt][0] = Bsp[cn * 20 + kc + tid4];
                bf[nt][1] = Bsp[cn * 20 + kc + tid4 + 4];
            }
            #pragma unroll
            for (int mt = 0; mt < 4; mt++)
                #pragma unroll
                for (int nt = 0; nt < 4; nt++)
                    mma_f16(acc[mt][nt], af[mt][0], af[mt][1], af[mt][2], af[mt][3],
                            bf[nt][0], bf[nt][1]);
        }
        __syncthreads();
    }

    // epilogue
    #pragma unroll
    for (int mt = 0; mt < 4; mt++) {
        int r0 = bm + wm * 64 + mt * 16 + gid;
        #pragma unroll
        for (int nt = 0; nt < 4; nt++) {
            int c0 = bn + wn * 32 + nt * 8 + tid4 * 2;
            float2 v0 = make_float2(acc[mt][nt][0], acc[mt][nt][1]);
            float2 v1 = make_float2(acc[mt][nt][2], acc[mt][nt][3]);
            float2* p0 = (float2*)(C + (size_t)r0 * N + c0);
            float2* p1 = (float2*)(C + (size_t)(r0 + 8) * N + c0);
            if (FINAL) {
                float gx = temb[2 * DIM + c0], gy = temb[2 * DIM + c0 + 1];
                float2 x0 = *(const float2*)(xres + (size_t)r0 * N + c0);
                float2 x1 = *(const float2*)(xres + (size_t)(r0 + 8) * N + c0);
                v0.x = x0.x + gx * v0.x; v0.y = x0.y + gy * v0.y;
                v1.x = x1.x + gx * v1.x; v1.y = x1.y + gy * v1.y;
            }
            *p0 = v0;
            *p1 = v1;
        }
    }
}

// ---------------- kernel 3: QKV extract + RMSNorm + RoPE ---------------------
__global__ __launch_bounds__(128) void k_qkvprep(
    const float* __restrict__ P, const float* __restrict__ cosb,
    const float* __restrict__ sinb, const float* __restrict__ nqw,
    const float* __restrict__ nkw,
    float* __restrict__ Qb, float* __restrict__ Kb, float* __restrict__ Vb)
{
    int s = blockIdx.x, h = blockIdx.y, d = threadIdx.x;
    const float* row = P + (size_t)s * FOUT + h * HD;
    float q = row[d];
    float k = row[DIM + d];
    float v = row[2 * DIM + d];

    __shared__ float sQ[HD], sK[HD], sred[8];
    float sq = q * q, sk = k * k;
    #pragma unroll
    for (int o = 16; o; o >>= 1) {
        sq += __shfl_xor_sync(0xffffffffu, sq, o);
        sk += __shfl_xor_sync(0xffffffffu, sk, o);
    }
    int w = d >> 5;
    if ((d & 31) == 0) { sred[w] = sq; sred[4 + w] = sk; }
    __syncthreads();
    float ssq = sred[0] + sred[1] + sred[2] + sred[3];
    float ssk = sred[4] + sred[5] + sred[6] + sred[7];
    float qn = q * rsqrtf(ssq * (1.0f / HD) + EPS) * nqw[d];
    float kn = k * rsqrtf(ssk * (1.0f / HD) + EPS) * nkw[d];
    sQ[d] = qn; sK[d] = kn;
    __syncthreads();
    float qrot = (d & 1) ? sQ[d - 1] : -sQ[d + 1];
    float krot = (d & 1) ? sK[d - 1] : -sK[d + 1];
    float c  = cosb[(size_t)s * HD + d];
    float sn = sinb[(size_t)s * HD + d];
    size_t o = ((size_t)h * S_LEN + s) * HD + d;
    Qb[o] = qn * c + qrot * sn;
    Kb[o] = kn * c + krot * sn;
    Vb[o] = v;
}

// ---------------- kernel 4: flash attention (tf32 mma.sync) ------------------
#define K_STR 132
#define V_STR 136
#define K_STAGE (64 * K_STR)
#define V_STAGE (64 * V_STR)
#define P_STR 68
#define PW_SZ (16 * P_STR)
#define ATTN_SMEM ((2 * K_STAGE + 2 * V_STAGE + 8 * PW_SZ) * 4)

__global__ __launch_bounds__(256, 1) void k_attn2(
    const float* __restrict__ Qb, const float* __restrict__ Kb,
    const float* __restrict__ Vb, __half* __restrict__ attnout)
{
    extern __shared__ float sm[];
    float* VsBase = sm + 2 * K_STAGE;
    float* Ps     = sm + 2 * K_STAGE + 2 * V_STAGE;

    int h  = blockIdx.y;
    int q0 = blockIdx.x * 128;
    int tid = threadIdx.x, warp = tid >> 5, lane = tid & 31;
    int gid = lane >> 2, tid4 = lane & 3;
    float* Pw = Ps + warp * PW_SZ;
    const float scale = 0.08838834764831843f;
    uint32_t smbase = (uint32_t)__cvta_generic_to_shared(sm);

    const float* Qg = Qb + ((size_t)h * S_LEN + q0) * HD;
    for (int i = tid; i < 128 * 32; i += 256) {
        int r = i >> 5, c4 = (i & 31) << 2;
        float4 v = *(const float4*)(Qg + (size_t)r * HD + c4);
        v.x *= scale; v.y *= scale; v.z *= scale; v.w *= scale;
        *(float4*)&sm[r * K_STR + c4] = v;
    }
    __syncthreads();
    uint32_t qf[16][4];
    {
        int r0 = warp * 16 + gid;
        #pragma unroll
        for (int kc = 0; kc < 16; kc++) {
            qf[kc][0] = __float_as_uint(sm[r0 * K_STR + kc * 8 + tid4]);
            qf[kc][1] = __float_as_uint(sm[(r0 + 8) * K_STR + kc * 8 + tid4]);
            qf[kc][2] = __float_as_uint(sm[r0 * K_STR + kc * 8 + tid4 + 4]);
            qf[kc][3] = __float_as_uint(sm[(r0 + 8) * K_STR + kc * 8 + tid4 + 4]);
        }
    }
    __syncthreads();

    float m0 = -1e30f, m1 = -1e30f, l0 = 0.f, l1 = 0.f;
    float o[16][4];
    #pragma unroll
    for (int dt = 0; dt < 16; dt++)
        #pragma unroll
        for (int j = 0; j < 4; j++) o[dt][j] = 0.f;

    #define LOAD_KV(T, SS)                                                       \
    {                                                                            \
        const float* Kg = Kb + ((size_t)h * S_LEN + (T) * 64) * HD;              \
        const float* Vg = Vb + ((size_t)h * S_LEN + (T) * 64) * HD;              \
        uint32_t ks = smbase + (uint32_t)((SS) * K_STAGE) * 4u;                  \
        uint32_t vs = smbase + (uint32_t)(2 * K_STAGE + (SS) * V_STAGE) * 4u;    \
        _Pragma("unroll")                                                        \
        for (int i = 0; i < 8; i++) {                                            \
            int idx = tid + i * 256;                                             \
            int r = idx >> 5, c4 = (idx & 31) << 2;                              \
            cp16(ks + (uint32_t)(r * K_STR + c4) * 4u, Kg + (size_t)r * HD + c4);\
            cp16(vs + (uint32_t)(r * V_STR + c4) * 4u, Vg + (size_t)r * HD + c4);\
        }                                                                        \
        asm volatile("cp.async.commit_group;\n");                                \
    }

    LOAD_KV(0, 0)

    for (int t = 0; t < 64; t++) {
        if (t + 1 < 64) {
            LOAD_KV(t + 1, (t + 1) & 1)
            asm volatile("cp.async.wait_group 1;\n");
        } else {
            asm volatile("cp.async.wait_group 0;\n");
        }
        __syncthreads();

        const float* Ks = sm + (t & 1) * K_STAGE;
        const float* Vs = VsBase + (t & 1) * V_STAGE;

        float sa[8][4];
        #pragma unroll
        for (int nt = 0; nt < 8; nt++)
            #pragma unroll
            for (int j = 0; j < 4; j++) sa[nt][j] = 0.f;
        #pragma unroll
        for (int nt = 0; nt < 8; nt++) {
            const float* Kr = Ks + (nt * 8 + gid) * K_STR;
            #pragma unroll
            for (int kc = 0; kc < 16; kc++) {
                uint32_t b0 = __float_as_uint(Kr[kc * 8 + tid4]);
                uint32_t b1 = __float_as_uint(Kr[kc * 8 + tid4 + 4]);
                mma_tf32(sa[nt], qf[kc][0], qf[kc][1], qf[kc][2], qf[kc][3], b0, b1);
            }
        }

        float mx0 = -1e30f, mx1 = -1e30f;
        #pragma unroll
        for (int nt = 0; nt < 8; nt++) {
            mx0 = fmaxf(mx0, fmaxf(sa[nt][0], sa[nt][1]));
            mx1 = fmaxf(mx1, fmaxf(sa[nt][2], sa[nt][3]));
        }
        mx0 = fmaxf(mx0, __shfl_xor_sync(0xffffffffu, mx0, 1));
        mx0 = fmaxf(mx0, __shfl_xor_sync(0xffffffffu, mx0, 2));
        mx1 = fmaxf(mx1, __shfl_xor_sync(0xffffffffu, mx1, 1));
        mx1 = fmaxf(mx1, __shfl_xor_sync(0xffffffffu, mx1, 2));
        float nm0 = fmaxf(m0, mx0), nm1 = fmaxf(m1, mx1);
        float corr0 = __expf(m0 - nm0), corr1 = __expf(m1 - nm1);
        float rs0 = 0.f, rs1 = 0.f;
        #pragma unroll
        for (int nt = 0; nt < 8; nt++) {
            float p0 = __expf(sa[nt][0] - nm0);
            float p1 = __expf(sa[nt][1] - nm0);
            float p2 = __expf(sa[nt][2] - nm1);
            float p3 = __expf(sa[nt][3] - nm1);
            rs0 += p0 + p1; rs1 += p2 + p3;
            *(float2*)&Pw[gid * P_STR + nt * 8 + 2 * tid4]       = make_float2(p0, p1);
            *(float2*)&Pw[(gid + 8) * P_STR + nt * 8 + 2 * tid4] = make_float2(p2, p3);
        }
        rs0 += __shfl_xor_sync(0xffffffffu, rs0, 1);
        rs0 += __shfl_xor_sync(0xffffffffu, rs0, 2);
        rs1 += __shfl_xor_sync(0xffffffffu, rs1, 1);
        rs1 += __shfl_xor_sync(0xffffffffu, rs1, 2);
        l0 = l0 * corr0 + rs0;
        l1 = l1 * corr1 + rs1;
        m0 = nm0; m1 = nm1;
        #pragma unroll
        for (int dt = 0; dt < 16; dt++) {
            o[dt][0] *= corr0; o[dt][1] *= corr0;
            o[dt][2] *= corr1; o[dt][3] *= corr1;
        }
        __syncwarp();

        #pragma unroll
        for (int kc = 0; kc < 8; kc++) {
            uint32_t a0 = __float_as_uint(Pw[gid * P_STR + kc * 8 + tid4]);
            uint32_t a1 = __float_as_uint(Pw[(gid + 8) * P_STR + kc * 8 + tid4]);
            uint32_t a2 = __float_as_uint(Pw[gid * P_STR + kc * 8 + tid4 + 4]);
            uint32_t a3 = __float_as_uint(Pw[(gid + 8) * P_STR + kc * 8 + tid4 + 4]);
            const float* Vr0 = Vs + (kc * 8 + tid4) * V_STR;
            const float* Vr1 = Vs + (kc * 8 + tid4 + 4) * V_STR;
            #pragma unroll
            for (int dt = 0; dt < 16; dt++) {
                uint32_t b0 = __float_as_uint(Vr0[dt * 8 + gid]);
                uint32_t b1 = __float_as_uint(Vr1[dt * 8 + gid]);
                mma_tf32(o[dt], a0, a1, a2, a3, b0, b1);
            }
        }
        __syncthreads();
    }

    // epilogue -> half cat columns [h*128, h*128+128)
    float inv0 = 1.0f / l0, inv1 = 1.0f / l1;
    int r0 = q0 + warp * 16 + gid;
    #pragma unroll
    for (int dt = 0; dt < 16; dt++) {
        int col = h * HD + dt * 8 + 2 * tid4;
        *(__half2*)&attnout[(size_t)r0 * CATK + col] =
            __floats2half2_rn(o[dt][0] * inv0, o[dt][1] * inv0);
        *(__half2*)&attnout[(size_t)(r0 + 8) * CATK + col] =
            __floats2half2_rn(o[dt][2] * inv1, o[dt][3] * inv1);
    }
}

// ---------------- kernel 5: SwiGLU -> half concat buffer ---------------------
__global__ __launch_bounds__(256) void k_swiglu(
    const float* __restrict__ P, __half* __restrict__ cat)
{
    int j = blockIdx.x * 256 + threadIdx.x;
    int s = blockIdx.y;
    float a = P[(size_t)s * FOUT + QKV + j];
    float b = P[(size_t)s * FOUT + QKV + MH + j];
    cat[(size_t)s * CATK + DIM + j] = __float2half_rn((a / (1.f + __expf(-a))) * b);
}

// ---------------- launch -----------------------------------------------------
extern "C" void kernel_launch(void* const* d_in, const int* in_sizes, int n_in,
                              void* d_out, int out_size)
{
    const float* x       = (const float*)d_in[0];
    const float* temb    = (const float*)d_in[1];
    const float* rcos    = (const float*)d_in[2];
    const float* rsin    = (const float*)d_in[3];
    const float* w1      = (const float*)d_in[4];
    const float* wo_attn = (const float*)d_in[5];
    const float* wo_mlp  = (const float*)d_in[6];
    const float* nqw     = (const float*)d_in[7];
    const float* nkw     = (const float*)d_in[8];
    float* out = (float*)d_out;

    __half *h, *cat, *w1h, *woh;
    float *P, *Qb, *Kb, *Vb;
    cudaGetSymbolAddress((void**)&h,   g_h);
    cudaGetSymbolAddress((void**)&P,   g_P);
    cudaGetSymbolAddress((void**)&Qb,  g_Qb);
    cudaGetSymbolAddress((void**)&Kb,  g_Kb);
    cudaGetSymbolAddress((void**)&Vb,  g_Vb);
    cudaGetSymbolAddress((void**)&cat, g_cat);
    cudaGetSymbolAddress((void**)&w1h, g_w1h);
    cudaGetSymbolAddress((void**)&woh, g_woh);

    // 0) weight convert + transpose to half [N][K]
    k_cvtT<<<dim3(FOUT / 32, DIM / 32), 256>>>(w1,      w1h, DIM, FOUT, DIM,  0);
    k_cvtT<<<dim3(DIM / 32,  DIM / 32), 256>>>(wo_attn, woh, DIM, DIM,  CATK, 0);
    k_cvtT<<<dim3(DIM / 32,  MH  / 32), 256>>>(wo_mlp,  woh, MH,  DIM,  CATK, DIM);

    // 1) LayerNorm + modulation -> half h
    k_lnmod<<<S_LEN, 256>>>(x, temb, h);

    cudaFuncSetAttribute(k_mm4<false>, cudaFuncAttributeMaxDynamicSharedMemorySize, MM_SMEM4);
    cudaFuncSetAttribute(k_mm4<true>,  cudaFuncAttributeMaxDynamicSharedMemorySize, MM_SMEM4);

    // 2) fused QKV+MLP projection: P = h @ w1   [4096 x 27648]
    {
        int tm = S_LEN / 128, tn = FOUT / 128;
        k_mm4<false><<<tm * tn, 256, MM_SMEM4>>>(
            h, w1h, P, S_LEN, FOUT, DIM, tm, tn, nullptr, nullptr);
    }

    // 3) QKV heads + RMSNorm + RoPE
    {
        dim3 g(S_LEN, HEADS);
        k_qkvprep<<<g, 128>>>(P, rcos, rsin, nqw, nkw, Qb, Kb, Vb);
    }

    // 4) attention -> cat[:, 0:3072]
    {
        cudaFuncSetAttribute(k_attn2, cudaFuncAttributeMaxDynamicSharedMemorySize, ATTN_SMEM);
        dim3 g(S_LEN / 128, HEADS);
        k_attn2<<<g, 256, ATTN_SMEM>>>(Qb, Kb, Vb, cat);
    }

    // 5) SwiGLU -> cat[:, 3072:12288]
    {
        dim3 g(MH / 256, S_LEN);
        k_swiglu<<<g, 256>>>(P, cat);
    }

    // 6) out = x + gate * (cat @ [wo_attn ; wo_mlp])   (K = 12288)
    {
        int tm = S_LEN / 128, tn = DIM / 128;
        k_mm4<true><<<tm * tn, 256, MM_SMEM4>>>(
            cat, woh, out, S_LEN, DIM, CATK, tm, tn, x, temb);
    }
}

// round 10
// speedup vs baseline: 6.8735x; 1.1261x over previous
#include <cuda_runtime.h>
#include <cuda_fp16.h>
#include <math.h>
#include <stdint.h>

#define S_LEN 4096
#define DIM   3072
#define HEADS 24
#define HD    128
#define MH    9216
#define FOUT  27648      // 3*DIM + 2*MH
#define QKV   9216       // 3*DIM
#define CATK  12288      // DIM + MH
#define EPS   1e-6f

// ---------------- scratch (device globals; no allocations allowed) ----------
__device__ __half g_h   [(size_t)S_LEN * DIM];
__device__ __half g_P   [(size_t)S_LEN * FOUT];
__device__ __half g_Qb  [(size_t)HEADS * S_LEN * HD];   // [h][s][d], pre-scaled
__device__ __half g_Kb  [(size_t)HEADS * S_LEN * HD];   // [h][s][d]
__device__ __half g_Vt  [(size_t)DIM * S_LEN];          // [h*HD+d][s]
__device__ __half g_cat [(size_t)S_LEN * CATK];         // [attn | swiglu]
__device__ __half g_w1h [(size_t)FOUT * DIM];           // w1^T [FOUT][DIM]
__device__ __half g_woh [(size_t)DIM * CATK];           // [wo_attn;wo_mlp]^T

__device__ __forceinline__ void cp16(uint32_t s, const void* g) {
    asm volatile("cp.async.cg.shared.global [%0], [%1], 16;\n" :: "r"(s), "l"(g));
}
__device__ __forceinline__ void mma_f16(float c[4],
    uint32_t a0, uint32_t a1, uint32_t a2, uint32_t a3, uint32_t b0, uint32_t b1)
{
    asm volatile(
        "mma.sync.aligned.m16n8k16.row.col.f32.f16.f16.f32 "
        "{%0,%1,%2,%3},{%4,%5,%6,%7},{%8,%9},{%0,%1,%2,%3};"
        : "+f"(c[0]), "+f"(c[1]), "+f"(c[2]), "+f"(c[3])
        : "r"(a0), "r"(a1), "r"(a2), "r"(a3), "r"(b0), "r"(b1));
}

// ---------------- kernel 0: fp32 [K][N] -> half [N][outK] transpose ----------
__global__ __launch_bounds__(256) void k_cvtT(
    const float* __restrict__ in, __half* __restrict__ out,
    int K, int N, int outK, int kofs)
{
    __shared__ float t[32][33];
    int k0 = blockIdx.y * 32, n0 = blockIdx.x * 32;
    int tx = threadIdx.x & 31, ty = threadIdx.x >> 5;
    #pragma unroll
    for (int i = 0; i < 32; i += 8)
        t[ty + i][tx] = in[(size_t)(k0 + ty + i) * N + n0 + tx];
    __syncthreads();
    #pragma unroll
    for (int i = 0; i < 32; i += 8)
        out[(size_t)(n0 + ty + i) * outK + kofs + k0 + tx] = __float2half_rn(t[tx][ty + i]);
}

// ---------------- kernel 1: LayerNorm + modulation (-> half) -----------------
__global__ __launch_bounds__(256) void k_lnmod(
    const float* __restrict__ x, const float* __restrict__ temb,
    __half* __restrict__ h)
{
    int s = blockIdx.x;
    const float* xr = x + (size_t)s * DIM;
    float v[12];
    float lsum = 0.f, lsq = 0.f;
    #pragma unroll
    for (int i = 0; i < 12; i++) {
        float t = xr[threadIdx.x + i * 256];
        v[i] = t; lsum += t; lsq += t * t;
    }
    __shared__ float red[16];
    #pragma unroll
    for (int o = 16; o; o >>= 1) {
        lsum += __shfl_xor_sync(0xffffffffu, lsum, o);
        lsq  += __shfl_xor_sync(0xffffffffu, lsq,  o);
    }
    int w = threadIdx.x >> 5;
    if ((threadIdx.x & 31) == 0) { red[w] = lsum; red[8 + w] = lsq; }
    __syncthreads();
    float ssum = 0.f, ssq = 0.f;
    #pragma unroll
    for (int i = 0; i < 8; i++) { ssum += red[i]; ssq += red[8 + i]; }
    float mu  = ssum * (1.0f / DIM);
    float var = ssq * (1.0f / DIM) - mu * mu;
    float rs  = rsqrtf(var + EPS);
    __half* hr = h + (size_t)s * DIM;
    #pragma unroll
    for (int i = 0; i < 12; i++) {
        int d = threadIdx.x + i * 256;
        float sc = temb[DIM + d];
        float sh = temb[d];
        hr[d] = __float2half_rn((v[i] - mu) * rs * (1.f + sc) + sh);
    }
}

// ---------------- kernel 2: fp16 GEMM, 128x128 CTA, 2 CTAs/SM ---------------
#define MM4_STG 4
#define ST4W  5120
#define ST4B  (ST4W * 4)
#define MM_SMEM4 (MM4_STG * ST4B)       // 81920 bytes

template <bool FINAL, typename OutT>
__global__ __launch_bounds__(256, 2) void k_mm4(
    const __half* __restrict__ A, const __half* __restrict__ B,
    OutT* __restrict__ C, int M, int N, int K, int tiles_m, int tiles_n,
    const float* __restrict__ xres, const float* __restrict__ temb)
{
    extern __shared__ float smf[];

    int pid = blockIdx.x;
    const int GROUPM = 16;
    int npg     = GROUPM * tiles_n;
    int groupid = pid / npg;
    int firstm  = groupid * GROUPM;
    int gsz     = min(GROUPM, tiles_m - firstm);
    int pm      = firstm + (pid % npg) % gsz;
    int pn      = (pid % npg) / gsz;
    int bm = pm * 128, bn = pn * 128;

    int tid  = threadIdx.x;
    int warp = tid >> 5, lane = tid & 31;
    int wm = warp & 1, wn = warp >> 1;
    int gid = lane >> 2, tid4 = lane & 3;

    float acc[4][4][4];
    #pragma unroll
    for (int i = 0; i < 4; i++)
        #pragma unroll
        for (int j = 0; j < 4; j++)
            #pragma unroll
            for (int q = 0; q < 4; q++) acc[i][j][q] = 0.f;

    uint32_t smb = (uint32_t)__cvta_generic_to_shared(smf);
    const __half* Ag = A + (size_t)bm * K;
    const __half* Bg = B + (size_t)bn * K;

    #define MM4_LOAD(KB, SS)                                                    \
    {                                                                           \
        int kt_ = (KB) * 32;                                                    \
        uint32_t sa_ = smb + (uint32_t)((SS) * ST4B);                           \
        uint32_t sb_ = sa_ + 10240u;                                            \
        _Pragma("unroll")                                                       \
        for (int i_ = 0; i_ < 2; i_++) {                                        \
            int id_ = tid + i_ * 256;                                           \
            int r_ = id_ >> 2, c_ = id_ & 3;                                    \
            cp16(sa_ + (uint32_t)(r_ * 80 + c_ * 16),                           \
                 Ag + (size_t)r_ * K + kt_ + c_ * 8);                           \
            cp16(sb_ + (uint32_t)(r_ * 80 + c_ * 16),                           \
                 Bg + (size_t)r_ * K + kt_ + c_ * 8);                           \
        }                                                                       \
        asm volatile("cp.async.commit_group;\n");                               \
    }

    int ntiles = K >> 5;

    MM4_LOAD(0, 0)
    MM4_LOAD(1, 1)
    MM4_LOAD(2, 2)

    for (int t = 0; t < ntiles; t++) {
        if (t + 3 < ntiles) {
            MM4_LOAD(t + 3, (t + 3) & 3)
            asm volatile("cp.async.wait_group 3;\n");
        } else if (t + 2 < ntiles) {
            asm volatile("cp.async.wait_group 2;\n");
        } else if (t + 1 < ntiles) {
            asm volatile("cp.async.wait_group 1;\n");
        } else {
            asm volatile("cp.async.wait_group 0;\n");
        }
        __syncthreads();

        const uint32_t* Asp = (const uint32_t*)smf + (t & 3) * ST4W;
        const uint32_t* Bsp = Asp + 2560;

        #pragma unroll
        for (int k16 = 0; k16 < 2; k16++) {
            int kc = k16 * 8;
            uint32_t af[4][4], bf[4][2];
            #pragma unroll
            for (int mt = 0; mt < 4; mt++) {
                int r = wm * 64 + mt * 16 + gid;
                af[mt][0] = Asp[r * 20 + kc + tid4];
                af[mt][1] = Asp[(r + 8) * 20 + kc + tid4];
                af[mt][2] = Asp[r * 20 + kc + tid4 + 4];
                af[mt][3] = Asp[(r + 8) * 20 + kc + tid4 + 4];
            }
            #pragma unroll
            for (int nt = 0; nt < 4; nt++) {
                int cn = wn * 32 + nt * 8 + gid;
                bf[nt][0] = Bsp[cn * 20 + kc + tid4];
                bf[nt][1] = Bsp[cn * 20 + kc + tid4 + 4];
            }
            #pragma unroll
            for (int mt = 0; mt < 4; mt++)
                #pragma unroll
                for (int nt = 0; nt < 4; nt++)
                    mma_f16(acc[mt][nt], af[mt][0], af[mt][1], af[mt][2], af[mt][3],
                            bf[nt][0], bf[nt][1]);
        }
        __syncthreads();
    }

    // epilogue
    #pragma unroll
    for (int mt = 0; mt < 4; mt++) {
        int r0 = bm + wm * 64 + mt * 16 + gid;
        #pragma unroll
        for (int nt = 0; nt < 4; nt++) {
            int c0 = bn + wn * 32 + nt * 8 + tid4 * 2;
            float2 v0 = make_float2(acc[mt][nt][0], acc[mt][nt][1]);
            float2 v1 = make_float2(acc[mt][nt][2], acc[mt][nt][3]);
            if (FINAL) {
                float gx = temb[2 * DIM + c0], gy = temb[2 * DIM + c0 + 1];
                float2 x0 = *(const float2*)(xres + (size_t)r0 * N + c0);
                float2 x1 = *(const float2*)(xres + (size_t)(r0 + 8) * N + c0);
                v0.x = x0.x + gx * v0.x; v0.y = x0.y + gy * v0.y;
                v1.x = x1.x + gx * v1.x; v1.y = x1.y + gy * v1.y;
            }
            if (sizeof(OutT) == 2) {
                *(__half2*)((__half*)C + (size_t)r0 * N + c0) =
                    __floats2half2_rn(v0.x, v0.y);
                *(__half2*)((__half*)C + (size_t)(r0 + 8) * N + c0) =
                    __floats2half2_rn(v1.x, v1.y);
            } else {
                *(float2*)((float*)C + (size_t)r0 * N + c0)       = v0;
                *(float2*)((float*)C + (size_t)(r0 + 8) * N + c0) = v1;
            }
        }
    }
}

// ---------------- kernel 3: QKV extract + RMSNorm + RoPE (-> half Q,K) ------
__global__ __launch_bounds__(128) void k_qkvprep(
    const __half* __restrict__ P, const float* __restrict__ cosb,
    const float* __restrict__ sinb, const float* __restrict__ nqw,
    const float* __restrict__ nkw,
    __half* __restrict__ Qb, __half* __restrict__ Kb)
{
    int s = blockIdx.x, h = blockIdx.y, d = threadIdx.x;
    const __half* row = P + (size_t)s * FOUT + h * HD;
    float q = __half2float(row[d]);
    float k = __half2float(row[DIM + d]);

    __shared__ float sQ[HD], sK[HD], sred[8];
    float sq = q * q, sk = k * k;
    #pragma unroll
    for (int o = 16; o; o >>= 1) {
        sq += __shfl_xor_sync(0xffffffffu, sq, o);
        sk += __shfl_xor_sync(0xffffffffu, sk, o);
    }
    int w = d >> 5;
    if ((d & 31) == 0) { sred[w] = sq; sred[4 + w] = sk; }
    __syncthreads();
    float ssq = sred[0] + sred[1] + sred[2] + sred[3];
    float ssk = sred[4] + sred[5] + sred[6] + sred[7];
    float qn = q * rsqrtf(ssq * (1.0f / HD) + EPS) * nqw[d];
    float kn = k * rsqrtf(ssk * (1.0f / HD) + EPS) * nkw[d];
    sQ[d] = qn; sK[d] = kn;
    __syncthreads();
    float qrot = (d & 1) ? sQ[d - 1] : -sQ[d + 1];
    float krot = (d & 1) ? sK[d - 1] : -sK[d + 1];
    float c  = cosb[(size_t)s * HD + d];
    float sn = sinb[(size_t)s * HD + d];
    const float scale = 0.08838834764831843f;   // 1/sqrt(128)
    size_t o = ((size_t)h * S_LEN + s) * HD + d;
    Qb[o] = __float2half_rn((qn * c + qrot * sn) * scale);
    Kb[o] = __float2half_rn(kn * c + krot * sn);
}

// ---------------- kernel 3b: V transpose (half [S][DIM] slice -> [DIM][S]) ---
__global__ __launch_bounds__(256) void k_vT(
    const __half* __restrict__ P, __half* __restrict__ Vt)
{
    __shared__ __half t[32][34];
    int c0 = blockIdx.x * 32, s0 = blockIdx.y * 32;
    int tx = threadIdx.x & 31, ty = threadIdx.x >> 5;
    #pragma unroll
    for (int i = 0; i < 32; i += 8)
        t[ty + i][tx] = P[(size_t)(s0 + ty + i) * FOUT + 2 * DIM + c0 + tx];
    __syncthreads();
    #pragma unroll
    for (int i = 0; i < 32; i += 8)
        Vt[(size_t)(c0 + ty + i) * S_LEN + s0 + tx] = t[tx][ty + i];
}

// ---------------- kernel 4: fp16 flash attention -----------------------------
// smem halfs: Ks 2x64x136 (Q tile 128x136 borrows both stages) | Vt 2x128x72 | P 8x16x72
#define K_STRH 136
#define V_STRH 72
#define P_STRH 72
#define K_STGH (64 * K_STRH)     // 8704 halfs
#define V_STGH (128 * V_STRH)    // 9216 halfs
#define PW_H   (16 * P_STRH)     // 1152 halfs
#define ATTN_SMEM ((2 * K_STGH + 2 * V_STGH + 8 * PW_H) * 2)   // 90112 B

__global__ __launch_bounds__(256, 1) void k_attn3(
    const __half* __restrict__ Qb, const __half* __restrict__ Kb,
    const __half* __restrict__ Vt, __half* __restrict__ attnout)
{
    extern __shared__ __half smh[];
    __half* VsBase = smh + 2 * K_STGH;
    __half* Ps     = smh + 2 * K_STGH + 2 * V_STGH;

    int h  = blockIdx.y;
    int q0 = blockIdx.x * 128;
    int tid = threadIdx.x, warp = tid >> 5, lane = tid & 31;
    int gid = lane >> 2, tid4 = lane & 3;
    __half* Pw = Ps + warp * PW_H;
    uint32_t smbase = (uint32_t)__cvta_generic_to_shared(smh);

    // ---- Q tile -> smem (borrows K stages), extract fp16 a-frags ----
    const __half* Qg = Qb + ((size_t)h * S_LEN + q0) * HD;
    #pragma unroll
    for (int i = 0; i < 8; i++) {
        int idx = tid + i * 256;
        int r = idx >> 4, c = idx & 15;
        cp16(smbase + (uint32_t)(r * K_STRH + c * 8) * 2u, Qg + (size_t)r * HD + c * 8);
    }
    asm volatile("cp.async.commit_group;\ncp.async.wait_group 0;\n");
    __syncthreads();
    uint32_t qf[8][4];
    {
        int r0 = warp * 16 + gid;
        #pragma unroll
        for (int k16 = 0; k16 < 8; k16++) {
            int k0 = k16 * 16;
            qf[k16][0] = *(const uint32_t*)&smh[r0 * K_STRH + k0 + 2 * tid4];
            qf[k16][1] = *(const uint32_t*)&smh[(r0 + 8) * K_STRH + k0 + 2 * tid4];
            qf[k16][2] = *(const uint32_t*)&smh[r0 * K_STRH + k0 + 8 + 2 * tid4];
            qf[k16][3] = *(const uint32_t*)&smh[(r0 + 8) * K_STRH + k0 + 8 + 2 * tid4];
        }
    }
    __syncthreads();

    float m0 = -1e30f, m1 = -1e30f, l0 = 0.f, l1 = 0.f;
    float o[16][4];
    #pragma unroll
    for (int dt = 0; dt < 16; dt++)
        #pragma unroll
        for (int j = 0; j < 4; j++) o[dt][j] = 0.f;

    #define LOAD_KV3(T, SS)                                                       \
    {                                                                             \
        const __half* Kg = Kb + ((size_t)h * S_LEN + (T) * 64) * HD;              \
        const __half* Vg = Vt + (size_t)h * HD * S_LEN + (T) * 64;                \
        uint32_t ks = smbase + (uint32_t)((SS) * K_STGH) * 2u;                    \
        uint32_t vs = smbase + (uint32_t)(2 * K_STGH + (SS) * V_STGH) * 2u;       \
        _Pragma("unroll")                                                         \
        for (int i = 0; i < 4; i++) {                                             \
            int idx = tid + i * 256;                                              \
            int kr = idx >> 4, kc = idx & 15;                                     \
            cp16(ks + (uint32_t)(kr * K_STRH + kc * 8) * 2u,                      \
                 Kg + (size_t)kr * HD + kc * 8);                                  \
            int vr = idx >> 3, vc = idx & 7;                                      \
            cp16(vs + (uint32_t)(vr * V_STRH + vc * 8) * 2u,                      \
                 Vg + (size_t)vr * S_LEN + vc * 8);                               \
        }                                                                         \
        asm volatile("cp.async.commit_group;\n");                                 \
    }

    LOAD_KV3(0, 0)

    for (int t = 0; t < 64; t++) {
        if (t + 1 < 64) {
            LOAD_KV3(t + 1, (t + 1) & 1)
            asm volatile("cp.async.wait_group 1;\n");
        } else {
            asm volatile("cp.async.wait_group 0;\n");
        }
        __syncthreads();

        const __half* Ks = smh + (t & 1) * K_STGH;
        const __half* Vs = VsBase + (t & 1) * V_STGH;

        // ---- S = Q K^T : 8 n-tiles x 8 k16 steps ----
        float sa[8][4];
        #pragma unroll
        for (int nt = 0; nt < 8; nt++)
            #pragma unroll
            for (int j = 0; j < 4; j++) sa[nt][j] = 0.f;
        #pragma unroll
        for (int nt = 0; nt < 8; nt++) {
            const __half* Kr = Ks + (nt * 8 + gid) * K_STRH;
            #pragma unroll
            for (int k16 = 0; k16 < 8; k16++) {
                int k0 = k16 * 16;
                uint32_t b0 = *(const uint32_t*)&Kr[k0 + 2 * tid4];
                uint32_t b1 = *(const uint32_t*)&Kr[k0 + 8 + 2 * tid4];
                mma_f16(sa[nt], qf[k16][0], qf[k16][1], qf[k16][2], qf[k16][3], b0, b1);
            }
        }

        // ---- online softmax ----
        float mx0 = -1e30f, mx1 = -1e30f;
        #pragma unroll
        for (int nt = 0; nt < 8; nt++) {
            mx0 = fmaxf(mx0, fmaxf(sa[nt][0], sa[nt][1]));
            mx1 = fmaxf(mx1, fmaxf(sa[nt][2], sa[nt][3]));
        }
        mx0 = fmaxf(mx0, __shfl_xor_sync(0xffffffffu, mx0, 1));
        mx0 = fmaxf(mx0, __shfl_xor_sync(0xffffffffu, mx0, 2));
        mx1 = fmaxf(mx1, __shfl_xor_sync(0xffffffffu, mx1, 1));
        mx1 = fmaxf(mx1, __shfl_xor_sync(0xffffffffu, mx1, 2));
        float nm0 = fmaxf(m0, mx0), nm1 = fmaxf(m1, mx1);
        float corr0 = __expf(m0 - nm0), corr1 = __expf(m1 - nm1);
        float rs0 = 0.f, rs1 = 0.f;
        #pragma unroll
        for (int nt = 0; nt < 8; nt++) {
            float p0 = __expf(sa[nt][0] - nm0);
            float p1 = __expf(sa[nt][1] - nm0);
            float p2 = __expf(sa[nt][2] - nm1);
            float p3 = __expf(sa[nt][3] - nm1);
            rs0 += p0 + p1; rs1 += p2 + p3;
            *(__half2*)&Pw[gid * P_STRH + nt * 8 + 2 * tid4]       = __floats2half2_rn(p0, p1);
            *(__half2*)&Pw[(gid + 8) * P_STRH + nt * 8 + 2 * tid4] = __floats2half2_rn(p2, p3);
        }
        rs0 += __shfl_xor_sync(0xffffffffu, rs0, 1);
        rs0 += __shfl_xor_sync(0xffffffffu, rs0, 2);
        rs1 += __shfl_xor_sync(0xffffffffu, rs1, 1);
        rs1 += __shfl_xor_sync(0xffffffffu, rs1, 2);
        l0 = l0 * corr0 + rs0;
        l1 = l1 * corr1 + rs1;
        m0 = nm0; m1 = nm1;
        #pragma unroll
        for (int dt = 0; dt < 16; dt++) {
            o[dt][0] *= corr0; o[dt][1] *= corr0;
            o[dt][2] *= corr1; o[dt][3] *= corr1;
        }
        __syncwarp();

        // ---- O += P V : 4 k16 steps x 16 d-tiles ----
        #pragma unroll
        for (int k16 = 0; k16 < 4; k16++) {
            int k0 = k16 * 16;
            uint32_t a0 = *(const uint32_t*)&Pw[gid * P_STRH + k0 + 2 * tid4];
            uint32_t a1 = *(const uint32_t*)&Pw[(gid + 8) * P_STRH + k0 + 2 * tid4];
            uint32_t a2 = *(const uint32_t*)&Pw[gid * P_STRH + k0 + 8 + 2 * tid4];
            uint32_t a3 = *(const uint32_t*)&Pw[(gid + 8) * P_STRH + k0 + 8 + 2 * tid4];
            #pragma unroll
            for (int dt = 0; dt < 16; dt++) {
                const __half* Vr = Vs + (dt * 8 + gid) * V_STRH;
                uint32_t b0 = *(const uint32_t*)&Vr[k0 + 2 * tid4];
                uint32_t b1 = *(const uint32_t*)&Vr[k0 + 8 + 2 * tid4];
                mma_f16(o[dt], a0, a1, a2, a3, b0, b1);
            }
        }
        __syncthreads();
    }

    // ---- epilogue -> half cat columns [h*128, h*128+128) ----
    float inv0 = 1.0f / l0, inv1 = 1.0f / l1;
    int r0 = q0 + warp * 16 + gid;
    #pragma unroll
    for (int dt = 0; dt < 16; dt++) {
        int col = h * HD + dt * 8 + 2 * tid4;
        *(__half2*)&attnout[(size_t)r0 * CATK + col] =
            __floats2half2_rn(o[dt][0] * inv0, o[dt][1] * inv0);
        *(__half2*)&attnout[(size_t)(r0 + 8) * CATK + col] =
            __floats2half2_rn(o[dt][2] * inv1, o[dt][3] * inv1);
    }
}

// ---------------- kernel 5: SwiGLU -> half concat buffer ---------------------
__global__ __launch_bounds__(256) void k_swiglu(
    const __half* __restrict__ P, __half* __restrict__ cat)
{
    int j = blockIdx.x * 256 + threadIdx.x;
    int s = blockIdx.y;
    float a = __half2float(P[(size_t)s * FOUT + QKV + j]);
    float b = __half2float(P[(size_t)s * FOUT + QKV + MH + j]);
    cat[(size_t)s * CATK + DIM + j] = __float2half_rn((a / (1.f + __expf(-a))) * b);
}

// ---------------- launch -----------------------------------------------------
extern "C" void kernel_launch(void* const* d_in, const int* in_sizes, int n_in,
                              void* d_out, int out_size)
{
    const float* x       = (const float*)d_in[0];
    const float* temb    = (const float*)d_in[1];
    const float* rcos    = (const float*)d_in[2];
    const float* rsin    = (const float*)d_in[3];
    const float* w1      = (const float*)d_in[4];
    const float* wo_attn = (const float*)d_in[5];
    const float* wo_mlp  = (const float*)d_in[6];
    const float* nqw     = (const float*)d_in[7];
    const float* nkw     = (const float*)d_in[8];
    float* out = (float*)d_out;

    __half *h, *P, *Qb, *Kb, *Vt, *cat, *w1h, *woh;
    cudaGetSymbolAddress((void**)&h,   g_h);
    cudaGetSymbolAddress((void**)&P,   g_P);
    cudaGetSymbolAddress((void**)&Qb,  g_Qb);
    cudaGetSymbolAddress((void**)&Kb,  g_Kb);
    cudaGetSymbolAddress((void**)&Vt,  g_Vt);
    cudaGetSymbolAddress((void**)&cat, g_cat);
    cudaGetSymbolAddress((void**)&w1h, g_w1h);
    cudaGetSymbolAddress((void**)&woh, g_woh);

    // 0) weight convert + transpose to half [N][K]
    k_cvtT<<<dim3(FOUT / 32, DIM / 32), 256>>>(w1,      w1h, DIM, FOUT, DIM,  0);
    k_cvtT<<<dim3(DIM / 32,  DIM / 32), 256>>>(wo_attn, woh, DIM, DIM,  CATK, 0);
    k_cvtT<<<dim3(DIM / 32,  MH  / 32), 256>>>(wo_mlp,  woh, MH,  DIM,  CATK, DIM);

    // 1) LayerNorm + modulation -> half h
    k_lnmod<<<S_LEN, 256>>>(x, temb, h);

    cudaFuncSetAttribute((const void*)k_mm4<false, __half>,
                         cudaFuncAttributeMaxDynamicSharedMemorySize, MM_SMEM4);
    cudaFuncSetAttribute((const void*)k_mm4<true, float>,
                         cudaFuncAttributeMaxDynamicSharedMemorySize, MM_SMEM4);

    // 2) fused QKV+MLP projection: P = h @ w1 (half output)
    {
        int tm = S_LEN / 128, tn = FOUT / 128;
        k_mm4<false, __half><<<tm * tn, 256, MM_SMEM4>>>(
            h, w1h, P, S_LEN, FOUT, DIM, tm, tn, nullptr, nullptr);
    }

    // 3) Q/K heads + RMSNorm + RoPE (half); 3b) V transpose
    {
        dim3 g(S_LEN, HEADS);
        k_qkvprep<<<g, 128>>>(P, rcos, rsin, nqw, nkw, Qb, Kb);
        k_vT<<<dim3(DIM / 32, S_LEN / 32), 256>>>(P, Vt);
    }

    // 4) fp16 attention -> cat[:, 0:3072]
    {
        cudaFuncSetAttribute(k_attn3, cudaFuncAttributeMaxDynamicSharedMemorySize, ATTN_SMEM);
        dim3 g(S_LEN / 128, HEADS);
        k_attn3<<<g, 256, ATTN_SMEM>>>(Qb, Kb, Vt, cat);
    }

    // 5) SwiGLU -> cat[:, 3072:12288]
    {
        dim3 g(MH / 256, S_LEN);
        k_swiglu<<<g, 256>>>(P, cat);
    }

    // 6) out = x + gate * (cat @ [wo_attn ; wo_mlp])   (K = 12288)
    {
        int tm = S_LEN / 128, tn = DIM / 128;
        k_mm4<true, float><<<tm * tn, 256, MM_SMEM4>>>(
            cat, woh, out, S_LEN, DIM, CATK, tm, tn, x, temb);
    }
}

// round 11
// speedup vs baseline: 7.2675x; 1.0573x over previous
#include <cuda_runtime.h>
#include <cuda_fp16.h>
#include <math.h>
#include <stdint.h>

#define S_LEN 4096
#define DIM   3072
#define HEADS 24
#define HD    128
#define MH    9216
#define FOUT  27648      // 3*DIM + 2*MH
#define QKV   9216       // 3*DIM
#define CATK  12288      // DIM + MH
#define EPS   1e-6f

// ---------------- scratch (device globals; no allocations allowed) ----------
__device__ __half g_h   [(size_t)S_LEN * DIM];
__device__ __half g_P   [(size_t)S_LEN * FOUT];
__device__ __half g_Qb  [(size_t)HEADS * S_LEN * HD];   // [h][s][d], pre-scaled
__device__ __half g_Kb  [(size_t)HEADS * S_LEN * HD];   // [h][s][d]
__device__ __half g_Vt  [(size_t)DIM * S_LEN];          // [h*HD+d][s]
__device__ __half g_cat [(size_t)S_LEN * CATK];         // [attn | swiglu]
__device__ __half g_w1h [(size_t)FOUT * DIM];           // w1^T [FOUT][DIM]
__device__ __half g_woh [(size_t)DIM * CATK];           // [wo_attn;wo_mlp]^T

__device__ __forceinline__ void cp16(uint32_t s, const void* g) {
    asm volatile("cp.async.cg.shared.global [%0], [%1], 16;\n" :: "r"(s), "l"(g));
}
__device__ __forceinline__ void mma_f16(float c[4],
    uint32_t a0, uint32_t a1, uint32_t a2, uint32_t a3, uint32_t b0, uint32_t b1)
{
    asm volatile(
        "mma.sync.aligned.m16n8k16.row.col.f32.f16.f16.f32 "
        "{%0,%1,%2,%3},{%4,%5,%6,%7},{%8,%9},{%0,%1,%2,%3};"
        : "+f"(c[0]), "+f"(c[1]), "+f"(c[2]), "+f"(c[3])
        : "r"(a0), "r"(a1), "r"(a2), "r"(a3), "r"(b0), "r"(b1));
}
__device__ __forceinline__ void ldsm4(uint32_t r[4], uint32_t addr) {
    asm volatile("ldmatrix.sync.aligned.m8n8.x4.shared.b16 {%0,%1,%2,%3}, [%4];"
                 : "=r"(r[0]), "=r"(r[1]), "=r"(r[2]), "=r"(r[3]) : "r"(addr));
}

// ---------------- kernel 0: fp32 [K][N] -> half [N][outK] transpose ----------
__global__ __launch_bounds__(256) void k_cvtT(
    const float* __restrict__ in, __half* __restrict__ out,
    int K, int N, int outK, int kofs)
{
    __shared__ float t[32][33];
    int k0 = blockIdx.y * 32, n0 = blockIdx.x * 32;
    int tx = threadIdx.x & 31, ty = threadIdx.x >> 5;
    #pragma unroll
    for (int i = 0; i < 32; i += 8)
        t[ty + i][tx] = in[(size_t)(k0 + ty + i) * N + n0 + tx];
    __syncthreads();
    #pragma unroll
    for (int i = 0; i < 32; i += 8)
        out[(size_t)(n0 + ty + i) * outK + kofs + k0 + tx] = __float2half_rn(t[tx][ty + i]);
}

// ---------------- kernel 1: LayerNorm + modulation (-> half) -----------------
__global__ __launch_bounds__(256) void k_lnmod(
    const float* __restrict__ x, const float* __restrict__ temb,
    __half* __restrict__ h)
{
    int s = blockIdx.x;
    const float* xr = x + (size_t)s * DIM;
    float v[12];
    float lsum = 0.f, lsq = 0.f;
    #pragma unroll
    for (int i = 0; i < 12; i++) {
        float t = xr[threadIdx.x + i * 256];
        v[i] = t; lsum += t; lsq += t * t;
    }
    __shared__ float red[16];
    #pragma unroll
    for (int o = 16; o; o >>= 1) {
        lsum += __shfl_xor_sync(0xffffffffu, lsum, o);
        lsq  += __shfl_xor_sync(0xffffffffu, lsq,  o);
    }
    int w = threadIdx.x >> 5;
    if ((threadIdx.x & 31) == 0) { red[w] = lsum; red[8 + w] = lsq; }
    __syncthreads();
    float ssum = 0.f, ssq = 0.f;
    #pragma unroll
    for (int i = 0; i < 8; i++) { ssum += red[i]; ssq += red[8 + i]; }
    float mu  = ssum * (1.0f / DIM);
    float var = ssq * (1.0f / DIM) - mu * mu;
    float rs  = rsqrtf(var + EPS);
    __half* hr = h + (size_t)s * DIM;
    #pragma unroll
    for (int i = 0; i < 12; i++) {
        int d = threadIdx.x + i * 256;
        float sc = temb[DIM + d];
        float sh = temb[d];
        hr[d] = __float2half_rn((v[i] - mu) * rs * (1.f + sc) + sh);
    }
}

// ---------------- kernel 2: fp16 GEMM (ldmatrix), 128x128 CTA, 2 CTAs/SM ----
#define MM4_STG 4
#define ST4W  5120
#define ST4B  (ST4W * 4)
#define MM_SMEM4 (MM4_STG * ST4B)       // 81920 bytes

template <bool FINAL, typename OutT>
__global__ __launch_bounds__(256, 2) void k_mm4(
    const __half* __restrict__ A, const __half* __restrict__ B,
    OutT* __restrict__ C, int M, int N, int K, int tiles_m, int tiles_n,
    const float* __restrict__ xres, const float* __restrict__ temb)
{
    extern __shared__ float smf[];

    int pid = blockIdx.x;
    const int GROUPM = 16;
    int npg     = GROUPM * tiles_n;
    int groupid = pid / npg;
    int firstm  = groupid * GROUPM;
    int gsz     = min(GROUPM, tiles_m - firstm);
    int pm      = firstm + (pid % npg) % gsz;
    int pn      = (pid % npg) / gsz;
    int bm = pm * 128, bn = pn * 128;

    int tid  = threadIdx.x;
    int warp = tid >> 5, lane = tid & 31;
    int wm = warp & 1, wn = warp >> 1;
    int gid = lane >> 2, tid4 = lane & 3;

    float acc[4][4][4];
    #pragma unroll
    for (int i = 0; i < 4; i++)
        #pragma unroll
        for (int j = 0; j < 4; j++)
            #pragma unroll
            for (int q = 0; q < 4; q++) acc[i][j][q] = 0.f;

    uint32_t smb = (uint32_t)__cvta_generic_to_shared(smf);
    const __half* Ag = A + (size_t)bm * K;
    const __half* Bg = B + (size_t)bn * K;

    // ldmatrix per-lane byte offsets within a stage
    uint32_t aoff[4], boff[2];
    #pragma unroll
    for (int mt = 0; mt < 4; mt++)
        aoff[mt] = (uint32_t)((wm * 64 + mt * 16 + (lane & 15)) * 80 + (lane >> 4) * 16);
    #pragma unroll
    for (int p = 0; p < 2; p++)
        boff[p] = 10240u + (uint32_t)((wn * 32 + p * 16 + ((lane >> 4) * 8) + (lane & 7)) * 80
                                      + (((lane >> 3) & 1) * 16));

    #define MM4_LOAD(KB, SS)                                                    \
    {                                                                           \
        int kt_ = (KB) * 32;                                                    \
        uint32_t sa_ = smb + (uint32_t)((SS) * ST4B);                           \
        uint32_t sb_ = sa_ + 10240u;                                            \
        _Pragma("unroll")                                                       \
        for (int i_ = 0; i_ < 2; i_++) {                                        \
            int id_ = tid + i_ * 256;                                           \
            int r_ = id_ >> 2, c_ = id_ & 3;                                    \
            cp16(sa_ + (uint32_t)(r_ * 80 + c_ * 16),                           \
                 Ag + (size_t)r_ * K + kt_ + c_ * 8);                           \
            cp16(sb_ + (uint32_t)(r_ * 80 + c_ * 16),                           \
                 Bg + (size_t)r_ * K + kt_ + c_ * 8);                           \
        }                                                                       \
        asm volatile("cp.async.commit_group;\n");                               \
    }

    int ntiles = K >> 5;

    MM4_LOAD(0, 0)
    MM4_LOAD(1, 1)
    MM4_LOAD(2, 2)

    for (int t = 0; t < ntiles; t++) {
        if (t + 3 < ntiles) {
            MM4_LOAD(t + 3, (t + 3) & 3)
            asm volatile("cp.async.wait_group 3;\n");
        } else if (t + 2 < ntiles) {
            asm volatile("cp.async.wait_group 2;\n");
        } else if (t + 1 < ntiles) {
            asm volatile("cp.async.wait_group 1;\n");
        } else {
            asm volatile("cp.async.wait_group 0;\n");
        }
        __syncthreads();

        uint32_t sbase = smb + (uint32_t)((t & 3) * ST4B);

        #pragma unroll
        for (int k16 = 0; k16 < 2; k16++) {
            uint32_t kb = (uint32_t)(k16 * 32);   // 16 halfs = 32 bytes
            uint32_t af[4][4], bq0[4], bq1[4];
            #pragma unroll
            for (int mt = 0; mt < 4; mt++)
                ldsm4(af[mt], sbase + aoff[mt] + kb);
            ldsm4(bq0, sbase + boff[0] + kb);   // bf[0][0],bf[0][1],bf[1][0],bf[1][1]
            ldsm4(bq1, sbase + boff[1] + kb);   // bf[2][0],bf[2][1],bf[3][0],bf[3][1]

            #pragma unroll
            for (int mt = 0; mt < 4; mt++) {
                mma_f16(acc[mt][0], af[mt][0], af[mt][1], af[mt][2], af[mt][3], bq0[0], bq0[1]);
                mma_f16(acc[mt][1], af[mt][0], af[mt][1], af[mt][2], af[mt][3], bq0[2], bq0[3]);
                mma_f16(acc[mt][2], af[mt][0], af[mt][1], af[mt][2], af[mt][3], bq1[0], bq1[1]);
                mma_f16(acc[mt][3], af[mt][0], af[mt][1], af[mt][2], af[mt][3], bq1[2], bq1[3]);
            }
        }
        __syncthreads();
    }

    // epilogue
    #pragma unroll
    for (int mt = 0; mt < 4; mt++) {
        int r0 = bm + wm * 64 + mt * 16 + gid;
        #pragma unroll
        for (int nt = 0; nt < 4; nt++) {
            int c0 = bn + wn * 32 + nt * 8 + tid4 * 2;
            float2 v0 = make_float2(acc[mt][nt][0], acc[mt][nt][1]);
            float2 v1 = make_float2(acc[mt][nt][2], acc[mt][nt][3]);
            if (FINAL) {
                float gx = temb[2 * DIM + c0], gy = temb[2 * DIM + c0 + 1];
                float2 x0 = *(const float2*)(xres + (size_t)r0 * N + c0);
                float2 x1 = *(const float2*)(xres + (size_t)(r0 + 8) * N + c0);
                v0.x = x0.x + gx * v0.x; v0.y = x0.y + gy * v0.y;
                v1.x = x1.x + gx * v1.x; v1.y = x1.y + gy * v1.y;
            }
            if (sizeof(OutT) == 2) {
                *(__half2*)((__half*)C + (size_t)r0 * N + c0) =
                    __floats2half2_rn(v0.x, v0.y);
                *(__half2*)((__half*)C + (size_t)(r0 + 8) * N + c0) =
                    __floats2half2_rn(v1.x, v1.y);
            } else {
                *(float2*)((float*)C + (size_t)r0 * N + c0)       = v0;
                *(float2*)((float*)C + (size_t)(r0 + 8) * N + c0) = v1;
            }
        }
    }
}

// ---------------- kernel 3: QKV extract + RMSNorm + RoPE (-> half Q,K) ------
__global__ __launch_bounds__(128) void k_qkvprep(
    const __half* __restrict__ P, const float* __restrict__ cosb,
    const float* __restrict__ sinb, const float* __restrict__ nqw,
    const float* __restrict__ nkw,
    __half* __restrict__ Qb, __half* __restrict__ Kb)
{
    int s = blockIdx.x, h = blockIdx.y, d = threadIdx.x;
    const __half* row = P + (size_t)s * FOUT + h * HD;
    float q = __half2float(row[d]);
    float k = __half2float(row[DIM + d]);

    __shared__ float sQ[HD], sK[HD], sred[8];
    float sq = q * q, sk = k * k;
    #pragma unroll
    for (int o = 16; o; o >>= 1) {
        sq += __shfl_xor_sync(0xffffffffu, sq, o);
        sk += __shfl_xor_sync(0xffffffffu, sk, o);
    }
    int w = d >> 5;
    if ((d & 31) == 0) { sred[w] = sq; sred[4 + w] = sk; }
    __syncthreads();
    float ssq = sred[0] + sred[1] + sred[2] + sred[3];
    float ssk = sred[4] + sred[5] + sred[6] + sred[7];
    float qn = q * rsqrtf(ssq * (1.0f / HD) + EPS) * nqw[d];
    float kn = k * rsqrtf(ssk * (1.0f / HD) + EPS) * nkw[d];
    sQ[d] = qn; sK[d] = kn;
    __syncthreads();
    float qrot = (d & 1) ? sQ[d - 1] : -sQ[d + 1];
    float krot = (d & 1) ? sK[d - 1] : -sK[d + 1];
    float c  = cosb[(size_t)s * HD + d];
    float sn = sinb[(size_t)s * HD + d];
    const float scale = 0.08838834764831843f;   // 1/sqrt(128)
    size_t o = ((size_t)h * S_LEN + s) * HD + d;
    Qb[o] = __float2half_rn((qn * c + qrot * sn) * scale);
    Kb[o] = __float2half_rn(kn * c + krot * sn);
}

// ---------------- kernel 3b: V transpose (half [S][DIM] slice -> [DIM][S]) ---
__global__ __launch_bounds__(256) void k_vT(
    const __half* __restrict__ P, __half* __restrict__ Vt)
{
    __shared__ __half t[32][34];
    int c0 = blockIdx.x * 32, s0 = blockIdx.y * 32;
    int tx = threadIdx.x & 31, ty = threadIdx.x >> 5;
    #pragma unroll
    for (int i = 0; i < 32; i += 8)
        t[ty + i][tx] = P[(size_t)(s0 + ty + i) * FOUT + 2 * DIM + c0 + tx];
    __syncthreads();
    #pragma unroll
    for (int i = 0; i < 32; i += 8)
        Vt[(size_t)(c0 + ty + i) * S_LEN + s0 + tx] = t[tx][ty + i];
}

// ---------------- kernel 4: fp16 flash attention -----------------------------
#define K_STRH 136
#define V_STRH 72
#define P_STRH 72
#define K_STGH (64 * K_STRH)
#define V_STGH (128 * V_STRH)
#define PW_H   (16 * P_STRH)
#define ATTN_SMEM ((2 * K_STGH + 2 * V_STGH + 8 * PW_H) * 2)   // 90112 B

__global__ __launch_bounds__(256, 1) void k_attn3(
    const __half* __restrict__ Qb, const __half* __restrict__ Kb,
    const __half* __restrict__ Vt, __half* __restrict__ attnout)
{
    extern __shared__ __half smh[];
    __half* VsBase = smh + 2 * K_STGH;
    __half* Ps     = smh + 2 * K_STGH + 2 * V_STGH;

    int h  = blockIdx.y;
    int q0 = blockIdx.x * 128;
    int tid = threadIdx.x, warp = tid >> 5, lane = tid & 31;
    int gid = lane >> 2, tid4 = lane & 3;
    __half* Pw = Ps + warp * PW_H;
    uint32_t smbase = (uint32_t)__cvta_generic_to_shared(smh);

    const __half* Qg = Qb + ((size_t)h * S_LEN + q0) * HD;
    #pragma unroll
    for (int i = 0; i < 8; i++) {
        int idx = tid + i * 256;
        int r = idx >> 4, c = idx & 15;
        cp16(smbase + (uint32_t)(r * K_STRH + c * 8) * 2u, Qg + (size_t)r * HD + c * 8);
    }
    asm volatile("cp.async.commit_group;\ncp.async.wait_group 0;\n");
    __syncthreads();
    uint32_t qf[8][4];
    {
        int r0 = warp * 16 + gid;
        #pragma unroll
        for (int k16 = 0; k16 < 8; k16++) {
            int k0 = k16 * 16;
            qf[k16][0] = *(const uint32_t*)&smh[r0 * K_STRH + k0 + 2 * tid4];
            qf[k16][1] = *(const uint32_t*)&smh[(r0 + 8) * K_STRH + k0 + 2 * tid4];
            qf[k16][2] = *(const uint32_t*)&smh[r0 * K_STRH + k0 + 8 + 2 * tid4];
            qf[k16][3] = *(const uint32_t*)&smh[(r0 + 8) * K_STRH + k0 + 8 + 2 * tid4];
        }
    }
    __syncthreads();

    float m0 = -1e30f, m1 = -1e30f, l0 = 0.f, l1 = 0.f;
    float o[16][4];
    #pragma unroll
    for (int dt = 0; dt < 16; dt++)
        #pragma unroll
        for (int j = 0; j < 4; j++) o[dt][j] = 0.f;

    #define LOAD_KV3(T, SS)                                                       \
    {                                                                             \
        const __half* Kg = Kb + ((size_t)h * S_LEN + (T) * 64) * HD;              \
        const __half* Vg = Vt + (size_t)h * HD * S_LEN + (T) * 64;                \
        uint32_t ks = smbase + (uint32_t)((SS) * K_STGH) * 2u;                    \
        uint32_t vs = smbase + (uint32_t)(2 * K_STGH + (SS) * V_STGH) * 2u;       \
        _Pragma("unroll")                                                         \
        for (int i = 0; i < 4; i++) {                                             \
            int idx = tid + i * 256;                                              \
            int kr = idx >> 4, kc = idx & 15;                                     \
            cp16(ks + (uint32_t)(kr * K_STRH + kc * 8) * 2u,                      \
                 Kg + (size_t)kr * HD + kc * 8);                                  \
            int vr = idx >> 3, vc = idx & 7;                                      \
            cp16(vs + (uint32_t)(vr * V_STRH + vc * 8) * 2u,                      \
                 Vg + (size_t)vr * S_LEN + vc * 8);                               \
        }                                                                         \
        asm volatile("cp.async.commit_group;\n");                                 \
    }

    LOAD_KV3(0, 0)

    for (int t = 0; t < 64; t++) {
        if (t + 1 < 64) {
            LOAD_KV3(t + 1, (t + 1) & 1)
            asm volatile("cp.async.wait_group 1;\n");
        } else {
            asm volatile("cp.async.wait_group 0;\n");
        }
        __syncthreads();

        const __half* Ks = smh + (t & 1) * K_STGH;
        const __half* Vs = VsBase + (t & 1) * V_STGH;

        float sa[8][4];
        #pragma unroll
        for (int nt = 0; nt < 8; nt++)
            #pragma unroll
            for (int j = 0; j < 4; j++) sa[nt][j] = 0.f;
        #pragma unroll
        for (int nt = 0; nt < 8; nt++) {
            const __half* Kr = Ks + (nt * 8 + gid) * K_STRH;
            #pragma unroll
            for (int k16 = 0; k16 < 8; k16++) {
                int k0 = k16 * 16;
                uint32_t b0 = *(const uint32_t*)&Kr[k0 + 2 * tid4];
                uint32_t b1 = *(const uint32_t*)&Kr[k0 + 8 + 2 * tid4];
                mma_f16(sa[nt], qf[k16][0], qf[k16][1], qf[k16][2], qf[k16][3], b0, b1);
            }
        }

        float mx0 = -1e30f, mx1 = -1e30f;
        #pragma unroll
        for (int nt = 0; nt < 8; nt++) {
            mx0 = fmaxf(mx0, fmaxf(sa[nt][0], sa[nt][1]));
            mx1 = fmaxf(mx1, fmaxf(sa[nt][2], sa[nt][3]));
        }
        mx0 = fmaxf(mx0, __shfl_xor_sync(0xffffffffu, mx0, 1));
        mx0 = fmaxf(mx0, __shfl_xor_sync(0xffffffffu, mx0, 2));
        mx1 = fmaxf(mx1, __shfl_xor_sync(0xffffffffu, mx1, 1));
        mx1 = fmaxf(mx1, __shfl_xor_sync(0xffffffffu, mx1, 2));
        float nm0 = fmaxf(m0, mx0), nm1 = fmaxf(m1, mx1);
        float corr0 = __expf(m0 - nm0), corr1 = __expf(m1 - nm1);
        float rs0 = 0.f, rs1 = 0.f;
        #pragma unroll
        for (int nt = 0; nt < 8; nt++) {
            float p0 = __expf(sa[nt][0] - nm0);
            float p1 = __expf(sa[nt][1] - nm0);
            float p2 = __expf(sa[nt][2] - nm1);
            float p3 = __expf(sa[nt][3] - nm1);
            rs0 += p0 + p1; rs1 += p2 + p3;
            *(__half2*)&Pw[gid * P_STRH + nt * 8 + 2 * tid4]       = __floats2half2_rn(p0, p1);
            *(__half2*)&Pw[(gid + 8) * P_STRH + nt * 8 + 2 * tid4] = __floats2half2_rn(p2, p3);
        }
        rs0 += __shfl_xor_sync(0xffffffffu, rs0, 1);
        rs0 += __shfl_xor_sync(0xffffffffu, rs0, 2);
        rs1 += __shfl_xor_sync(0xffffffffu, rs1, 1);
        rs1 += __shfl_xor_sync(0xffffffffu, rs1, 2);
        l0 = l0 * corr0 + rs0;
        l1 = l1 * corr1 + rs1;
        m0 = nm0; m1 = nm1;
        #pragma unroll
        for (int dt = 0; dt < 16; dt++) {
            o[dt][0] *= corr0; o[dt][1] *= corr0;
            o[dt][2] *= corr1; o[dt][3] *= corr1;
        }
        __syncwarp();

        #pragma unroll
        for (int k16 = 0; k16 < 4; k16++) {
            int k0 = k16 * 16;
            uint32_t a0 = *(const uint32_t*)&Pw[gid * P_STRH + k0 + 2 * tid4];
            uint32_t a1 = *(const uint32_t*)&Pw[(gid + 8) * P_STRH + k0 + 2 * tid4];
            uint32_t a2 = *(const uint32_t*)&Pw[gid * P_STRH + k0 + 8 + 2 * tid4];
            uint32_t a3 = *(const uint32_t*)&Pw[(gid + 8) * P_STRH + k0 + 8 + 2 * tid4];
            #pragma unroll
            for (int dt = 0; dt < 16; dt++) {
                const __half* Vr = Vs + (dt * 8 + gid) * V_STRH;
                uint32_t b0 = *(const uint32_t*)&Vr[k0 + 2 * tid4];
                uint32_t b1 = *(const uint32_t*)&Vr[k0 + 8 + 2 * tid4];
                mma_f16(o[dt], a0, a1, a2, a3, b0, b1);
            }
        }
        __syncthreads();
    }

    float inv0 = 1.0f / l0, inv1 = 1.0f / l1;
    int r0 = q0 + warp * 16 + gid;
    #pragma unroll
    for (int dt = 0; dt < 16; dt++) {
        int col = h * HD + dt * 8 + 2 * tid4;
        *(__half2*)&attnout[(size_t)r0 * CATK + col] =
            __floats2half2_rn(o[dt][0] * inv0, o[dt][1] * inv0);
        *(__half2*)&attnout[(size_t)(r0 + 8) * CATK + col] =
            __floats2half2_rn(o[dt][2] * inv1, o[dt][3] * inv1);
    }
}

// ---------------- kernel 5: SwiGLU -> half concat buffer ---------------------
__global__ __launch_bounds__(256) void k_swiglu(
    const __half* __restrict__ P, __half* __restrict__ cat)
{
    int j = blockIdx.x * 256 + threadIdx.x;
    int s = blockIdx.y;
    float a = __half2float(P[(size_t)s * FOUT + QKV + j]);
    float b = __half2float(P[(size_t)s * FOUT + QKV + MH + j]);
    cat[(size_t)s * CATK + DIM + j] = __float2half_rn((a / (1.f + __expf(-a))) * b);
}

// ---------------- launch -----------------------------------------------------
extern "C" void kernel_launch(void* const* d_in, const int* in_sizes, int n_in,
                              void* d_out, int out_size)
{
    const float* x       = (const float*)d_in[0];
    const float* temb    = (const float*)d_in[1];
    const float* rcos    = (const float*)d_in[2];
    const float* rsin    = (const float*)d_in[3];
    const float* w1      = (const float*)d_in[4];
    const float* wo_attn = (const float*)d_in[5];
    const float* wo_mlp  = (const float*)d_in[6];
    const float* nqw     = (const float*)d_in[7];
    const float* nkw     = (const float*)d_in[8];
    float* out = (float*)d_out;

    __half *h, *P, *Qb, *Kb, *Vt, *cat, *w1h, *woh;
    cudaGetSymbolAddress((void**)&h,   g_h);
    cudaGetSymbolAddress((void**)&P,   g_P);
    cudaGetSymbolAddress((void**)&Qb,  g_Qb);
    cudaGetSymbolAddress((void**)&Kb,  g_Kb);
    cudaGetSymbolAddress((void**)&Vt,  g_Vt);
    cudaGetSymbolAddress((void**)&cat, g_cat);
    cudaGetSymbolAddress((void**)&w1h, g_w1h);
    cudaGetSymbolAddress((void**)&woh, g_woh);

    // 0) weight convert + transpose to half [N][K]
    k_cvtT<<<dim3(FOUT / 32, DIM / 32), 256>>>(w1,      w1h, DIM, FOUT, DIM,  0);
    k_cvtT<<<dim3(DIM / 32,  DIM / 32), 256>>>(wo_attn, woh, DIM, DIM,  CATK, 0);
    k_cvtT<<<dim3(DIM / 32,  MH  / 32), 256>>>(wo_mlp,  woh, MH,  DIM,  CATK, DIM);

    // 1) LayerNorm + modulation -> half h
    k_lnmod<<<S_LEN, 256>>>(x, temb, h);

    cudaFuncSetAttribute((const void*)k_mm4<false, __half>,
                         cudaFuncAttributeMaxDynamicSharedMemorySize, MM_SMEM4);
    cudaFuncSetAttribute((const void*)k_mm4<true, float>,
                         cudaFuncAttributeMaxDynamicSharedMemorySize, MM_SMEM4);

    // 2) fused QKV+MLP projection: P = h @ w1 (half output)
    {
        int tm = S_LEN / 128, tn = FOUT / 128;
        k_mm4<false, __half><<<tm * tn, 256, MM_SMEM4>>>(
            h, w1h, P, S_LEN, FOUT, DIM, tm, tn, nullptr, nullptr);
    }

    // 3) Q/K heads + RMSNorm + RoPE (half); 3b) V transpose
    {
        dim3 g(S_LEN, HEADS);
        k_qkvprep<<<g, 128>>>(P, rcos, rsin, nqw, nkw, Qb, Kb);
        k_vT<<<dim3(DIM / 32, S_LEN / 32), 256>>>(P, Vt);
    }

    // 4) fp16 attention -> cat[:, 0:3072]
    {
        cudaFuncSetAttribute(k_attn3, cudaFuncAttributeMaxDynamicSharedMemorySize, ATTN_SMEM);
        dim3 g(S_LEN / 128, HEADS);
        k_attn3<<<g, 256, ATTN_SMEM>>>(Qb, Kb, Vt, cat);
    }

    // 5) SwiGLU -> cat[:, 3072:12288]
    {
        dim3 g(MH / 256, S_LEN);
        k_swiglu<<<g, 256>>>(P, cat);
    }

    // 6) out = x + gate * (cat @ [wo_attn ; wo_mlp])   (K = 12288)
    {
        int tm = S_LEN / 128, tn = DIM / 128;
        k_mm4<true, float><<<tm * tn, 256, MM_SMEM4>>>(
            cat, woh, out, S_LEN, DIM, CATK, tm, tn, x, temb);
    }
}

// round 12
// speedup vs baseline: 7.6565x; 1.0535x over previous
#include <cuda_runtime.h>
#include <cuda_fp16.h>
#include <math.h>
#include <stdint.h>

#define S_LEN 4096
#define DIM   3072
#define HEADS 24
#define HD    128
#define MH    9216
#define FOUT  27648      // 3*DIM + 2*MH
#define QKV   9216       // 3*DIM
#define CATK  12288      // DIM + MH
#define EPS   1e-6f

// ---------------- scratch (device globals; no allocations allowed) ----------
__device__ __half g_h   [(size_t)S_LEN * DIM];
__device__ __half g_P   [(size_t)S_LEN * FOUT];
__device__ __half g_Qb  [(size_t)HEADS * S_LEN * HD];   // [h][s][d], pre-scaled
__device__ __half g_Kb  [(size_t)HEADS * S_LEN * HD];   // [h][s][d]
__device__ __half g_Vt  [(size_t)DIM * S_LEN];          // [h*HD+d][s]
__device__ __half g_cat [(size_t)S_LEN * CATK];         // [attn | swiglu]
__device__ __half g_w1h [(size_t)FOUT * DIM];           // w1^T [FOUT][DIM]
__device__ __half g_woh [(size_t)DIM * CATK];           // [wo_attn;wo_mlp]^T

__device__ __forceinline__ void cp16(uint32_t s, const void* g) {
    asm volatile("cp.async.cg.shared.global [%0], [%1], 16;\n" :: "r"(s), "l"(g));
}
__device__ __forceinline__ void mma_f16(float c[4],
    uint32_t a0, uint32_t a1, uint32_t a2, uint32_t a3, uint32_t b0, uint32_t b1)
{
    asm volatile(
        "mma.sync.aligned.m16n8k16.row.col.f32.f16.f16.f32 "
        "{%0,%1,%2,%3},{%4,%5,%6,%7},{%8,%9},{%0,%1,%2,%3};"
        : "+f"(c[0]), "+f"(c[1]), "+f"(c[2]), "+f"(c[3])
        : "r"(a0), "r"(a1), "r"(a2), "r"(a3), "r"(b0), "r"(b1));
}
__device__ __forceinline__ void ldsm4(uint32_t r[4], uint32_t addr) {
    asm volatile("ldmatrix.sync.aligned.m8n8.x4.shared.b16 {%0,%1,%2,%3}, [%4];"
                 : "=r"(r[0]), "=r"(r[1]), "=r"(r[2]), "=r"(r[3]) : "r"(addr));
}

// ---------------- kernel 0: fp32 [K][N] -> half [N][outK] transpose ----------
__global__ __launch_bounds__(256) void k_cvtT(
    const float* __restrict__ in, __half* __restrict__ out,
    int K, int N, int outK, int kofs)
{
    __shared__ float t[32][33];
    int k0 = blockIdx.y * 32, n0 = blockIdx.x * 32;
    int tx = threadIdx.x & 31, ty = threadIdx.x >> 5;
    #pragma unroll
    for (int i = 0; i < 32; i += 8)
        t[ty + i][tx] = in[(size_t)(k0 + ty + i) * N + n0 + tx];
    __syncthreads();
    #pragma unroll
    for (int i = 0; i < 32; i += 8)
        out[(size_t)(n0 + ty + i) * outK + kofs + k0 + tx] = __float2half_rn(t[tx][ty + i]);
}

// ---------------- kernel 1: LayerNorm + modulation (-> half) -----------------
__global__ __launch_bounds__(256) void k_lnmod(
    const float* __restrict__ x, const float* __restrict__ temb,
    __half* __restrict__ h)
{
    int s = blockIdx.x;
    const float* xr = x + (size_t)s * DIM;
    float v[12];
    float lsum = 0.f, lsq = 0.f;
    #pragma unroll
    for (int i = 0; i < 12; i++) {
        float t = xr[threadIdx.x + i * 256];
        v[i] = t; lsum += t; lsq += t * t;
    }
    __shared__ float red[16];
    #pragma unroll
    for (int o = 16; o; o >>= 1) {
        lsum += __shfl_xor_sync(0xffffffffu, lsum, o);
        lsq  += __shfl_xor_sync(0xffffffffu, lsq,  o);
    }
    int w = threadIdx.x >> 5;
    if ((threadIdx.x & 31) == 0) { red[w] = lsum; red[8 + w] = lsq; }
    __syncthreads();
    float ssum = 0.f, ssq = 0.f;
    #pragma unroll
    for (int i = 0; i < 8; i++) { ssum += red[i]; ssq += red[8 + i]; }
    float mu  = ssum * (1.0f / DIM);
    float var = ssq * (1.0f / DIM) - mu * mu;
    float rs  = rsqrtf(var + EPS);
    __half* hr = h + (size_t)s * DIM;
    #pragma unroll
    for (int i = 0; i < 12; i++) {
        int d = threadIdx.x + i * 256;
        float sc = temb[DIM + d];
        float sh = temb[d];
        hr[d] = __float2half_rn((v[i] - mu) * rs * (1.f + sc) + sh);
    }
}

// ---------------- kernel 2: fp16 GEMM (ldmatrix), 128x128 CTA, 2 CTAs/SM ----
#define MM4_STG 4
#define ST4W  5120
#define ST4B  (ST4W * 4)
#define MM_SMEM4 (MM4_STG * ST4B)       // 81920 bytes

template <bool FINAL, typename OutT>
__global__ __launch_bounds__(256, 2) void k_mm4(
    const __half* __restrict__ A, const __half* __restrict__ B,
    OutT* __restrict__ C, int M, int N, int K, int tiles_m, int tiles_n,
    const float* __restrict__ xres, const float* __restrict__ temb)
{
    extern __shared__ float smf[];

    int pid = blockIdx.x;
    const int GROUPM = 16;
    int npg     = GROUPM * tiles_n;
    int groupid = pid / npg;
    int firstm  = groupid * GROUPM;
    int gsz     = min(GROUPM, tiles_m - firstm);
    int pm      = firstm + (pid % npg) % gsz;
    int pn      = (pid % npg) / gsz;
    int bm = pm * 128, bn = pn * 128;

    int tid  = threadIdx.x;
    int warp = tid >> 5, lane = tid & 31;
    int wm = warp & 1, wn = warp >> 1;
    int gid = lane >> 2, tid4 = lane & 3;

    float acc[4][4][4];
    #pragma unroll
    for (int i = 0; i < 4; i++)
        #pragma unroll
        for (int j = 0; j < 4; j++)
            #pragma unroll
            for (int q = 0; q < 4; q++) acc[i][j][q] = 0.f;

    uint32_t smb = (uint32_t)__cvta_generic_to_shared(smf);
    const __half* Ag = A + (size_t)bm * K;
    const __half* Bg = B + (size_t)bn * K;

    uint32_t aoff[4], boff[2];
    #pragma unroll
    for (int mt = 0; mt < 4; mt++)
        aoff[mt] = (uint32_t)((wm * 64 + mt * 16 + (lane & 15)) * 80 + (lane >> 4) * 16);
    #pragma unroll
    for (int p = 0; p < 2; p++)
        boff[p] = 10240u + (uint32_t)((wn * 32 + p * 16 + ((lane >> 4) * 8) + (lane & 7)) * 80
                                      + (((lane >> 3) & 1) * 16));

    #define MM4_LOAD(KB, SS)                                                    \
    {                                                                           \
        int kt_ = (KB) * 32;                                                    \
        uint32_t sa_ = smb + (uint32_t)((SS) * ST4B);                           \
        uint32_t sb_ = sa_ + 10240u;                                            \
        _Pragma("unroll")                                                       \
        for (int i_ = 0; i_ < 2; i_++) {                                        \
            int id_ = tid + i_ * 256;                                           \
            int r_ = id_ >> 2, c_ = id_ & 3;                                    \
            cp16(sa_ + (uint32_t)(r_ * 80 + c_ * 16),                           \
                 Ag + (size_t)r_ * K + kt_ + c_ * 8);                           \
            cp16(sb_ + (uint32_t)(r_ * 80 + c_ * 16),                           \
                 Bg + (size_t)r_ * K + kt_ + c_ * 8);                           \
        }                                                                       \
        asm volatile("cp.async.commit_group;\n");                               \
    }

    int ntiles = K >> 5;

    MM4_LOAD(0, 0)
    MM4_LOAD(1, 1)
    MM4_LOAD(2, 2)

    for (int t = 0; t < ntiles; t++) {
        if (t <= ntiles - 3) {
            asm volatile("cp.async.wait_group 2;\n");
        } else if (t == ntiles - 2) {
            asm volatile("cp.async.wait_group 1;\n");
        } else {
            asm volatile("cp.async.wait_group 0;\n");
        }
        __syncthreads();
        if (t + 3 < ntiles) MM4_LOAD(t + 3, (t + 3) & 3)

        uint32_t sbase = smb + (uint32_t)((t & 3) * ST4B);

        #pragma unroll
        for (int k16 = 0; k16 < 2; k16++) {
            uint32_t kb = (uint32_t)(k16 * 32);
            uint32_t af[4][4], bq0[4], bq1[4];
            #pragma unroll
            for (int mt = 0; mt < 4; mt++)
                ldsm4(af[mt], sbase + aoff[mt] + kb);
            ldsm4(bq0, sbase + boff[0] + kb);
            ldsm4(bq1, sbase + boff[1] + kb);

            #pragma unroll
            for (int mt = 0; mt < 4; mt++) {
                mma_f16(acc[mt][0], af[mt][0], af[mt][1], af[mt][2], af[mt][3], bq0[0], bq0[1]);
                mma_f16(acc[mt][1], af[mt][0], af[mt][1], af[mt][2], af[mt][3], bq0[2], bq0[3]);
                mma_f16(acc[mt][2], af[mt][0], af[mt][1], af[mt][2], af[mt][3], bq1[0], bq1[1]);
                mma_f16(acc[mt][3], af[mt][0], af[mt][1], af[mt][2], af[mt][3], bq1[2], bq1[3]);
            }
        }
    }

    __syncthreads();   // protect smem before any tail usage (none) & uniform exit

    // epilogue
    #pragma unroll
    for (int mt = 0; mt < 4; mt++) {
        int r0 = bm + wm * 64 + mt * 16 + gid;
        #pragma unroll
        for (int nt = 0; nt < 4; nt++) {
            int c0 = bn + wn * 32 + nt * 8 + tid4 * 2;
            float2 v0 = make_float2(acc[mt][nt][0], acc[mt][nt][1]);
            float2 v1 = make_float2(acc[mt][nt][2], acc[mt][nt][3]);
            if (FINAL) {
                float gx = temb[2 * DIM + c0], gy = temb[2 * DIM + c0 + 1];
                float2 x0 = *(const float2*)(xres + (size_t)r0 * N + c0);
                float2 x1 = *(const float2*)(xres + (size_t)(r0 + 8) * N + c0);
                v0.x = x0.x + gx * v0.x; v0.y = x0.y + gy * v0.y;
                v1.x = x1.x + gx * v1.x; v1.y = x1.y + gy * v1.y;
            }
            if (sizeof(OutT) == 2) {
                *(__half2*)((__half*)C + (size_t)r0 * N + c0) =
                    __floats2half2_rn(v0.x, v0.y);
                *(__half2*)((__half*)C + (size_t)(r0 + 8) * N + c0) =
                    __floats2half2_rn(v1.x, v1.y);
            } else {
                *(float2*)((float*)C + (size_t)r0 * N + c0)       = v0;
                *(float2*)((float*)C + (size_t)(r0 + 8) * N + c0) = v1;
            }
        }
    }
}

// ---------------- kernel 3: QKV extract + RMSNorm + RoPE (-> half Q,K) ------
__global__ __launch_bounds__(128) void k_qkvprep(
    const __half* __restrict__ P, const float* __restrict__ cosb,
    const float* __restrict__ sinb, const float* __restrict__ nqw,
    const float* __restrict__ nkw,
    __half* __restrict__ Qb, __half* __restrict__ Kb)
{
    int s = blockIdx.x, h = blockIdx.y, d = threadIdx.x;
    const __half* row = P + (size_t)s * FOUT + h * HD;
    float q = __half2float(row[d]);
    float k = __half2float(row[DIM + d]);

    __shared__ float sQ[HD], sK[HD], sred[8];
    float sq = q * q, sk = k * k;
    #pragma unroll
    for (int o = 16; o; o >>= 1) {
        sq += __shfl_xor_sync(0xffffffffu, sq, o);
        sk += __shfl_xor_sync(0xffffffffu, sk, o);
    }
    int w = d >> 5;
    if ((d & 31) == 0) { sred[w] = sq; sred[4 + w] = sk; }
    __syncthreads();
    float ssq = sred[0] + sred[1] + sred[2] + sred[3];
    float ssk = sred[4] + sred[5] + sred[6] + sred[7];
    float qn = q * rsqrtf(ssq * (1.0f / HD) + EPS) * nqw[d];
    float kn = k * rsqrtf(ssk * (1.0f / HD) + EPS) * nkw[d];
    sQ[d] = qn; sK[d] = kn;
    __syncthreads();
    float qrot = (d & 1) ? sQ[d - 1] : -sQ[d + 1];
    float krot = (d & 1) ? sK[d - 1] : -sK[d + 1];
    float c  = cosb[(size_t)s * HD + d];
    float sn = sinb[(size_t)s * HD + d];
    const float scale = 0.08838834764831843f;
    size_t o = ((size_t)h * S_LEN + s) * HD + d;
    Qb[o] = __float2half_rn((qn * c + qrot * sn) * scale);
    Kb[o] = __float2half_rn(kn * c + krot * sn);
}

// ---------------- kernel 3b: V transpose (half [S][DIM] slice -> [DIM][S]) ---
__global__ __launch_bounds__(256) void k_vT(
    const __half* __restrict__ P, __half* __restrict__ Vt)
{
    __shared__ __half t[32][34];
    int c0 = blockIdx.x * 32, s0 = blockIdx.y * 32;
    int tx = threadIdx.x & 31, ty = threadIdx.x >> 5;
    #pragma unroll
    for (int i = 0; i < 32; i += 8)
        t[ty + i][tx] = P[(size_t)(s0 + ty + i) * FOUT + 2 * DIM + c0 + tx];
    __syncthreads();
    #pragma unroll
    for (int i = 0; i < 32; i += 8)
        Vt[(size_t)(c0 + ty + i) * S_LEN + s0 + tx] = t[tx][ty + i];
}

// ---------------- kernel 4: fp16 flash attention (ldmatrix, 3-stage) --------
#define K_STRH 136
#define V_STRH 72
#define P_STRH 72
#define K_STGH (64 * K_STRH)     // 8704 halfs
#define V_STGH (128 * V_STRH)    // 9216 halfs
#define PW_H   (16 * P_STRH)     // 1152 halfs
#define ATT_STG 3
#define ATTN_SMEM ((ATT_STG * (K_STGH + V_STGH) + 8 * PW_H) * 2)   // 125952 B

__global__ __launch_bounds__(256, 1) void k_attn3(
    const __half* __restrict__ Qb, const __half* __restrict__ Kb,
    const __half* __restrict__ Vt, __half* __restrict__ attnout)
{
    extern __shared__ __half smh[];
    __half* Ps = smh + ATT_STG * (K_STGH + V_STGH);

    int h  = blockIdx.y;
    int q0 = blockIdx.x * 128;
    int tid = threadIdx.x, warp = tid >> 5, lane = tid & 31;
    int gid = lane >> 2, tid4 = lane & 3;
    __half* Pw = Ps + warp * PW_H;
    uint32_t smbase = (uint32_t)__cvta_generic_to_shared(smh);
    uint32_t pwbase = smbase + (uint32_t)(ATT_STG * (K_STGH + V_STGH) + warp * PW_H) * 2u;

    // ldmatrix lane offsets (GEMM-verified pattern)
    uint32_t kfoff = (uint32_t)((((lane >> 4) * 8) + (lane & 7)) * (K_STRH * 2)
                                + ((lane >> 3) & 1) * 16);
    uint32_t vfoff = (uint32_t)((((lane >> 4) * 8) + (lane & 7)) * (V_STRH * 2)
                                + ((lane >> 3) & 1) * 16);
    uint32_t pfoff = (uint32_t)((lane & 15) * (P_STRH * 2) + (lane >> 4) * 16);

    // ---- Q tile -> smem (borrows K stage space), extract fp16 a-frags ----
    const __half* Qg = Qb + ((size_t)h * S_LEN + q0) * HD;
    #pragma unroll
    for (int i = 0; i < 8; i++) {
        int idx = tid + i * 256;
        int r = idx >> 4, c = idx & 15;
        cp16(smbase + (uint32_t)(r * K_STRH + c * 8) * 2u, Qg + (size_t)r * HD + c * 8);
    }
    asm volatile("cp.async.commit_group;\ncp.async.wait_group 0;\n");
    __syncthreads();
    uint32_t qf[8][4];
    {
        uint32_t qoff = smbase + (uint32_t)((warp * 16 + (lane & 15)) * (K_STRH * 2)
                                            + (lane >> 4) * 16);
        #pragma unroll
        for (int k16 = 0; k16 < 8; k16++)
            ldsm4(qf[k16], qoff + (uint32_t)(k16 * 32));
    }
    __syncthreads();

    float m0 = -1e30f, m1 = -1e30f, l0 = 0.f, l1 = 0.f;
    float o[16][4];
    #pragma unroll
    for (int dt = 0; dt < 16; dt++)
        #pragma unroll
        for (int j = 0; j < 4; j++) o[dt][j] = 0.f;

    #define LOAD_KV3(T, SS)                                                       \
    {                                                                             \
        const __half* Kg = Kb + ((size_t)h * S_LEN + (T) * 64) * HD;              \
        const __half* Vg = Vt + (size_t)h * HD * S_LEN + (T) * 64;                \
        uint32_t ks = smbase + (uint32_t)((SS) * (K_STGH + V_STGH)) * 2u;         \
        uint32_t vs = ks + (uint32_t)K_STGH * 2u;                                 \
        _Pragma("unroll")                                                         \
        for (int i = 0; i < 4; i++) {                                             \
            int idx = tid + i * 256;                                              \
            int kr = idx >> 4, kc = idx & 15;                                     \
            cp16(ks + (uint32_t)(kr * K_STRH + kc * 8) * 2u,                      \
                 Kg + (size_t)kr * HD + kc * 8);                                  \
            int vr = idx >> 3, vc = idx & 7;                                      \
            cp16(vs + (uint32_t)(vr * V_STRH + vc * 8) * 2u,                      \
                 Vg + (size_t)vr * S_LEN + vc * 8);                               \
        }                                                                         \
        asm volatile("cp.async.commit_group;\n");                                 \
    }

    LOAD_KV3(0, 0)
    LOAD_KV3(1, 1)

    int st = 0, sl = 2;
    for (int t = 0; t < 64; t++) {
        if (t < 62) {
            asm volatile("cp.async.wait_group 1;\n");
        } else {
            asm volatile("cp.async.wait_group 0;\n");
        }
        __syncthreads();
        if (t + 2 < 64) {
            LOAD_KV3(t + 2, sl)
            sl = (sl == 2) ? 0 : sl + 1;
        }

        uint32_t ksb = smbase + (uint32_t)(st * (K_STGH + V_STGH)) * 2u;
        uint32_t vsb = ksb + (uint32_t)K_STGH * 2u;
        st = (st == 2) ? 0 : st + 1;

        // ---- S = Q K^T ----
        float sa[8][4];
        #pragma unroll
        for (int nt = 0; nt < 8; nt++)
            #pragma unroll
            for (int j = 0; j < 4; j++) sa[nt][j] = 0.f;
        #pragma unroll
        for (int ntp = 0; ntp < 4; ntp++) {
            uint32_t ka = ksb + kfoff + (uint32_t)(ntp * 16 * K_STRH * 2);
            #pragma unroll
            for (int k16 = 0; k16 < 8; k16++) {
                uint32_t bq[4];
                ldsm4(bq, ka + (uint32_t)(k16 * 32));
                mma_f16(sa[2 * ntp],     qf[k16][0], qf[k16][1], qf[k16][2], qf[k16][3],
                        bq[0], bq[1]);
                mma_f16(sa[2 * ntp + 1], qf[k16][0], qf[k16][1], qf[k16][2], qf[k16][3],
                        bq[2], bq[3]);
            }
        }

        // ---- online softmax ----
        float mx0 = -1e30f, mx1 = -1e30f;
        #pragma unroll
        for (int nt = 0; nt < 8; nt++) {
            mx0 = fmaxf(mx0, fmaxf(sa[nt][0], sa[nt][1]));
            mx1 = fmaxf(mx1, fmaxf(sa[nt][2], sa[nt][3]));
        }
        mx0 = fmaxf(mx0, __shfl_xor_sync(0xffffffffu, mx0, 1));
        mx0 = fmaxf(mx0, __shfl_xor_sync(0xffffffffu, mx0, 2));
        mx1 = fmaxf(mx1, __shfl_xor_sync(0xffffffffu, mx1, 1));
        mx1 = fmaxf(mx1, __shfl_xor_sync(0xffffffffu, mx1, 2));
        float nm0 = fmaxf(m0, mx0), nm1 = fmaxf(m1, mx1);
        float corr0 = __expf(m0 - nm0), corr1 = __expf(m1 - nm1);
        float rs0 = 0.f, rs1 = 0.f;
        #pragma unroll
        for (int nt = 0; nt < 8; nt++) {
            float p0 = __expf(sa[nt][0] - nm0);
            float p1 = __expf(sa[nt][1] - nm0);
            float p2 = __expf(sa[nt][2] - nm1);
            float p3 = __expf(sa[nt][3] - nm1);
            rs0 += p0 + p1; rs1 += p2 + p3;
            *(__half2*)&Pw[gid * P_STRH + nt * 8 + 2 * tid4]       = __floats2half2_rn(p0, p1);
            *(__half2*)&Pw[(gid + 8) * P_STRH + nt * 8 + 2 * tid4] = __floats2half2_rn(p2, p3);
        }
        rs0 += __shfl_xor_sync(0xffffffffu, rs0, 1);
        rs0 += __shfl_xor_sync(0xffffffffu, rs0, 2);
        rs1 += __shfl_xor_sync(0xffffffffu, rs1, 1);
        rs1 += __shfl_xor_sync(0xffffffffu, rs1, 2);
        l0 = l0 * corr0 + rs0;
        l1 = l1 * corr1 + rs1;
        m0 = nm0; m1 = nm1;
        #pragma unroll
        for (int dt = 0; dt < 16; dt++) {
            o[dt][0] *= corr0; o[dt][1] *= corr0;
            o[dt][2] *= corr1; o[dt][3] *= corr1;
        }
        __syncwarp();

        // ---- O += P V ----
        #pragma unroll
        for (int k16 = 0; k16 < 4; k16++) {
            uint32_t aq[4];
            ldsm4(aq, pwbase + pfoff + (uint32_t)(k16 * 32));
            #pragma unroll
            for (int dtp = 0; dtp < 8; dtp++) {
                uint32_t bq[4];
                ldsm4(bq, vsb + vfoff + (uint32_t)(dtp * 16 * V_STRH * 2 + k16 * 32));
                mma_f16(o[2 * dtp],     aq[0], aq[1], aq[2], aq[3], bq[0], bq[1]);
                mma_f16(o[2 * dtp + 1], aq[0], aq[1], aq[2], aq[3], bq[2], bq[3]);
            }
        }
        __syncwarp();
    }

    // ---- epilogue ----
    float inv0 = 1.0f / l0, inv1 = 1.0f / l1;
    int r0 = q0 + warp * 16 + gid;
    #pragma unroll
    for (int dt = 0; dt < 16; dt++) {
        int col = h * HD + dt * 8 + 2 * tid4;
        *(__half2*)&attnout[(size_t)r0 * CATK + col] =
            __floats2half2_rn(o[dt][0] * inv0, o[dt][1] * inv0);
        *(__half2*)&attnout[(size_t)(r0 + 8) * CATK + col] =
            __floats2half2_rn(o[dt][2] * inv1, o[dt][3] * inv1);
    }
}

// ---------------- kernel 5: SwiGLU -> half concat buffer ---------------------
__global__ __launch_bounds__(256) void k_swiglu(
    const __half* __restrict__ P, __half* __restrict__ cat)
{
    int j = blockIdx.x * 256 + threadIdx.x;
    int s = blockIdx.y;
    float a = __half2float(P[(size_t)s * FOUT + QKV + j]);
    float b = __half2float(P[(size_t)s * FOUT + QKV + MH + j]);
    cat[(size_t)s * CATK + DIM + j] = __float2half_rn((a / (1.f + __expf(-a))) * b);
}

// ---------------- launch -----------------------------------------------------
extern "C" void kernel_launch(void* const* d_in, const int* in_sizes, int n_in,
                              void* d_out, int out_size)
{
    const float* x       = (const float*)d_in[0];
    const float* temb    = (const float*)d_in[1];
    const float* rcos    = (const float*)d_in[2];
    const float* rsin    = (const float*)d_in[3];
    const float* w1      = (const float*)d_in[4];
    const float* wo_attn = (const float*)d_in[5];
    const float* wo_mlp  = (const float*)d_in[6];
    const float* nqw     = (const float*)d_in[7];
    const float* nkw     = (const float*)d_in[8];
    float* out = (float*)d_out;

    __half *h, *P, *Qb, *Kb, *Vt, *cat, *w1h, *woh;
    cudaGetSymbolAddress((void**)&h,   g_h);
    cudaGetSymbolAddress((void**)&P,   g_P);
    cudaGetSymbolAddress((void**)&Qb,  g_Qb);
    cudaGetSymbolAddress((void**)&Kb,  g_Kb);
    cudaGetSymbolAddress((void**)&Vt,  g_Vt);
    cudaGetSymbolAddress((void**)&cat, g_cat);
    cudaGetSymbolAddress((void**)&w1h, g_w1h);
    cudaGetSymbolAddress((void**)&woh, g_woh);

    // 0) weight convert + transpose to half [N][K]
    k_cvtT<<<dim3(FOUT / 32, DIM / 32), 256>>>(w1,      w1h, DIM, FOUT, DIM,  0);
    k_cvtT<<<dim3(DIM / 32,  DIM / 32), 256>>>(wo_attn, woh, DIM, DIM,  CATK, 0);
    k_cvtT<<<dim3(DIM / 32,  MH  / 32), 256>>>(wo_mlp,  woh, MH,  DIM,  CATK, DIM);

    // 1) LayerNorm + modulation -> half h
    k_lnmod<<<S_LEN, 256>>>(x, temb, h);

    cudaFuncSetAttribute((const void*)k_mm4<false, __half>,
                         cudaFuncAttributeMaxDynamicSharedMemorySize, MM_SMEM4);
    cudaFuncSetAttribute((const void*)k_mm4<true, float>,
                         cudaFuncAttributeMaxDynamicSharedMemorySize, MM_SMEM4);

    // 2) fused QKV+MLP projection: P = h @ w1 (half output)
    {
        int tm = S_LEN / 128, tn = FOUT / 128;
        k_mm4<false, __half><<<tm * tn, 256, MM_SMEM4>>>(
            h, w1h, P, S_LEN, FOUT, DIM, tm, tn, nullptr, nullptr);
    }

    // 3) Q/K heads + RMSNorm + RoPE (half); 3b) V transpose
    {
        dim3 g(S_LEN, HEADS);
        k_qkvprep<<<g, 128>>>(P, rcos, rsin, nqw, nkw, Qb, Kb);
        k_vT<<<dim3(DIM / 32, S_LEN / 32), 256>>>(P, Vt);
    }

    // 4) fp16 attention -> cat[:, 0:3072]
    {
        cudaFuncSetAttribute(k_attn3, cudaFuncAttributeMaxDynamicSharedMemorySize, ATTN_SMEM);
        dim3 g(S_LEN / 128, HEADS);
        k_attn3<<<g, 256, ATTN_SMEM>>>(Qb, Kb, Vt, cat);
    }

    // 5) SwiGLU -> cat[:, 3072:12288]
    {
        dim3 g(MH / 256, S_LEN);
        k_swiglu<<<g, 256>>>(P, cat);
    }

    // 6) out = x + gate * (cat @ [wo_attn ; wo_mlp])   (K = 12288)
    {
        int tm = S_LEN / 128, tn = DIM / 128;
        k_mm4<true, float><<<tm * tn, 256, MM_SMEM4>>>(
            cat, woh, out, S_LEN, DIM, CATK, tm, tn, x, temb);
    }
}